// round 1
// baseline (speedup 1.0000x reference)
#include <cuda_runtime.h>
#include <math.h>

// ---------------- problem constants ----------------
// B=8, M=1024, DM=768, H=12, DH=64, R=32, RFF=384, DFF=3072, RWO=384
// rows = B*M = 8192

// ---------------- scratch (device globals; no allocation) ----------------
__device__ float g_t   [3ull * 8 * 1024 * 384];        // qkv low-rank temps [3][B][M][H*R]
__device__ float g_qkv [3ull * 8 * 12 * 1024 * 64];    // Q,K,V [3][B][H][M][DH]
__device__ float g_sc  [96ull * 1024 * 1024];          // scores/probs [B*H][M][M]
__device__ float g_at2 [8ull * 1024 * 768];            // attn merged [B,M,DM]
__device__ float g_tmp [8192ull * 384];                // rank-384 temp
__device__ float g_x1  [8192ull * 768];                // x1 (post LN1)
__device__ float g_y   [8192ull * 768];                // pre-LN buffers
__device__ float g_hdn [8192ull * 3072];               // FFN hidden

// ---------------- tiled GEMM config ----------------
// 64x64 tile, BK=16, 256 threads, 4x4 per-thread microtile.

// Specialized: t[b, m, h*32+r] = sum_d x[b,m,d] * P[h,d,r]   (P: [12,768,32])
__global__ void proj_p_kernel(const float* __restrict__ x,
                              const float* __restrict__ P,
                              float* __restrict__ C) {
    __shared__ float As[16][65];
    __shared__ float Bs[16][65];
    const int b = blockIdx.z;
    const float* A = x + (size_t)b * 1024 * 768;
    float* Cb = C + (size_t)b * 1024 * 384;
    const int x0 = blockIdx.x * 64, y0 = blockIdx.y * 64;
    const int tid = threadIdx.x;
    const int tx = tid & 15, ty = tid >> 4;
    float acc[4][4] = {};
    for (int k0 = 0; k0 < 768; k0 += 16) {
#pragma unroll
        for (int i = 0; i < 4; i++) {
            int idx = tid + i * 256;
            int r = idx >> 4, c = idx & 15;
            As[c][r] = A[(size_t)(y0 + r) * 768 + k0 + c];
        }
#pragma unroll
        for (int i = 0; i < 4; i++) {
            int idx = tid + i * 256;
            int kr = idx >> 6, c = idx & 63;
            int n = x0 + c;
            Bs[kr][c] = P[((size_t)(n >> 5) * 768 + (k0 + kr)) * 32 + (n & 31)];
        }
        __syncthreads();
#pragma unroll
        for (int kk = 0; kk < 16; kk++) {
            float a[4], bv[4];
#pragma unroll
            for (int i = 0; i < 4; i++) a[i] = As[kk][ty * 4 + i];
#pragma unroll
            for (int j = 0; j < 4; j++) bv[j] = Bs[kk][tx * 4 + j];
#pragma unroll
            for (int i = 0; i < 4; i++)
#pragma unroll
                for (int j = 0; j < 4; j++) acc[i][j] = fmaf(a[i], bv[j], acc[i][j]);
        }
        __syncthreads();
    }
#pragma unroll
    for (int i = 0; i < 4; i++)
#pragma unroll
        for (int j = 0; j < 4; j++)
            Cb[(size_t)(y0 + ty * 4 + i) * 384 + x0 + tx * 4 + j] = acc[i][j];
}

__device__ __forceinline__ float gelu_exact(float v) {
    return 0.5f * v * (1.0f + erff(v * 0.70710678118654752440f));
}

// Generic batched GEMM: C = scale*(A@B or A@B^T) + bias + res, optional GELU.
// Batch z decomposed as z = i1*D2 + i2; operand offsets via stride pairs.
template <bool BT>
__global__ void gemm_ep(const float* __restrict__ A, const float* __restrict__ Bm,
                        float* __restrict__ C,
                        const float* __restrict__ bias, const float* __restrict__ res,
                        int lda, int ldb, int ldc, int ldres,
                        int K, float scale, int do_gelu, int D2,
                        long long sA1, long long sA2,
                        long long sB1, long long sB2,
                        long long sC1, long long sC2,
                        long long sb1, long long sb2) {
    __shared__ float As[16][65];
    __shared__ float Bs[16][65];
    const int z = blockIdx.z;
    const int i1 = z / D2, i2 = z % D2;
    A  += i1 * sA1 + i2 * sA2;
    Bm += i1 * sB1 + i2 * sB2;
    C  += i1 * sC1 + i2 * sC2;
    const long long boff = i1 * sb1 + i2 * sb2;

    const int x0 = blockIdx.x * 64, y0 = blockIdx.y * 64;
    const int tid = threadIdx.x;
    const int tx = tid & 15, ty = tid >> 4;
    float acc[4][4] = {};

    for (int k0 = 0; k0 < K; k0 += 16) {
#pragma unroll
        for (int i = 0; i < 4; i++) {
            int idx = tid + i * 256;
            int r = idx >> 4, c = idx & 15;
            As[c][r] = A[(size_t)(y0 + r) * lda + k0 + c];
        }
        if (BT) {
#pragma unroll
            for (int i = 0; i < 4; i++) {
                int idx = tid + i * 256;
                int n = idx >> 4, k = idx & 15;
                Bs[k][n] = Bm[(size_t)(x0 + n) * ldb + k0 + k];
            }
        } else {
#pragma unroll
            for (int i = 0; i < 4; i++) {
                int idx = tid + i * 256;
                int kr = idx >> 6, c = idx & 63;
                Bs[kr][c] = Bm[(size_t)(k0 + kr) * ldb + x0 + c];
            }
        }
        __syncthreads();
#pragma unroll
        for (int kk = 0; kk < 16; kk++) {
            float a[4], bv[4];
#pragma unroll
            for (int i = 0; i < 4; i++) a[i] = As[kk][ty * 4 + i];
#pragma unroll
            for (int j = 0; j < 4; j++) bv[j] = Bs[kk][tx * 4 + j];
#pragma unroll
            for (int i = 0; i < 4; i++)
#pragma unroll
                for (int j = 0; j < 4; j++) acc[i][j] = fmaf(a[i], bv[j], acc[i][j]);
        }
        __syncthreads();
    }

#pragma unroll
    for (int i = 0; i < 4; i++) {
        int m = y0 + ty * 4 + i;
#pragma unroll
        for (int j = 0; j < 4; j++) {
            int n = x0 + tx * 4 + j;
            float v = acc[i][j] * scale;
            if (bias) v += bias[boff + n];
            if (res)  v += res[(size_t)m * ldres + n];
            if (do_gelu) v = gelu_exact(v);
            C[(size_t)m * ldc + n] = v;
        }
    }
}

// Row softmax over 1024 columns. grid: (1024 rows, 96 bh)
__global__ void softmax_kernel(float* __restrict__ S) {
    __shared__ float red[256];
    float* row = S + (size_t)blockIdx.y * 1024 * 1024 + (size_t)blockIdx.x * 1024;
    const int tid = threadIdx.x;
    float v[4];
    float mx = -1e30f;
#pragma unroll
    for (int i = 0; i < 4; i++) { v[i] = row[tid + i * 256]; mx = fmaxf(mx, v[i]); }
    red[tid] = mx; __syncthreads();
    for (int s = 128; s > 0; s >>= 1) {
        if (tid < s) red[tid] = fmaxf(red[tid], red[tid + s]);
        __syncthreads();
    }
    mx = red[0]; __syncthreads();
    float sum = 0.0f;
#pragma unroll
    for (int i = 0; i < 4; i++) { v[i] = expf(v[i] - mx); sum += v[i]; }
    red[tid] = sum; __syncthreads();
    for (int s = 128; s > 0; s >>= 1) {
        if (tid < s) red[tid] += red[tid + s];
        __syncthreads();
    }
    float inv = 1.0f / red[0];
#pragma unroll
    for (int i = 0; i < 4; i++) row[tid + i * 256] = v[i] * inv;
}

// LayerNorm over 768 columns. grid: 8192 rows, 256 threads.
__global__ void ln_kernel(const float* __restrict__ in, float* __restrict__ out,
                          const float* __restrict__ g, const float* __restrict__ bb) {
    __shared__ float red[256];
    const float* xr = in + (size_t)blockIdx.x * 768;
    float* yr = out + (size_t)blockIdx.x * 768;
    const int tid = threadIdx.x;
    float v[3];
    float s = 0.0f;
#pragma unroll
    for (int i = 0; i < 3; i++) { v[i] = xr[tid + i * 256]; s += v[i]; }
    red[tid] = s; __syncthreads();
    for (int t = 128; t > 0; t >>= 1) {
        if (tid < t) red[tid] += red[tid + t];
        __syncthreads();
    }
    const float mu = red[0] * (1.0f / 768.0f);
    __syncthreads();
    float ss = 0.0f;
#pragma unroll
    for (int i = 0; i < 3; i++) { float d = v[i] - mu; ss += d * d; }
    red[tid] = ss; __syncthreads();
    for (int t = 128; t > 0; t >>= 1) {
        if (tid < t) red[tid] += red[tid + t];
        __syncthreads();
    }
    const float rs = rsqrtf(red[0] * (1.0f / 768.0f) + 1e-12f);
    __syncthreads();
#pragma unroll
    for (int i = 0; i < 3; i++) {
        int c = tid + i * 256;
        yr[c] = (v[i] - mu) * rs * g[c] + bb[c];
    }
}

extern "C" void kernel_launch(void* const* d_in, const int* in_sizes, int n_in,
                              void* d_out, int out_size) {
    const float* x    = (const float*)d_in[0];
    const float* mask = (const float*)d_in[1];
    const float* Pq   = (const float*)d_in[2];
    const float* Vq   = (const float*)d_in[3];
    const float* bq   = (const float*)d_in[4];
    const float* Pk   = (const float*)d_in[5];
    const float* Vk   = (const float*)d_in[6];
    const float* bk   = (const float*)d_in[7];
    const float* Pv   = (const float*)d_in[8];
    const float* Vv   = (const float*)d_in[9];
    const float* bv   = (const float*)d_in[10];
    const float* Uo   = (const float*)d_in[11];
    const float* Vo   = (const float*)d_in[12];
    const float* bo   = (const float*)d_in[13];
    const float* U1   = (const float*)d_in[14];
    const float* V1   = (const float*)d_in[15];
    const float* b1   = (const float*)d_in[16];
    const float* U2   = (const float*)d_in[17];
    const float* V2   = (const float*)d_in[18];
    const float* b2   = (const float*)d_in[19];
    const float* ln1g = (const float*)d_in[20];
    const float* ln1b = (const float*)d_in[21];
    const float* ln2g = (const float*)d_in[22];
    const float* ln2b = (const float*)d_in[23];
    float* out = (float*)d_out;

    float *t_p, *qkv_p, *sc_p, *at2_p, *tmp_p, *x1_p, *y_p, *hdn_p;
    cudaGetSymbolAddress((void**)&t_p,   g_t);
    cudaGetSymbolAddress((void**)&qkv_p, g_qkv);
    cudaGetSymbolAddress((void**)&sc_p,  g_sc);
    cudaGetSymbolAddress((void**)&at2_p, g_at2);
    cudaGetSymbolAddress((void**)&tmp_p, g_tmp);
    cudaGetSymbolAddress((void**)&x1_p,  g_x1);
    cudaGetSymbolAddress((void**)&y_p,   g_y);
    cudaGetSymbolAddress((void**)&hdn_p, g_hdn);

    const long long T_QKV = 3145728;   // 8*1024*384
    const long long Q_QKV = 6291456;   // 8*12*1024*64

    const float* Ps[3] = {Pq, Pk, Pv};
    const float* Vs[3] = {Vq, Vk, Vv};
    const float* bs[3] = {bq, bk, bv};

    // 1) t_qkv = x @ P   -> [3][B][M][H*R]
    for (int q = 0; q < 3; q++)
        proj_p_kernel<<<dim3(6, 16, 8), 256>>>(x, Ps[q], t_p + q * T_QKV);

    // 2) Q/K/V = t @ Vqkv + b   -> [3][B][H][M][DH]; z=(b,h)
    for (int q = 0; q < 3; q++)
        gemm_ep<false><<<dim3(1, 16, 96), 256>>>(
            t_p + q * T_QKV, Vs[q], qkv_p + q * Q_QKV, bs[q], nullptr,
            384, 64, 64, 0, 32, 1.0f, 0, 12,
            393216LL, 32LL,      // A: b*M*384 + h*32
            0LL, 2048LL,         // B: h*R*DH
            786432LL, 65536LL,   // C: b*H*M*64 + h*M*64
            0LL, 64LL);          // bias: h*64

    // 3) scores = scale * Q@K^T + mask[b,:]   z=(b,h)
    gemm_ep<true><<<dim3(16, 16, 96), 256>>>(
        qkv_p, qkv_p + Q_QKV, sc_p, mask, nullptr,
        64, 64, 1024, 0, 64, 0.125f, 0, 12,
        786432LL, 65536LL,
        786432LL, 65536LL,
        12582912LL, 1048576LL,
        1024LL, 0LL);

    // 4) softmax rows
    softmax_kernel<<<dim3(1024, 96), 256>>>(sc_p);

    // 5) attn = probs @ V -> merged layout [B, M, H*DH]; z=(b,h)
    gemm_ep<false><<<dim3(1, 16, 96), 256>>>(
        sc_p, qkv_p + 2 * Q_QKV, at2_p, nullptr, nullptr,
        1024, 64, 768, 0, 1024, 1.0f, 0, 12,
        12582912LL, 1048576LL,
        786432LL, 65536LL,
        786432LL, 64LL,
        0LL, 0LL);

    // 6) ao = attn @ Uo  [8192,768]@[768,384]
    gemm_ep<false><<<dim3(6, 128, 1), 256>>>(
        at2_p, Uo, tmp_p, nullptr, nullptr,
        768, 384, 384, 0, 768, 1.0f, 0, 1,
        0, 0, 0, 0, 0, 0, 0, 0);

    // 7) x1pre = ao @ Vo + bo + x
    gemm_ep<false><<<dim3(12, 128, 1), 256>>>(
        tmp_p, Vo, y_p, bo, x,
        384, 768, 768, 768, 384, 1.0f, 0, 1,
        0, 0, 0, 0, 0, 0, 0, 0);

    // 8) LN1
    ln_kernel<<<8192, 256>>>(y_p, x1_p, ln1g, ln1b);

    // 9) mid = x1 @ U1
    gemm_ep<false><<<dim3(6, 128, 1), 256>>>(
        x1_p, U1, tmp_p, nullptr, nullptr,
        768, 384, 384, 0, 768, 1.0f, 0, 1,
        0, 0, 0, 0, 0, 0, 0, 0);

    // 10) hdn = gelu(mid @ V1 + b1)  [8192,384]@[384,3072]
    gemm_ep<false><<<dim3(48, 128, 1), 256>>>(
        tmp_p, V1, hdn_p, b1, nullptr,
        384, 3072, 3072, 0, 384, 1.0f, 1, 1,
        0, 0, 0, 0, 0, 0, 0, 0);

    // 11) h2 = hdn @ U2  [8192,3072]@[3072,384]
    gemm_ep<false><<<dim3(6, 128, 1), 256>>>(
        hdn_p, U2, tmp_p, nullptr, nullptr,
        3072, 384, 384, 0, 3072, 1.0f, 0, 1,
        0, 0, 0, 0, 0, 0, 0, 0);

    // 12) ypre = h2 @ V2 + b2 + x1
    gemm_ep<false><<<dim3(12, 128, 1), 256>>>(
        tmp_p, V2, y_p, b2, x1_p,
        384, 768, 768, 768, 384, 1.0f, 0, 1,
        0, 0, 0, 0, 0, 0, 0, 0);

    // 13) LN2 -> out
    ln_kernel<<<8192, 256>>>(y_p, out, ln2g, ln2b);
}

// round 2
// speedup vs baseline: 1.4437x; 1.4437x over previous
#include <cuda_runtime.h>
#include <math.h>

// B=8, M=1024, DM=768, H=12, DH=64, R=32, RFF=384, DFF=3072, RWO=384

// ---------------- scratch (device globals) ----------------
__device__ float g_w   [3ull * 768 * 384];             // packed P factors [3][768][H*R]
__device__ float g_t   [3ull * 8 * 1024 * 384];        // qkv low-rank temps
__device__ float g_qkv [3ull * 8 * 12 * 1024 * 64];    // Q,K,V [3][B][H][M][DH]
__device__ float g_sc  [96ull * 1024 * 1024];          // scores/probs
__device__ float g_at2 [8ull * 1024 * 768];            // attn merged [B,M,DM]
__device__ float g_tmp [8192ull * 384];
__device__ float g_x1  [8192ull * 768];
__device__ float g_y   [8192ull * 768];
__device__ float g_hdn [8192ull * 3072];

// ---------------- f32x2 helpers ----------------
__device__ __forceinline__ unsigned long long pack2(float lo, float hi) {
    unsigned long long r;
    asm("mov.b64 %0, {%1, %2};" : "=l"(r) : "f"(lo), "f"(hi));
    return r;
}
__device__ __forceinline__ unsigned long long dup2(float v) { return pack2(v, v); }
__device__ __forceinline__ void fma2(unsigned long long& acc, unsigned long long a,
                                     unsigned long long b) {
    asm("fma.rn.f32x2 %0, %1, %2, %0;" : "+l"(acc) : "l"(a), "l"(b));
}
__device__ __forceinline__ void unpack2(unsigned long long v, float& lo, float& hi) {
    asm("mov.b64 {%0, %1}, %2;" : "=f"(lo), "=f"(hi) : "l"(v));
}
__device__ __forceinline__ float gelu_exact(float v) {
    return 0.5f * v * (1.0f + erff(v * 0.70710678118654752440f));
}

// ---------------- big-tile f32x2 GEMM ----------------
// C = scale*(A@B or A@B^T) [+ bias[col]] [+ res] [gelu]; batch z = i1*D2+i2.
template <int BM, int BN, bool BT>
__global__ void __launch_bounds__((BM / 8) * (BN / 8), 2)
gemm2(const float* __restrict__ A, const float* __restrict__ Bm, float* __restrict__ C,
      const float* __restrict__ bias, const float* __restrict__ res,
      int lda, int ldb, int ldc, int ldres, int K, float scale, int do_gelu, int D2,
      long long sA1, long long sA2, long long sB1, long long sB2,
      long long sC1, long long sC2, long long sb1, long long sb2) {
    constexpr int TX = BN / 8, TY = BM / 8, NT = TX * TY;
    constexpr int LA = (BM * 16) / (4 * NT);
    constexpr int LB = (BN * 16) / (4 * NT);
    __shared__ float As[2][16][BM + 4];
    __shared__ float Bs[2][16][BN + 4];

    const int z = blockIdx.z;
    const int i1 = z / D2, i2 = z % D2;
    A += i1 * sA1 + i2 * sA2;
    Bm += i1 * sB1 + i2 * sB2;
    C += i1 * sC1 + i2 * sC2;
    const long long boff = i1 * sb1 + i2 * sb2;

    const int x0 = blockIdx.x * BN, y0 = blockIdx.y * BM;
    const int tid = threadIdx.x;
    const int tx = tid % TX, ty = tid / TX;

    float4 ra[LA], rb[LB];

    auto ldg = [&](int k0) {
#pragma unroll
        for (int i = 0; i < LA; i++) {
            int f = tid + i * NT;
            int m = f >> 2, kq = f & 3;
            ra[i] = *(const float4*)(A + (size_t)(y0 + m) * lda + k0 + kq * 4);
        }
#pragma unroll
        for (int i = 0; i < LB; i++) {
            int f = tid + i * NT;
            if (BT) {
                int n = f >> 2, kq = f & 3;
                rb[i] = *(const float4*)(Bm + (size_t)(x0 + n) * ldb + k0 + kq * 4);
            } else {
                int k = f / (BN / 4), nq = f % (BN / 4);
                rb[i] = *(const float4*)(Bm + (size_t)(k0 + k) * ldb + x0 + nq * 4);
            }
        }
    };
    auto sts = [&](int buf) {
#pragma unroll
        for (int i = 0; i < LA; i++) {
            int f = tid + i * NT;
            int m = f >> 2, kq = f & 3;
            As[buf][kq * 4 + 0][m] = ra[i].x;
            As[buf][kq * 4 + 1][m] = ra[i].y;
            As[buf][kq * 4 + 2][m] = ra[i].z;
            As[buf][kq * 4 + 3][m] = ra[i].w;
        }
#pragma unroll
        for (int i = 0; i < LB; i++) {
            int f = tid + i * NT;
            if (BT) {
                int n = f >> 2, kq = f & 3;
                Bs[buf][kq * 4 + 0][n] = rb[i].x;
                Bs[buf][kq * 4 + 1][n] = rb[i].y;
                Bs[buf][kq * 4 + 2][n] = rb[i].z;
                Bs[buf][kq * 4 + 3][n] = rb[i].w;
            } else {
                int k = f / (BN / 4), nq = f % (BN / 4);
                *(float4*)&Bs[buf][k][nq * 4] = rb[i];
            }
        }
    };

    unsigned long long acc[8][4];
#pragma unroll
    for (int i = 0; i < 8; i++)
#pragma unroll
        for (int j = 0; j < 4; j++) acc[i][j] = 0ull;

    ldg(0);
    sts(0);
    __syncthreads();
    const int nb = K >> 4;
    for (int kb = 0; kb < nb; kb++) {
        const int cur = kb & 1;
        if (kb + 1 < nb) ldg((kb + 1) << 4);
#pragma unroll
        for (int kk = 0; kk < 16; kk++) {
            float4 a0 = *(const float4*)&As[cur][kk][ty * 8];
            float4 a1 = *(const float4*)&As[cur][kk][ty * 8 + 4];
            float4 b0 = *(const float4*)&Bs[cur][kk][tx * 8];
            float4 b1 = *(const float4*)&Bs[cur][kk][tx * 8 + 4];
            unsigned long long bp[4] = {pack2(b0.x, b0.y), pack2(b0.z, b0.w),
                                        pack2(b1.x, b1.y), pack2(b1.z, b1.w)};
            float av[8] = {a0.x, a0.y, a0.z, a0.w, a1.x, a1.y, a1.z, a1.w};
#pragma unroll
            for (int i = 0; i < 8; i++) {
                unsigned long long ad = dup2(av[i]);
#pragma unroll
                for (int j = 0; j < 4; j++) fma2(acc[i][j], ad, bp[j]);
            }
        }
        if (kb + 1 < nb) sts(cur ^ 1);
        __syncthreads();
    }

#pragma unroll
    for (int i = 0; i < 8; i++) {
        int m = y0 + ty * 8 + i;
        int nbase = x0 + tx * 8;
        float v[8];
#pragma unroll
        for (int j = 0; j < 4; j++) unpack2(acc[i][j], v[2 * j], v[2 * j + 1]);
#pragma unroll
        for (int j = 0; j < 8; j++) {
            float t = v[j] * scale;
            if (bias) t += bias[boff + nbase + j];
            if (res) t += res[(size_t)m * ldres + nbase + j];
            if (do_gelu) t = gelu_exact(t);
            v[j] = t;
        }
        *(float4*)(C + (size_t)m * ldc + nbase) = make_float4(v[0], v[1], v[2], v[3]);
        *(float4*)(C + (size_t)m * ldc + nbase + 4) = make_float4(v[4], v[5], v[6], v[7]);
    }
}

// ---------------- pack P [H,DM,R] -> W [DM, H*R] ----------------
__global__ void pack_p(const float* __restrict__ Pq, const float* __restrict__ Pk,
                       const float* __restrict__ Pv, float* __restrict__ W) {
    int idx = blockIdx.x * blockDim.x + threadIdx.x;
    if (idx >= 3 * 768 * 384) return;
    int q = idx / (768 * 384);
    int r2 = idx % (768 * 384);
    int k = r2 / 384, n = r2 % 384;
    const float* P = (q == 0) ? Pq : ((q == 1) ? Pk : Pv);
    W[idx] = P[((size_t)(n >> 5) * 768 + k) * 32 + (n & 31)];
}

// ---------------- small-K SIMT GEMM (kept for t@Vqkv, K=32) ----------------
template <bool BT>
__global__ void gemm_ep(const float* __restrict__ A, const float* __restrict__ Bm,
                        float* __restrict__ C,
                        const float* __restrict__ bias, const float* __restrict__ res,
                        int lda, int ldb, int ldc, int ldres,
                        int K, float scale, int do_gelu, int D2,
                        long long sA1, long long sA2,
                        long long sB1, long long sB2,
                        long long sC1, long long sC2,
                        long long sb1, long long sb2) {
    __shared__ float As[16][65];
    __shared__ float Bs[16][65];
    const int z = blockIdx.z;
    const int i1 = z / D2, i2 = z % D2;
    A += i1 * sA1 + i2 * sA2;
    Bm += i1 * sB1 + i2 * sB2;
    C += i1 * sC1 + i2 * sC2;
    const long long boff = i1 * sb1 + i2 * sb2;

    const int x0 = blockIdx.x * 64, y0 = blockIdx.y * 64;
    const int tid = threadIdx.x;
    const int tx = tid & 15, ty = tid >> 4;
    float acc[4][4] = {};

    for (int k0 = 0; k0 < K; k0 += 16) {
#pragma unroll
        for (int i = 0; i < 4; i++) {
            int idx = tid + i * 256;
            int r = idx >> 4, c = idx & 15;
            As[c][r] = A[(size_t)(y0 + r) * lda + k0 + c];
        }
        if (BT) {
#pragma unroll
            for (int i = 0; i < 4; i++) {
                int idx = tid + i * 256;
                int n = idx >> 4, k = idx & 15;
                Bs[k][n] = Bm[(size_t)(x0 + n) * ldb + k0 + k];
            }
        } else {
#pragma unroll
            for (int i = 0; i < 4; i++) {
                int idx = tid + i * 256;
                int kr = idx >> 6, c = idx & 63;
                Bs[kr][c] = Bm[(size_t)(k0 + kr) * ldb + x0 + c];
            }
        }
        __syncthreads();
#pragma unroll
        for (int kk = 0; kk < 16; kk++) {
            float a[4], bv[4];
#pragma unroll
            for (int i = 0; i < 4; i++) a[i] = As[kk][ty * 4 + i];
#pragma unroll
            for (int j = 0; j < 4; j++) bv[j] = Bs[kk][tx * 4 + j];
#pragma unroll
            for (int i = 0; i < 4; i++)
#pragma unroll
                for (int j = 0; j < 4; j++) acc[i][j] = fmaf(a[i], bv[j], acc[i][j]);
        }
        __syncthreads();
    }

#pragma unroll
    for (int i = 0; i < 4; i++) {
        int m = y0 + ty * 4 + i;
#pragma unroll
        for (int j = 0; j < 4; j++) {
            int n = x0 + tx * 4 + j;
            float v = acc[i][j] * scale;
            if (bias) v += bias[boff + n];
            if (res) v += res[(size_t)m * ldres + n];
            if (do_gelu) v = gelu_exact(v);
            C[(size_t)m * ldc + n] = v;
        }
    }
}

// ---------------- softmax over 1024 cols ----------------
__global__ void softmax_kernel(float* __restrict__ S) {
    __shared__ float red[256];
    float* row = S + (size_t)blockIdx.y * 1024 * 1024 + (size_t)blockIdx.x * 1024;
    const int tid = threadIdx.x;
    float v[4];
    float mx = -1e30f;
#pragma unroll
    for (int i = 0; i < 4; i++) { v[i] = row[tid + i * 256]; mx = fmaxf(mx, v[i]); }
    red[tid] = mx; __syncthreads();
    for (int s = 128; s > 0; s >>= 1) {
        if (tid < s) red[tid] = fmaxf(red[tid], red[tid + s]);
        __syncthreads();
    }
    mx = red[0]; __syncthreads();
    float sum = 0.0f;
#pragma unroll
    for (int i = 0; i < 4; i++) { v[i] = expf(v[i] - mx); sum += v[i]; }
    red[tid] = sum; __syncthreads();
    for (int s = 128; s > 0; s >>= 1) {
        if (tid < s) red[tid] += red[tid + s];
        __syncthreads();
    }
    float inv = 1.0f / red[0];
#pragma unroll
    for (int i = 0; i < 4; i++) row[tid + i * 256] = v[i] * inv;
}

// ---------------- LayerNorm over 768 cols ----------------
__global__ void ln_kernel(const float* __restrict__ in, float* __restrict__ out,
                          const float* __restrict__ g, const float* __restrict__ bb) {
    __shared__ float red[256];
    const float* xr = in + (size_t)blockIdx.x * 768;
    float* yr = out + (size_t)blockIdx.x * 768;
    const int tid = threadIdx.x;
    float v[3];
    float s = 0.0f;
#pragma unroll
    for (int i = 0; i < 3; i++) { v[i] = xr[tid + i * 256]; s += v[i]; }
    red[tid] = s; __syncthreads();
    for (int t = 128; t > 0; t >>= 1) {
        if (tid < t) red[tid] += red[tid + t];
        __syncthreads();
    }
    const float mu = red[0] * (1.0f / 768.0f);
    __syncthreads();
    float ss = 0.0f;
#pragma unroll
    for (int i = 0; i < 3; i++) { float d = v[i] - mu; ss += d * d; }
    red[tid] = ss; __syncthreads();
    for (int t = 128; t > 0; t >>= 1) {
        if (tid < t) red[tid] += red[tid + t];
        __syncthreads();
    }
    const float rs = rsqrtf(red[0] * (1.0f / 768.0f) + 1e-12f);
    __syncthreads();
#pragma unroll
    for (int i = 0; i < 3; i++) {
        int c = tid + i * 256;
        yr[c] = (v[i] - mu) * rs * g[c] + bb[c];
    }
}

extern "C" void kernel_launch(void* const* d_in, const int* in_sizes, int n_in,
                              void* d_out, int out_size) {
    const float* x    = (const float*)d_in[0];
    const float* mask = (const float*)d_in[1];
    const float* Pq   = (const float*)d_in[2];
    const float* Vq   = (const float*)d_in[3];
    const float* bq   = (const float*)d_in[4];
    const float* Pk   = (const float*)d_in[5];
    const float* Vk   = (const float*)d_in[6];
    const float* bk   = (const float*)d_in[7];
    const float* Pv   = (const float*)d_in[8];
    const float* Vv   = (const float*)d_in[9];
    const float* bv   = (const float*)d_in[10];
    const float* Uo   = (const float*)d_in[11];
    const float* Vo   = (const float*)d_in[12];
    const float* bo   = (const float*)d_in[13];
    const float* U1   = (const float*)d_in[14];
    const float* V1   = (const float*)d_in[15];
    const float* b1   = (const float*)d_in[16];
    const float* U2   = (const float*)d_in[17];
    const float* V2   = (const float*)d_in[18];
    const float* b2   = (const float*)d_in[19];
    const float* ln1g = (const float*)d_in[20];
    const float* ln1b = (const float*)d_in[21];
    const float* ln2g = (const float*)d_in[22];
    const float* ln2b = (const float*)d_in[23];
    float* out = (float*)d_out;

    float *w_p, *t_p, *qkv_p, *sc_p, *at2_p, *tmp_p, *x1_p, *y_p, *hdn_p;
    cudaGetSymbolAddress((void**)&w_p,   g_w);
    cudaGetSymbolAddress((void**)&t_p,   g_t);
    cudaGetSymbolAddress((void**)&qkv_p, g_qkv);
    cudaGetSymbolAddress((void**)&sc_p,  g_sc);
    cudaGetSymbolAddress((void**)&at2_p, g_at2);
    cudaGetSymbolAddress((void**)&tmp_p, g_tmp);
    cudaGetSymbolAddress((void**)&x1_p,  g_x1);
    cudaGetSymbolAddress((void**)&y_p,   g_y);
    cudaGetSymbolAddress((void**)&hdn_p, g_hdn);

    const long long T_QKV = 3145728;   // 8*1024*384
    const long long Q_QKV = 6291456;   // 8*12*1024*64
    const long long W_SZ  = 294912;    // 768*384

    // 0) pack P factors into plain [768, 384] weights
    pack_p<<<(3 * 768 * 384 + 255) / 256, 256>>>(Pq, Pk, Pv, w_p);

    // 1) t = x @ W  (z over qkv)
    gemm2<128, 128, false><<<dim3(3, 64, 3), 256>>>(
        x, w_p, t_p, nullptr, nullptr,
        768, 384, 384, 0, 768, 1.0f, 0, 3,
        0LL, 0LL, 0LL, W_SZ, 0LL, T_QKV, 0LL, 0LL);

    // 2) Q/K/V = t @ Vqkv + b   (small K=32; SIMT kernel), z=(b,h)
    const float* Vs[3] = {Vq, Vk, Vv};
    const float* bs[3] = {bq, bk, bv};
    for (int q = 0; q < 3; q++)
        gemm_ep<false><<<dim3(1, 16, 96), 256>>>(
            t_p + q * T_QKV, Vs[q], qkv_p + q * Q_QKV, bs[q], nullptr,
            384, 64, 64, 0, 32, 1.0f, 0, 12,
            393216LL, 32LL, 0LL, 2048LL, 786432LL, 65536LL, 0LL, 64LL);

    // 3) scores = 0.125 * Q@K^T + mask[b,:]   z=(b,h)
    gemm2<128, 128, true><<<dim3(8, 8, 96), 256>>>(
        qkv_p, qkv_p + Q_QKV, sc_p, mask, nullptr,
        64, 64, 1024, 0, 64, 0.125f, 0, 12,
        786432LL, 65536LL, 786432LL, 65536LL,
        12582912LL, 1048576LL, 1024LL, 0LL);

    // 4) softmax rows
    softmax_kernel<<<dim3(1024, 96), 256>>>(sc_p);

    // 5) attn = probs @ V -> [B, M, H*DH]; z=(b,h)
    gemm2<128, 64, false><<<dim3(1, 8, 96), 128>>>(
        sc_p, qkv_p + 2 * Q_QKV, at2_p, nullptr, nullptr,
        1024, 64, 768, 0, 1024, 1.0f, 0, 12,
        12582912LL, 1048576LL, 786432LL, 65536LL,
        786432LL, 64LL, 0LL, 0LL);

    // 6) ao = attn @ Uo
    gemm2<128, 128, false><<<dim3(3, 64, 1), 256>>>(
        at2_p, Uo, tmp_p, nullptr, nullptr,
        768, 384, 384, 0, 768, 1.0f, 0, 1,
        0, 0, 0, 0, 0, 0, 0, 0);

    // 7) x1pre = ao @ Vo + bo + x
    gemm2<128, 128, false><<<dim3(6, 64, 1), 256>>>(
        tmp_p, Vo, y_p, bo, x,
        384, 768, 768, 768, 384, 1.0f, 0, 1,
        0, 0, 0, 0, 0, 0, 0, 0);

    // 8) LN1
    ln_kernel<<<8192, 256>>>(y_p, x1_p, ln1g, ln1b);

    // 9) mid = x1 @ U1
    gemm2<128, 128, false><<<dim3(3, 64, 1), 256>>>(
        x1_p, U1, tmp_p, nullptr, nullptr,
        768, 384, 384, 0, 768, 1.0f, 0, 1,
        0, 0, 0, 0, 0, 0, 0, 0);

    // 10) hdn = gelu(mid @ V1 + b1)
    gemm2<128, 128, false><<<dim3(24, 64, 1), 256>>>(
        tmp_p, V1, hdn_p, b1, nullptr,
        384, 3072, 3072, 0, 384, 1.0f, 1, 1,
        0, 0, 0, 0, 0, 0, 0, 0);

    // 11) h2 = hdn @ U2
    gemm2<128, 128, false><<<dim3(3, 64, 1), 256>>>(
        hdn_p, U2, tmp_p, nullptr, nullptr,
        3072, 384, 384, 0, 3072, 1.0f, 0, 1,
        0, 0, 0, 0, 0, 0, 0, 0);

    // 12) ypre = h2 @ V2 + b2 + x1
    gemm2<128, 128, false><<<dim3(6, 64, 1), 256>>>(
        tmp_p, V2, y_p, b2, x1_p,
        384, 768, 768, 768, 384, 1.0f, 0, 1,
        0, 0, 0, 0, 0, 0, 0, 0);

    // 13) LN2 -> out
    ln_kernel<<<8192, 256>>>(y_p, out, ln2g, ln2b);
}

// round 4
// speedup vs baseline: 2.8202x; 1.9534x over previous
#include <cuda_runtime.h>
#include <math.h>
#include <stdint.h>

// B=8, M=1024, DM=768, H=12, DH=64, R=32, RFF=384, DFF=3072, RWO=384

// ---------------- scratch (device globals) ----------------
__device__ float g_w   [3ull * 768 * 384];
__device__ float g_t   [3ull * 8 * 1024 * 384];
__device__ float g_qkv [3ull * 8 * 12 * 1024 * 64];
__device__ float g_sc  [96ull * 1024 * 1024];
__device__ float g_at2 [8ull * 1024 * 768];
__device__ float g_tmp [8192ull * 384];
__device__ float g_x1  [8192ull * 768];
__device__ float g_y   [8192ull * 768];
__device__ float g_hdn [8192ull * 3072];

__device__ __forceinline__ uint32_t tf32r(float f) {
    uint32_t r;
    asm("cvt.rna.tf32.f32 %0, %1;" : "=r"(r) : "f"(f));
    return r;
}
__device__ __forceinline__ float gelu_exact(float v) {
    return 0.5f * v * (1.0f + erff(v * 0.70710678118654752440f));
}
__device__ __forceinline__ void mma8(float* c, const uint32_t* a, const uint32_t* b) {
    asm volatile(
        "mma.sync.aligned.m16n8k8.row.col.f32.tf32.tf32.f32 "
        "{%0,%1,%2,%3}, {%4,%5,%6,%7}, {%8,%9}, {%0,%1,%2,%3};"
        : "+f"(c[0]), "+f"(c[1]), "+f"(c[2]), "+f"(c[3])
        : "r"(a[0]), "r"(a[1]), "r"(a[2]), "r"(a[3]), "r"(b[0]), "r"(b[1]));
}

// ---------------- tf32 mma.sync GEMM ----------------
// C = scale*(A@B or A@B^T) [+bias[col]] [+res] [gelu]; z = i1*D2+i2.
// A row-major [M,K]; B: BT ? [N,K] : [K,N] row-major. BM=128 fixed.
template <int BN, bool BT>
__global__ void __launch_bounds__(256, 2)
gemm_mma(const float* __restrict__ A, const float* __restrict__ Bm, float* __restrict__ C,
         const float* __restrict__ bias, const float* __restrict__ res,
         int lda, int ldb, int ldc, int ldres, int K, float scale, int do_gelu, int D2,
         long long sA1, long long sA2, long long sB1, long long sB2,
         long long sC1, long long sC2, long long sb1, long long sb2) {
    constexpr int BM = 128;
    constexpr int NT = 256;
    constexpr int WN = BN / 4;          // warp N extent (2x4 warp grid)
    constexpr int NTILES = WN / 8;      // n8 tiles per warp
    constexpr int LA = (BM * 16) / (4 * NT);   // float4 loads of A per thread
    constexpr int LB = (BN * 16) / (4 * NT);
    constexpr int NQ = BN / 4;

    __shared__ float As[2][16][BM + 8];
    __shared__ float Bs[2][16][BN + 8];

    const int z = blockIdx.z;
    const int i1 = z / D2, i2 = z % D2;
    A += i1 * sA1 + i2 * sA2;
    Bm += i1 * sB1 + i2 * sB2;
    C += i1 * sC1 + i2 * sC2;
    const long long boff = i1 * sb1 + i2 * sb2;

    const int x0 = blockIdx.x * BN, y0 = blockIdx.y * BM;
    const int tid = threadIdx.x;
    const int wid = tid >> 5, lane = tid & 31;
    const int wm0 = (wid >> 2) * 64;
    const int wn0 = (wid & 3) * WN;
    const int qr = lane >> 2, qc = lane & 3;

    float4 ra[LA], rb[LB];

    auto ldg = [&](int k0) {
#pragma unroll
        for (int i = 0; i < LA; i++) {
            int f = tid + i * NT;
            int m = f >> 2, kq = f & 3;
            ra[i] = *(const float4*)(A + (size_t)(y0 + m) * lda + k0 + kq * 4);
        }
#pragma unroll
        for (int i = 0; i < LB; i++) {
            int f = tid + i * NT;
            if (BT) {
                int n = f >> 2, kq = f & 3;
                rb[i] = *(const float4*)(Bm + (size_t)(x0 + n) * ldb + k0 + kq * 4);
            } else {
                int k = f / NQ, nq = f % NQ;
                rb[i] = *(const float4*)(Bm + (size_t)(k0 + k) * ldb + x0 + nq * 4);
            }
        }
    };
    auto sts = [&](int buf) {
#pragma unroll
        for (int i = 0; i < LA; i++) {
            int f = tid + i * NT;
            int m = f >> 2, kq = f & 3;
            As[buf][kq * 4 + 0][m] = __uint_as_float(tf32r(ra[i].x));
            As[buf][kq * 4 + 1][m] = __uint_as_float(tf32r(ra[i].y));
            As[buf][kq * 4 + 2][m] = __uint_as_float(tf32r(ra[i].z));
            As[buf][kq * 4 + 3][m] = __uint_as_float(tf32r(ra[i].w));
        }
#pragma unroll
        for (int i = 0; i < LB; i++) {
            int f = tid + i * NT;
            if (BT) {
                int n = f >> 2, kq = f & 3;
                Bs[buf][kq * 4 + 0][n] = __uint_as_float(tf32r(rb[i].x));
                Bs[buf][kq * 4 + 1][n] = __uint_as_float(tf32r(rb[i].y));
                Bs[buf][kq * 4 + 2][n] = __uint_as_float(tf32r(rb[i].z));
                Bs[buf][kq * 4 + 3][n] = __uint_as_float(tf32r(rb[i].w));
            } else {
                int k = f / NQ, nq = f % NQ;
                float4 t;
                t.x = __uint_as_float(tf32r(rb[i].x));
                t.y = __uint_as_float(tf32r(rb[i].y));
                t.z = __uint_as_float(tf32r(rb[i].z));
                t.w = __uint_as_float(tf32r(rb[i].w));
                *(float4*)&Bs[buf][k][nq * 4] = t;
            }
        }
    };

    float acc[4][NTILES][4];
#pragma unroll
    for (int i = 0; i < 4; i++)
#pragma unroll
        for (int j = 0; j < NTILES; j++)
#pragma unroll
            for (int l = 0; l < 4; l++) acc[i][j][l] = 0.0f;

    ldg(0);
    sts(0);
    __syncthreads();
    const int nb = K >> 4;
    for (int kb = 0; kb < nb; kb++) {
        const int cur = kb & 1;
        if (kb + 1 < nb) ldg((kb + 1) << 4);
#pragma unroll
        for (int kk = 0; kk < 16; kk += 8) {
            uint32_t af[4][4], bf[NTILES][2];
#pragma unroll
            for (int mt = 0; mt < 4; mt++) {
                int m = wm0 + mt * 16 + qr;
                af[mt][0] = __float_as_uint(As[cur][kk + qc][m]);
                af[mt][1] = __float_as_uint(As[cur][kk + qc][m + 8]);
                af[mt][2] = __float_as_uint(As[cur][kk + qc + 4][m]);
                af[mt][3] = __float_as_uint(As[cur][kk + qc + 4][m + 8]);
            }
#pragma unroll
            for (int nt = 0; nt < NTILES; nt++) {
                int n = wn0 + nt * 8 + qr;
                bf[nt][0] = __float_as_uint(Bs[cur][kk + qc][n]);
                bf[nt][1] = __float_as_uint(Bs[cur][kk + qc + 4][n]);
            }
#pragma unroll
            for (int mt = 0; mt < 4; mt++)
#pragma unroll
                for (int nt = 0; nt < NTILES; nt++) mma8(acc[mt][nt], af[mt], bf[nt]);
        }
        if (kb + 1 < nb) sts(cur ^ 1);
        __syncthreads();
    }

    // ---- epilogue ----
#pragma unroll
    for (int mt = 0; mt < 4; mt++) {
#pragma unroll
        for (int nt = 0; nt < NTILES; nt++) {
            const int n = x0 + wn0 + nt * 8 + qc * 2;
#pragma unroll
            for (int half = 0; half < 2; half++) {
                const int m = y0 + wm0 + mt * 16 + qr + half * 8;
                float v0 = acc[mt][nt][half * 2 + 0] * scale;
                float v1 = acc[mt][nt][half * 2 + 1] * scale;
                if (bias) { v0 += bias[boff + n]; v1 += bias[boff + n + 1]; }
                if (res) {
                    v0 += res[(size_t)m * ldres + n];
                    v1 += res[(size_t)m * ldres + n + 1];
                }
                if (do_gelu) { v0 = gelu_exact(v0); v1 = gelu_exact(v1); }
                *(float2*)(C + (size_t)m * ldc + n) = make_float2(v0, v1);
            }
        }
    }
}

// ---------------- pack P [H,DM,R] -> W [DM, H*R] ----------------
__global__ void pack_p(const float* __restrict__ Pq, const float* __restrict__ Pk,
                       const float* __restrict__ Pv, float* __restrict__ W) {
    int idx = blockIdx.x * blockDim.x + threadIdx.x;
    if (idx >= 3 * 768 * 384) return;
    int q = idx / (768 * 384);
    int r2 = idx % (768 * 384);
    int k = r2 / 384, n = r2 % 384;
    const float* P = (q == 0) ? Pq : ((q == 1) ? Pk : Pv);
    W[idx] = P[((size_t)(n >> 5) * 768 + k) * 32 + (n & 31)];
}

// ---------------- softmax over 1024 cols ----------------
__global__ void softmax_kernel(float* __restrict__ S) {
    __shared__ float red[256];
    float* row = S + (size_t)blockIdx.y * 1024 * 1024 + (size_t)blockIdx.x * 1024;
    const int tid = threadIdx.x;
    float v[4];
    float mx = -1e30f;
#pragma unroll
    for (int i = 0; i < 4; i++) { v[i] = row[tid + i * 256]; mx = fmaxf(mx, v[i]); }
    red[tid] = mx; __syncthreads();
    for (int s = 128; s > 0; s >>= 1) {
        if (tid < s) red[tid] = fmaxf(red[tid], red[tid + s]);
        __syncthreads();
    }
    mx = red[0]; __syncthreads();
    float sum = 0.0f;
#pragma unroll
    for (int i = 0; i < 4; i++) { v[i] = expf(v[i] - mx); sum += v[i]; }
    red[tid] = sum; __syncthreads();
    for (int s = 128; s > 0; s >>= 1) {
        if (tid < s) red[tid] += red[tid + s];
        __syncthreads();
    }
    float inv = 1.0f / red[0];
#pragma unroll
    for (int i = 0; i < 4; i++) row[tid + i * 256] = v[i] * inv;
}

// ---------------- LayerNorm over 768 cols ----------------
__global__ void ln_kernel(const float* __restrict__ in, float* __restrict__ out,
                          const float* __restrict__ g, const float* __restrict__ bb) {
    __shared__ float red[256];
    const float* xr = in + (size_t)blockIdx.x * 768;
    float* yr = out + (size_t)blockIdx.x * 768;
    const int tid = threadIdx.x;
    float v[3];
    float s = 0.0f;
#pragma unroll
    for (int i = 0; i < 3; i++) { v[i] = xr[tid + i * 256]; s += v[i]; }
    red[tid] = s; __syncthreads();
    for (int t = 128; t > 0; t >>= 1) {
        if (tid < t) red[tid] += red[tid + t];
        __syncthreads();
    }
    const float mu = red[0] * (1.0f / 768.0f);
    __syncthreads();
    float ss = 0.0f;
#pragma unroll
    for (int i = 0; i < 3; i++) { float d = v[i] - mu; ss += d * d; }
    red[tid] = ss; __syncthreads();
    for (int t = 128; t > 0; t >>= 1) {
        if (tid < t) red[tid] += red[tid + t];
        __syncthreads();
    }
    const float rs = rsqrtf(red[0] * (1.0f / 768.0f) + 1e-12f);
    __syncthreads();
#pragma unroll
    for (int i = 0; i < 3; i++) {
        int c = tid + i * 256;
        yr[c] = (v[i] - mu) * rs * g[c] + bb[c];
    }
}

extern "C" void kernel_launch(void* const* d_in, const int* in_sizes, int n_in,
                              void* d_out, int out_size) {
    const float* x    = (const float*)d_in[0];
    const float* mask = (const float*)d_in[1];
    const float* Pq   = (const float*)d_in[2];
    const float* Vq   = (const float*)d_in[3];
    const float* bq   = (const float*)d_in[4];
    const float* Pk   = (const float*)d_in[5];
    const float* Vk   = (const float*)d_in[6];
    const float* bk   = (const float*)d_in[7];
    const float* Pv   = (const float*)d_in[8];
    const float* Vv   = (const float*)d_in[9];
    const float* bv   = (const float*)d_in[10];
    const float* Uo   = (const float*)d_in[11];
    const float* Vo   = (const float*)d_in[12];
    const float* bo   = (const float*)d_in[13];
    const float* U1   = (const float*)d_in[14];
    const float* V1   = (const float*)d_in[15];
    const float* b1   = (const float*)d_in[16];
    const float* U2   = (const float*)d_in[17];
    const float* V2   = (const float*)d_in[18];
    const float* b2   = (const float*)d_in[19];
    const float* ln1g = (const float*)d_in[20];
    const float* ln1b = (const float*)d_in[21];
    const float* ln2g = (const float*)d_in[22];
    const float* ln2b = (const float*)d_in[23];
    float* out = (float*)d_out;

    float *w_p, *t_p, *qkv_p, *sc_p, *at2_p, *tmp_p, *x1_p, *y_p, *hdn_p;
    cudaGetSymbolAddress((void**)&w_p,   g_w);
    cudaGetSymbolAddress((void**)&t_p,   g_t);
    cudaGetSymbolAddress((void**)&qkv_p, g_qkv);
    cudaGetSymbolAddress((void**)&sc_p,  g_sc);
    cudaGetSymbolAddress((void**)&at2_p, g_at2);
    cudaGetSymbolAddress((void**)&tmp_p, g_tmp);
    cudaGetSymbolAddress((void**)&x1_p,  g_x1);
    cudaGetSymbolAddress((void**)&y_p,   g_y);
    cudaGetSymbolAddress((void**)&hdn_p, g_hdn);

    const long long T_QKV = 3145728, Q_QKV = 6291456, W_SZ = 294912;

    // 0) pack P
    pack_p<<<(3 * 768 * 384 + 255) / 256, 256>>>(Pq, Pk, Pv, w_p);

    // 1) t = x @ W   (z over qkv)
    gemm_mma<128, false><<<dim3(3, 64, 3), 256>>>(
        x, w_p, t_p, nullptr, nullptr,
        768, 384, 384, 0, 768, 1.0f, 0, 3,
        0LL, 0LL, 0LL, W_SZ, 0LL, T_QKV, 0LL, 0LL);

    // 2) Q/K/V = t @ Vqkv + b   z=(b,h), K=32
    const float* Vs[3] = {Vq, Vk, Vv};
    const float* bs[3] = {bq, bk, bv};
    for (int q = 0; q < 3; q++)
        gemm_mma<64, false><<<dim3(1, 8, 96), 256>>>(
            t_p + q * T_QKV, Vs[q], qkv_p + q * Q_QKV, bs[q], nullptr,
            384, 64, 64, 0, 32, 1.0f, 0, 12,
            393216LL, 32LL, 0LL, 2048LL, 786432LL, 65536LL, 0LL, 64LL);

    // 3) scores = 0.125 * Q@K^T + mask[b,:]   z=(b,h)
    gemm_mma<128, true><<<dim3(8, 8, 96), 256>>>(
        qkv_p, qkv_p + Q_QKV, sc_p, mask, nullptr,
        64, 64, 1024, 0, 64, 0.125f, 0, 12,
        786432LL, 65536LL, 786432LL, 65536LL,
        12582912LL, 1048576LL, 1024LL, 0LL);

    // 4) softmax
    softmax_kernel<<<dim3(1024, 96), 256>>>(sc_p);

    // 5) attn = probs @ V -> [B,M,H*DH]   z=(b,h), K=1024
    gemm_mma<64, false><<<dim3(1, 8, 96), 256>>>(
        sc_p, qkv_p + 2 * Q_QKV, at2_p, nullptr, nullptr,
        1024, 64, 768, 0, 1024, 1.0f, 0, 12,
        12582912LL, 1048576LL, 786432LL, 65536LL,
        786432LL, 64LL, 0LL, 0LL);

    // 6) ao = attn @ Uo
    gemm_mma<128, false><<<dim3(3, 64, 1), 256>>>(
        at2_p, Uo, tmp_p, nullptr, nullptr,
        768, 384, 384, 0, 768, 1.0f, 0, 1, 0, 0, 0, 0, 0, 0, 0, 0);

    // 7) x1pre = ao @ Vo + bo + x
    gemm_mma<128, false><<<dim3(6, 64, 1), 256>>>(
        tmp_p, Vo, y_p, bo, x,
        384, 768, 768, 768, 384, 1.0f, 0, 1, 0, 0, 0, 0, 0, 0, 0, 0);

    // 8) LN1
    ln_kernel<<<8192, 256>>>(y_p, x1_p, ln1g, ln1b);

    // 9) mid = x1 @ U1
    gemm_mma<128, false><<<dim3(3, 64, 1), 256>>>(
        x1_p, U1, tmp_p, nullptr, nullptr,
        768, 384, 384, 0, 768, 1.0f, 0, 1, 0, 0, 0, 0, 0, 0, 0, 0);

    // 10) hdn = gelu(mid @ V1 + b1)
    gemm_mma<128, false><<<dim3(24, 64, 1), 256>>>(
        tmp_p, V1, hdn_p, b1, nullptr,
        384, 3072, 3072, 0, 384, 1.0f, 1, 1, 0, 0, 0, 0, 0, 0, 0, 0);

    // 11) h2 = hdn @ U2
    gemm_mma<128, false><<<dim3(3, 64, 1), 256>>>(
        hdn_p, U2, tmp_p, nullptr, nullptr,
        3072, 384, 384, 0, 3072, 1.0f, 0, 1, 0, 0, 0, 0, 0, 0, 0, 0);

    // 12) ypre = h2 @ V2 + b2 + x1
    gemm_mma<128, false><<<dim3(6, 64, 1), 256>>>(
        tmp_p, V2, y_p, b2, x1_p,
        384, 768, 768, 768, 384, 1.0f, 0, 1, 0, 0, 0, 0, 0, 0, 0, 0);

    // 13) LN2 -> out
    ln_kernel<<<8192, 256>>>(y_p, out, ln2g, ln2b);
}

// round 5
// speedup vs baseline: 3.6235x; 1.2848x over previous
#include <cuda_runtime.h>
#include <math.h>
#include <stdint.h>

// B=8, M=1024, DM=768, H=12, DH=64, R=32, RFF=384, DFF=3072, RWO=384

// ---------------- scratch (device globals) ----------------
__device__ float g_w   [3ull * 768 * 384];
__device__ float g_t   [3ull * 8 * 1024 * 384];
__device__ float g_qkv [3ull * 8 * 12 * 1024 * 64];
__device__ float g_at2 [8ull * 1024 * 768];
__device__ float g_tmp [8192ull * 384];
__device__ float g_x1  [8192ull * 768];
__device__ float g_y   [8192ull * 768];
__device__ float g_hdn [8192ull * 3072];

__device__ __forceinline__ uint32_t tf32r(float f) {
    uint32_t r;
    asm("cvt.rna.tf32.f32 %0, %1;" : "=r"(r) : "f"(f));
    return r;
}
__device__ __forceinline__ float gelu_exact(float v) {
    return 0.5f * v * (1.0f + erff(v * 0.70710678118654752440f));
}
__device__ __forceinline__ void mma8(float* c, const uint32_t* a, const uint32_t* b) {
    asm volatile(
        "mma.sync.aligned.m16n8k8.row.col.f32.tf32.tf32.f32 "
        "{%0,%1,%2,%3}, {%4,%5,%6,%7}, {%8,%9}, {%0,%1,%2,%3};"
        : "+f"(c[0]), "+f"(c[1]), "+f"(c[2]), "+f"(c[3])
        : "r"(a[0]), "r"(a[1]), "r"(a[2]), "r"(a[3]), "r"(b[0]), "r"(b[1]));
}

// ================= fused flash attention =================
// grid: (8 q-tiles, 96 b*h). block 256 (8 warps, 16 rows each).
// Q/K/V: [bh][1024][64]; out: at2[b][m][h*64+d] (ldc 768).
#define FL_PAD 76
__global__ void __launch_bounds__(256, 1)
flash_attn(const float* __restrict__ Qg, const float* __restrict__ Kg,
           const float* __restrict__ Vg, const float* __restrict__ maskg,
           float* __restrict__ Og) {
    extern __shared__ float sm[];
    float* Ks = sm;                       // [128][FL_PAD]
    float* Vs = sm + 128 * FL_PAD;        // [128][FL_PAD]
    float* Ms = Vs + 128 * FL_PAD;        // [128]

    const int bh = blockIdx.y;
    const int b = bh / 12, h = bh % 12;
    const float* Q = Qg + (size_t)bh * 65536;
    const float* K = Kg + (size_t)bh * 65536;
    const float* V = Vg + (size_t)bh * 65536;
    const float* mask = maskg + b * 1024;
    float* O = Og + (size_t)b * 1024 * 768 + h * 64;

    const int tid = threadIdx.x;
    const int wid = tid >> 5, lane = tid & 31;
    const int qr = lane >> 2, qc = lane & 3;
    const int m0row = blockIdx.x * 128 + wid * 16;

    // ---- Q fragments (scaled by 1/8, tf32) ----
    uint32_t qf[8][4];
    {
        const float* Qr0 = Q + (size_t)(m0row + qr) * 64;
        const float* Qr1 = Q + (size_t)(m0row + qr + 8) * 64;
#pragma unroll
        for (int kd = 0; kd < 8; kd++) {
            qf[kd][0] = tf32r(Qr0[kd * 8 + qc] * 0.125f);
            qf[kd][1] = tf32r(Qr1[kd * 8 + qc] * 0.125f);
            qf[kd][2] = tf32r(Qr0[kd * 8 + qc + 4] * 0.125f);
            qf[kd][3] = tf32r(Qr1[kd * 8 + qc + 4] * 0.125f);
        }
    }

    float oacc[8][4];
#pragma unroll
    for (int i = 0; i < 8; i++)
#pragma unroll
        for (int j = 0; j < 4; j++) oacc[i][j] = 0.0f;
    float mrow0 = -INFINITY, mrow1 = -INFINITY, lrow0 = 0.0f, lrow1 = 0.0f;

    for (int c = 0; c < 8; c++) {
        const int kvb = c << 7;
        __syncthreads();
        // ---- load K/V chunk (natural [kv][d], tf32-rounded) ----
#pragma unroll
        for (int i = 0; i < 8; i++) {
            int f = tid + (i << 8);
            int kv = f >> 4, dq = (f & 15) << 2;
            float4 kvv = *(const float4*)(K + (size_t)(kvb + kv) * 64 + dq);
            float4 vvv = *(const float4*)(V + (size_t)(kvb + kv) * 64 + dq);
            float4 kt, vt;
            kt.x = __uint_as_float(tf32r(kvv.x)); kt.y = __uint_as_float(tf32r(kvv.y));
            kt.z = __uint_as_float(tf32r(kvv.z)); kt.w = __uint_as_float(tf32r(kvv.w));
            vt.x = __uint_as_float(tf32r(vvv.x)); vt.y = __uint_as_float(tf32r(vvv.y));
            vt.z = __uint_as_float(tf32r(vvv.z)); vt.w = __uint_as_float(tf32r(vvv.w));
            *(float4*)&Ks[kv * FL_PAD + dq] = kt;
            *(float4*)&Vs[kv * FL_PAD + dq] = vt;
        }
        if (tid < 32) *(float4*)&Ms[tid * 4] = *(const float4*)(mask + kvb + tid * 4);
        __syncthreads();

        // ---- S = (Q/8) @ K^T ----
        float sacc[16][4];
#pragma unroll
        for (int nt = 0; nt < 16; nt++) {
            sacc[nt][0] = sacc[nt][1] = sacc[nt][2] = sacc[nt][3] = 0.0f;
            const int n = nt * 8 + qr;
#pragma unroll
            for (int kd = 0; kd < 8; kd++) {
                uint32_t bf[2];
                bf[0] = __float_as_uint(Ks[n * FL_PAD + kd * 8 + qc]);
                bf[1] = __float_as_uint(Ks[n * FL_PAD + kd * 8 + qc + 4]);
                mma8(sacc[nt], qf[kd], bf);
            }
        }

        // ---- online softmax (rows qr / qr+8) ----
        float cm0 = -INFINITY, cm1 = -INFINITY;
#pragma unroll
        for (int nt = 0; nt < 16; nt++) {
            float mk0 = Ms[nt * 8 + 2 * qc], mk1 = Ms[nt * 8 + 2 * qc + 1];
            sacc[nt][0] += mk0; sacc[nt][1] += mk1;
            sacc[nt][2] += mk0; sacc[nt][3] += mk1;
            cm0 = fmaxf(cm0, fmaxf(sacc[nt][0], sacc[nt][1]));
            cm1 = fmaxf(cm1, fmaxf(sacc[nt][2], sacc[nt][3]));
        }
        cm0 = fmaxf(cm0, __shfl_xor_sync(0xffffffffu, cm0, 1));
        cm0 = fmaxf(cm0, __shfl_xor_sync(0xffffffffu, cm0, 2));
        cm1 = fmaxf(cm1, __shfl_xor_sync(0xffffffffu, cm1, 1));
        cm1 = fmaxf(cm1, __shfl_xor_sync(0xffffffffu, cm1, 2));
        const float mn0 = fmaxf(mrow0, cm0), mn1 = fmaxf(mrow1, cm1);
        const float al0 = __expf(mrow0 - mn0), al1 = __expf(mrow1 - mn1);
        mrow0 = mn0; mrow1 = mn1;
        float sum0 = 0.0f, sum1 = 0.0f;
#pragma unroll
        for (int nt = 0; nt < 16; nt++) {
            sacc[nt][0] = __expf(sacc[nt][0] - mn0);
            sacc[nt][1] = __expf(sacc[nt][1] - mn0);
            sacc[nt][2] = __expf(sacc[nt][2] - mn1);
            sacc[nt][3] = __expf(sacc[nt][3] - mn1);
            sum0 += sacc[nt][0] + sacc[nt][1];
            sum1 += sacc[nt][2] + sacc[nt][3];
        }
        sum0 += __shfl_xor_sync(0xffffffffu, sum0, 1);
        sum0 += __shfl_xor_sync(0xffffffffu, sum0, 2);
        sum1 += __shfl_xor_sync(0xffffffffu, sum1, 1);
        sum1 += __shfl_xor_sync(0xffffffffu, sum1, 2);
        lrow0 = lrow0 * al0 + sum0;
        lrow1 = lrow1 * al1 + sum1;
#pragma unroll
        for (int i = 0; i < 8; i++) {
            oacc[i][0] *= al0; oacc[i][1] *= al0;
            oacc[i][2] *= al1; oacc[i][3] *= al1;
        }

        // ---- O += P @ V ----
        const int src0 = (qr << 2) | (qc >> 1);
        const int src1 = src0 + 2;
        const bool odd = qc & 1;
#pragma unroll
        for (int kt = 0; kt < 16; kt++) {
            float p0 = sacc[kt][0], p1 = sacc[kt][1], p2 = sacc[kt][2], p3 = sacc[kt][3];
            float t00 = __shfl_sync(0xffffffffu, p0, src0);
            float t01 = __shfl_sync(0xffffffffu, p1, src0);
            float t10 = __shfl_sync(0xffffffffu, p0, src1);
            float t11 = __shfl_sync(0xffffffffu, p1, src1);
            float u00 = __shfl_sync(0xffffffffu, p2, src0);
            float u01 = __shfl_sync(0xffffffffu, p3, src0);
            float u10 = __shfl_sync(0xffffffffu, p2, src1);
            float u11 = __shfl_sync(0xffffffffu, p3, src1);
            uint32_t af[4];
            af[0] = tf32r(odd ? t01 : t00);
            af[1] = tf32r(odd ? u01 : u00);
            af[2] = tf32r(odd ? t11 : t10);
            af[3] = tf32r(odd ? u11 : u10);
#pragma unroll
            for (int nt2 = 0; nt2 < 8; nt2++) {
                const int n = nt2 * 8 + qr;
                uint32_t bf[2];
                bf[0] = __float_as_uint(Vs[(kt * 8 + qc) * FL_PAD + n]);
                bf[1] = __float_as_uint(Vs[(kt * 8 + qc + 4) * FL_PAD + n]);
                mma8(oacc[nt2], af, bf);
            }
        }
    }

    // ---- write out ----
    const float il0 = 1.0f / lrow0, il1 = 1.0f / lrow1;
    const int r0 = m0row + qr, r1 = m0row + qr + 8;
#pragma unroll
    for (int nt2 = 0; nt2 < 8; nt2++) {
        const int col = nt2 * 8 + 2 * qc;
        *(float2*)(O + (size_t)r0 * 768 + col) =
            make_float2(oacc[nt2][0] * il0, oacc[nt2][1] * il0);
        *(float2*)(O + (size_t)r1 * 768 + col) =
            make_float2(oacc[nt2][2] * il1, oacc[nt2][3] * il1);
    }
}

// ---------------- tf32 mma.sync GEMM (unchanged core) ----------------
template <int BN, bool BT>
__global__ void __launch_bounds__(256, 2)
gemm_mma(const float* __restrict__ A, const float* __restrict__ Bm, float* __restrict__ C,
         const float* __restrict__ bias, const float* __restrict__ res,
         int lda, int ldb, int ldc, int ldres, int K, float scale, int do_gelu, int D2,
         long long sA1, long long sA2, long long sB1, long long sB2,
         long long sC1, long long sC2, long long sb1, long long sb2) {
    constexpr int BM = 128;
    constexpr int NT = 256;
    constexpr int WN = BN / 4;
    constexpr int NTILES = WN / 8;
    constexpr int LA = (BM * 16) / (4 * NT);
    constexpr int LB = (BN * 16) / (4 * NT);
    constexpr int NQ = BN / 4;

    __shared__ float As[2][16][BM + 8];
    __shared__ float Bs[2][16][BN + 8];

    const int z = blockIdx.z;
    const int i1 = z / D2, i2 = z % D2;
    A += i1 * sA1 + i2 * sA2;
    Bm += i1 * sB1 + i2 * sB2;
    C += i1 * sC1 + i2 * sC2;
    const long long boff = i1 * sb1 + i2 * sb2;

    const int x0 = blockIdx.x * BN, y0 = blockIdx.y * BM;
    const int tid = threadIdx.x;
    const int wid = tid >> 5, lane = tid & 31;
    const int wm0 = (wid >> 2) * 64;
    const int wn0 = (wid & 3) * WN;
    const int qr = lane >> 2, qc = lane & 3;

    float4 ra[LA], rb[LB];

    auto ldg = [&](int k0) {
#pragma unroll
        for (int i = 0; i < LA; i++) {
            int f = tid + i * NT;
            int m = f >> 2, kq = f & 3;
            ra[i] = *(const float4*)(A + (size_t)(y0 + m) * lda + k0 + kq * 4);
        }
#pragma unroll
        for (int i = 0; i < LB; i++) {
            int f = tid + i * NT;
            if (BT) {
                int n = f >> 2, kq = f & 3;
                rb[i] = *(const float4*)(Bm + (size_t)(x0 + n) * ldb + k0 + kq * 4);
            } else {
                int k = f / NQ, nq = f % NQ;
                rb[i] = *(const float4*)(Bm + (size_t)(k0 + k) * ldb + x0 + nq * 4);
            }
        }
    };
    auto sts = [&](int buf) {
#pragma unroll
        for (int i = 0; i < LA; i++) {
            int f = tid + i * NT;
            int m = f >> 2, kq = f & 3;
            As[buf][kq * 4 + 0][m] = __uint_as_float(tf32r(ra[i].x));
            As[buf][kq * 4 + 1][m] = __uint_as_float(tf32r(ra[i].y));
            As[buf][kq * 4 + 2][m] = __uint_as_float(tf32r(ra[i].z));
            As[buf][kq * 4 + 3][m] = __uint_as_float(tf32r(ra[i].w));
        }
#pragma unroll
        for (int i = 0; i < LB; i++) {
            int f = tid + i * NT;
            if (BT) {
                int n = f >> 2, kq = f & 3;
                Bs[buf][kq * 4 + 0][n] = __uint_as_float(tf32r(rb[i].x));
                Bs[buf][kq * 4 + 1][n] = __uint_as_float(tf32r(rb[i].y));
                Bs[buf][kq * 4 + 2][n] = __uint_as_float(tf32r(rb[i].z));
                Bs[buf][kq * 4 + 3][n] = __uint_as_float(tf32r(rb[i].w));
            } else {
                int k = f / NQ, nq = f % NQ;
                float4 t;
                t.x = __uint_as_float(tf32r(rb[i].x));
                t.y = __uint_as_float(tf32r(rb[i].y));
                t.z = __uint_as_float(tf32r(rb[i].z));
                t.w = __uint_as_float(tf32r(rb[i].w));
                *(float4*)&Bs[buf][k][nq * 4] = t;
            }
        }
    };

    float acc[4][NTILES][4];
#pragma unroll
    for (int i = 0; i < 4; i++)
#pragma unroll
        for (int j = 0; j < NTILES; j++)
#pragma unroll
            for (int l = 0; l < 4; l++) acc[i][j][l] = 0.0f;

    ldg(0);
    sts(0);
    __syncthreads();
    const int nb = K >> 4;
    for (int kb = 0; kb < nb; kb++) {
        const int cur = kb & 1;
        if (kb + 1 < nb) ldg((kb + 1) << 4);
#pragma unroll
        for (int kk = 0; kk < 16; kk += 8) {
            uint32_t af[4][4], bf[NTILES][2];
#pragma unroll
            for (int mt = 0; mt < 4; mt++) {
                int m = wm0 + mt * 16 + qr;
                af[mt][0] = __float_as_uint(As[cur][kk + qc][m]);
                af[mt][1] = __float_as_uint(As[cur][kk + qc][m + 8]);
                af[mt][2] = __float_as_uint(As[cur][kk + qc + 4][m]);
                af[mt][3] = __float_as_uint(As[cur][kk + qc + 4][m + 8]);
            }
#pragma unroll
            for (int nt = 0; nt < NTILES; nt++) {
                int n = wn0 + nt * 8 + qr;
                bf[nt][0] = __float_as_uint(Bs[cur][kk + qc][n]);
                bf[nt][1] = __float_as_uint(Bs[cur][kk + qc + 4][n]);
            }
#pragma unroll
            for (int mt = 0; mt < 4; mt++)
#pragma unroll
                for (int nt = 0; nt < NTILES; nt++) mma8(acc[mt][nt], af[mt], bf[nt]);
        }
        if (kb + 1 < nb) sts(cur ^ 1);
        __syncthreads();
    }

#pragma unroll
    for (int mt = 0; mt < 4; mt++) {
#pragma unroll
        for (int nt = 0; nt < NTILES; nt++) {
            const int n = x0 + wn0 + nt * 8 + qc * 2;
#pragma unroll
            for (int half = 0; half < 2; half++) {
                const int m = y0 + wm0 + mt * 16 + qr + half * 8;
                float v0 = acc[mt][nt][half * 2 + 0] * scale;
                float v1 = acc[mt][nt][half * 2 + 1] * scale;
                if (bias) { v0 += bias[boff + n]; v1 += bias[boff + n + 1]; }
                if (res) {
                    v0 += res[(size_t)m * ldres + n];
                    v1 += res[(size_t)m * ldres + n + 1];
                }
                if (do_gelu) { v0 = gelu_exact(v0); v1 = gelu_exact(v1); }
                *(float2*)(C + (size_t)m * ldc + n) = make_float2(v0, v1);
            }
        }
    }
}

// ---------------- pack P [H,DM,R] -> W [DM, H*R] ----------------
__global__ void pack_p(const float* __restrict__ Pq, const float* __restrict__ Pk,
                       const float* __restrict__ Pv, float* __restrict__ W) {
    int idx = blockIdx.x * blockDim.x + threadIdx.x;
    if (idx >= 3 * 768 * 384) return;
    int q = idx / (768 * 384);
    int r2 = idx % (768 * 384);
    int k = r2 / 384, n = r2 % 384;
    const float* P = (q == 0) ? Pq : ((q == 1) ? Pk : Pv);
    W[idx] = P[((size_t)(n >> 5) * 768 + k) * 32 + (n & 31)];
}

// ---------------- LayerNorm over 768 cols ----------------
__global__ void ln_kernel(const float* __restrict__ in, float* __restrict__ out,
                          const float* __restrict__ g, const float* __restrict__ bb) {
    __shared__ float red[256];
    const float* xr = in + (size_t)blockIdx.x * 768;
    float* yr = out + (size_t)blockIdx.x * 768;
    const int tid = threadIdx.x;
    float v[3];
    float s = 0.0f;
#pragma unroll
    for (int i = 0; i < 3; i++) { v[i] = xr[tid + i * 256]; s += v[i]; }
    red[tid] = s; __syncthreads();
    for (int t = 128; t > 0; t >>= 1) {
        if (tid < t) red[tid] += red[tid + t];
        __syncthreads();
    }
    const float mu = red[0] * (1.0f / 768.0f);
    __syncthreads();
    float ss = 0.0f;
#pragma unroll
    for (int i = 0; i < 3; i++) { float d = v[i] - mu; ss += d * d; }
    red[tid] = ss; __syncthreads();
    for (int t = 128; t > 0; t >>= 1) {
        if (tid < t) red[tid] += red[tid + t];
        __syncthreads();
    }
    const float rs = rsqrtf(red[0] * (1.0f / 768.0f) + 1e-12f);
    __syncthreads();
#pragma unroll
    for (int i = 0; i < 3; i++) {
        int c = tid + i * 256;
        yr[c] = (v[i] - mu) * rs * g[c] + bb[c];
    }
}

extern "C" void kernel_launch(void* const* d_in, const int* in_sizes, int n_in,
                              void* d_out, int out_size) {
    const float* x    = (const float*)d_in[0];
    const float* mask = (const float*)d_in[1];
    const float* Pq   = (const float*)d_in[2];
    const float* Vq   = (const float*)d_in[3];
    const float* bq   = (const float*)d_in[4];
    const float* Pk   = (const float*)d_in[5];
    const float* Vk   = (const float*)d_in[6];
    const float* bk   = (const float*)d_in[7];
    const float* Pv   = (const float*)d_in[8];
    const float* Vv   = (const float*)d_in[9];
    const float* bv   = (const float*)d_in[10];
    const float* Uo   = (const float*)d_in[11];
    const float* Vo   = (const float*)d_in[12];
    const float* bo   = (const float*)d_in[13];
    const float* U1   = (const float*)d_in[14];
    const float* V1   = (const float*)d_in[15];
    const float* b1   = (const float*)d_in[16];
    const float* U2   = (const float*)d_in[17];
    const float* V2   = (const float*)d_in[18];
    const float* b2   = (const float*)d_in[19];
    const float* ln1g = (const float*)d_in[20];
    const float* ln1b = (const float*)d_in[21];
    const float* ln2g = (const float*)d_in[22];
    const float* ln2b = (const float*)d_in[23];
    float* out = (float*)d_out;

    float *w_p, *t_p, *qkv_p, *at2_p, *tmp_p, *x1_p, *y_p, *hdn_p;
    cudaGetSymbolAddress((void**)&w_p,   g_w);
    cudaGetSymbolAddress((void**)&t_p,   g_t);
    cudaGetSymbolAddress((void**)&qkv_p, g_qkv);
    cudaGetSymbolAddress((void**)&at2_p, g_at2);
    cudaGetSymbolAddress((void**)&tmp_p, g_tmp);
    cudaGetSymbolAddress((void**)&x1_p,  g_x1);
    cudaGetSymbolAddress((void**)&y_p,   g_y);
    cudaGetSymbolAddress((void**)&hdn_p, g_hdn);

    const long long T_QKV = 3145728, Q_QKV = 6291456, W_SZ = 294912;
    const int FL_SMEM = (2 * 128 * FL_PAD + 128) * 4;
    cudaFuncSetAttribute(flash_attn, cudaFuncAttributeMaxDynamicSharedMemorySize, FL_SMEM);

    // 0) pack P
    pack_p<<<(3 * 768 * 384 + 255) / 256, 256>>>(Pq, Pk, Pv, w_p);

    // 1) t = x @ W   (z over qkv)
    gemm_mma<128, false><<<dim3(3, 64, 3), 256>>>(
        x, w_p, t_p, nullptr, nullptr,
        768, 384, 384, 0, 768, 1.0f, 0, 3,
        0LL, 0LL, 0LL, W_SZ, 0LL, T_QKV, 0LL, 0LL);

    // 2) Q/K/V = t @ Vqkv + b   z=(b,h), K=32
    const float* Vs[3] = {Vq, Vk, Vv};
    const float* bs[3] = {bq, bk, bv};
    for (int q = 0; q < 3; q++)
        gemm_mma<64, false><<<dim3(1, 8, 96), 256>>>(
            t_p + q * T_QKV, Vs[q], qkv_p + q * Q_QKV, bs[q], nullptr,
            384, 64, 64, 0, 32, 1.0f, 0, 12,
            393216LL, 32LL, 0LL, 2048LL, 786432LL, 65536LL, 0LL, 64LL);

    // 3) fused attention -> at2 [B,M,768]
    flash_attn<<<dim3(8, 96), 256, FL_SMEM>>>(
        qkv_p, qkv_p + Q_QKV, qkv_p + 2 * Q_QKV, mask, at2_p);

    // 4) ao = attn @ Uo
    gemm_mma<128, false><<<dim3(3, 64, 1), 256>>>(
        at2_p, Uo, tmp_p, nullptr, nullptr,
        768, 384, 384, 0, 768, 1.0f, 0, 1, 0, 0, 0, 0, 0, 0, 0, 0);

    // 5) x1pre = ao @ Vo + bo + x
    gemm_mma<128, false><<<dim3(6, 64, 1), 256>>>(
        tmp_p, Vo, y_p, bo, x,
        384, 768, 768, 768, 384, 1.0f, 0, 1, 0, 0, 0, 0, 0, 0, 0, 0);

    // 6) LN1
    ln_kernel<<<8192, 256>>>(y_p, x1_p, ln1g, ln1b);

    // 7) mid = x1 @ U1
    gemm_mma<128, false><<<dim3(3, 64, 1), 256>>>(
        x1_p, U1, tmp_p, nullptr, nullptr,
        768, 384, 384, 0, 768, 1.0f, 0, 1, 0, 0, 0, 0, 0, 0, 0, 0);

    // 8) hdn = gelu(mid @ V1 + b1)
    gemm_mma<128, false><<<dim3(24, 64, 1), 256>>>(
        tmp_p, V1, hdn_p, b1, nullptr,
        384, 3072, 3072, 0, 384, 1.0f, 1, 1, 0, 0, 0, 0, 0, 0, 0, 0);

    // 9) h2 = hdn @ U2
    gemm_mma<128, false><<<dim3(3, 64, 1), 256>>>(
        hdn_p, U2, tmp_p, nullptr, nullptr,
        3072, 384, 384, 0, 3072, 1.0f, 0, 1, 0, 0, 0, 0, 0, 0, 0, 0);

    // 10) ypre = h2 @ V2 + b2 + x1
    gemm_mma<128, false><<<dim3(6, 64, 1), 256>>>(
        tmp_p, V2, y_p, b2, x1_p,
        384, 768, 768, 768, 384, 1.0f, 0, 1, 0, 0, 0, 0, 0, 0, 0, 0);

    // 11) LN2 -> out
    ln_kernel<<<8192, 256>>>(y_p, out, ln2g, ln2b);
}

// round 6
// speedup vs baseline: 3.6381x; 1.0040x over previous
#include <cuda_runtime.h>
#include <math.h>
#include <stdint.h>

// B=8, M=1024, DM=768, H=12, DH=64, R=32, RFF=384, DFF=3072, RWO=384

// ---------------- scratch (device globals) ----------------
__device__ float g_w   [3ull * 768 * 384];
__device__ float g_vw  [3ull * 12 * 32 * 64];
__device__ float g_vb  [3ull * 12 * 64];
__device__ float g_t   [3ull * 8 * 1024 * 384];
__device__ float g_qkv [3ull * 8 * 12 * 1024 * 64];
__device__ float g_at2 [8ull * 1024 * 768];
__device__ float g_tmp [8192ull * 384];
__device__ float g_x1  [8192ull * 768];
__device__ float g_y   [8192ull * 768];
__device__ float g_hdn [8192ull * 3072];

__device__ __forceinline__ uint32_t tf32r(float f) {
    uint32_t r;
    asm("cvt.rna.tf32.f32 %0, %1;" : "=r"(r) : "f"(f));
    return r;
}
__device__ __forceinline__ float gelu_exact(float v) {
    return 0.5f * v * (1.0f + erff(v * 0.70710678118654752440f));
}
__device__ __forceinline__ void mma8(float* c, const uint32_t* a, const uint32_t* b) {
    asm volatile(
        "mma.sync.aligned.m16n8k8.row.col.f32.tf32.tf32.f32 "
        "{%0,%1,%2,%3}, {%4,%5,%6,%7}, {%8,%9}, {%0,%1,%2,%3};"
        : "+f"(c[0]), "+f"(c[1]), "+f"(c[2]), "+f"(c[3])
        : "r"(a[0]), "r"(a[1]), "r"(a[2]), "r"(a[3]), "r"(b[0]), "r"(b[1]));
}
__device__ __forceinline__ uint32_t smem_u32(const void* p) {
    uint32_t a;
    asm("{ .reg .u64 t; cvta.to.shared.u64 t, %1; cvt.u32.u64 %0, t; }" : "=r"(a) : "l"(p));
    return a;
}
#define CPA16(dst, src) \
    asm volatile("cp.async.cg.shared.global [%0], [%1], 16;" ::"r"(dst), "l"(src) : "memory")
#define CPA_COMMIT() asm volatile("cp.async.commit_group;" ::: "memory")

// ================= fused flash attention (cp.async double-buffered) =================
// grid: (8 q-tiles, 96 b*h). block 256 (8 warps x 16 rows).
// Q/K/V already tf32-rounded in gmem. out: at2[b][m][h*64+d].
#define FL_PAD 76
__global__ void __launch_bounds__(256, 1)
flash_attn(const float* __restrict__ Qg, const float* __restrict__ Kg,
           const float* __restrict__ Vg, const float* __restrict__ maskg,
           float* __restrict__ Og) {
    extern __shared__ float sm[];
    // per buf: Ks[128][76], Vs[128][76]; then Ms[1024]
    float* Ms = sm + 2 * 2 * 128 * FL_PAD;

    const int bh = blockIdx.y;
    const int b = bh / 12, h = bh % 12;
    const float* Q = Qg + (size_t)bh * 65536;
    const float* K = Kg + (size_t)bh * 65536;
    const float* V = Vg + (size_t)bh * 65536;
    const float* mask = maskg + b * 1024;
    float* O = Og + (size_t)b * 1024 * 768 + h * 64;

    const int tid = threadIdx.x;
    const int wid = tid >> 5, lane = tid & 31;
    const int qr = lane >> 2, qc = lane & 3;
    const int m0row = blockIdx.x * 128 + wid * 16;

    const int kv = tid >> 4, dq = (tid & 15) << 2;   // this thread's slice base

    auto load_chunk = [&](int c, int buf) {
        float* Ks = sm + buf * (2 * 128 * FL_PAD);
        float* Vs = Ks + 128 * FL_PAD;
        const float* Kc = K + ((size_t)(c << 7)) * 64;
        const float* Vc = V + ((size_t)(c << 7)) * 64;
#pragma unroll
        for (int i = 0; i < 8; i++) {
            int r = kv + i * 16;
            CPA16(smem_u32(&Ks[r * FL_PAD + dq]), Kc + (size_t)r * 64 + dq);
            CPA16(smem_u32(&Vs[r * FL_PAD + dq]), Vc + (size_t)r * 64 + dq);
        }
    };

    // mask preload + first two chunks
    CPA16(smem_u32(&Ms[tid * 4]), mask + tid * 4);
    load_chunk(0, 0);
    CPA_COMMIT();
    load_chunk(1, 1);
    CPA_COMMIT();

    // ---- Q fragments (scaled by 1/8; data already tf32-grid, scale exact) ----
    uint32_t qf[8][4];
    {
        const float* Qr0 = Q + (size_t)(m0row + qr) * 64;
        const float* Qr1 = Q + (size_t)(m0row + qr + 8) * 64;
#pragma unroll
        for (int kd = 0; kd < 8; kd++) {
            qf[kd][0] = __float_as_uint(Qr0[kd * 8 + qc] * 0.125f);
            qf[kd][1] = __float_as_uint(Qr1[kd * 8 + qc] * 0.125f);
            qf[kd][2] = __float_as_uint(Qr0[kd * 8 + qc + 4] * 0.125f);
            qf[kd][3] = __float_as_uint(Qr1[kd * 8 + qc + 4] * 0.125f);
        }
    }

    float oacc[8][4];
#pragma unroll
    for (int i = 0; i < 8; i++)
#pragma unroll
        for (int j = 0; j < 4; j++) oacc[i][j] = 0.0f;
    float mrow0 = -INFINITY, mrow1 = -INFINITY, lrow0 = 0.0f, lrow1 = 0.0f;

    for (int c = 0; c < 8; c++) {
        const int buf = c & 1;
        float* Ks = sm + buf * (2 * 128 * FL_PAD);
        float* Vs = Ks + 128 * FL_PAD;
        const int kvb = c << 7;

        if (c < 7) asm volatile("cp.async.wait_group 1;" ::: "memory");
        else       asm volatile("cp.async.wait_group 0;" ::: "memory");
        __syncthreads();

        // ---- S = (Q/8) @ K^T ----
        float sacc[16][4];
#pragma unroll
        for (int nt = 0; nt < 16; nt++) {
            sacc[nt][0] = sacc[nt][1] = sacc[nt][2] = sacc[nt][3] = 0.0f;
            const int n = nt * 8 + qr;
#pragma unroll
            for (int kd = 0; kd < 8; kd++) {
                uint32_t bf[2];
                bf[0] = __float_as_uint(Ks[n * FL_PAD + kd * 8 + qc]);
                bf[1] = __float_as_uint(Ks[n * FL_PAD + kd * 8 + qc + 4]);
                mma8(sacc[nt], qf[kd], bf);
            }
        }

        // ---- online softmax ----
        float cm0 = -INFINITY, cm1 = -INFINITY;
#pragma unroll
        for (int nt = 0; nt < 16; nt++) {
            float mk0 = Ms[kvb + nt * 8 + 2 * qc], mk1 = Ms[kvb + nt * 8 + 2 * qc + 1];
            sacc[nt][0] += mk0; sacc[nt][1] += mk1;
            sacc[nt][2] += mk0; sacc[nt][3] += mk1;
            cm0 = fmaxf(cm0, fmaxf(sacc[nt][0], sacc[nt][1]));
            cm1 = fmaxf(cm1, fmaxf(sacc[nt][2], sacc[nt][3]));
        }
        cm0 = fmaxf(cm0, __shfl_xor_sync(0xffffffffu, cm0, 1));
        cm0 = fmaxf(cm0, __shfl_xor_sync(0xffffffffu, cm0, 2));
        cm1 = fmaxf(cm1, __shfl_xor_sync(0xffffffffu, cm1, 1));
        cm1 = fmaxf(cm1, __shfl_xor_sync(0xffffffffu, cm1, 2));
        const float mn0 = fmaxf(mrow0, cm0), mn1 = fmaxf(mrow1, cm1);
        const float al0 = __expf(mrow0 - mn0), al1 = __expf(mrow1 - mn1);
        mrow0 = mn0; mrow1 = mn1;
        float sum0 = 0.0f, sum1 = 0.0f;
#pragma unroll
        for (int nt = 0; nt < 16; nt++) {
            sacc[nt][0] = __expf(sacc[nt][0] - mn0);
            sacc[nt][1] = __expf(sacc[nt][1] - mn0);
            sacc[nt][2] = __expf(sacc[nt][2] - mn1);
            sacc[nt][3] = __expf(sacc[nt][3] - mn1);
            sum0 += sacc[nt][0] + sacc[nt][1];
            sum1 += sacc[nt][2] + sacc[nt][3];
        }
        sum0 += __shfl_xor_sync(0xffffffffu, sum0, 1);
        sum0 += __shfl_xor_sync(0xffffffffu, sum0, 2);
        sum1 += __shfl_xor_sync(0xffffffffu, sum1, 1);
        sum1 += __shfl_xor_sync(0xffffffffu, sum1, 2);
        lrow0 = lrow0 * al0 + sum0;
        lrow1 = lrow1 * al1 + sum1;
#pragma unroll
        for (int i = 0; i < 8; i++) {
            oacc[i][0] *= al0; oacc[i][1] *= al0;
            oacc[i][2] *= al1; oacc[i][3] *= al1;
        }

        // ---- O += P @ V ----
        const int src0 = (qr << 2) | (qc >> 1);
        const int src1 = src0 + 2;
        const bool odd = qc & 1;
#pragma unroll
        for (int kt = 0; kt < 16; kt++) {
            float p0 = sacc[kt][0], p1 = sacc[kt][1], p2 = sacc[kt][2], p3 = sacc[kt][3];
            float t00 = __shfl_sync(0xffffffffu, p0, src0);
            float t01 = __shfl_sync(0xffffffffu, p1, src0);
            float t10 = __shfl_sync(0xffffffffu, p0, src1);
            float t11 = __shfl_sync(0xffffffffu, p1, src1);
            float u00 = __shfl_sync(0xffffffffu, p2, src0);
            float u01 = __shfl_sync(0xffffffffu, p3, src0);
            float u10 = __shfl_sync(0xffffffffu, p2, src1);
            float u11 = __shfl_sync(0xffffffffu, p3, src1);
            uint32_t af[4];
            af[0] = tf32r(odd ? t01 : t00);
            af[1] = tf32r(odd ? u01 : u00);
            af[2] = tf32r(odd ? t11 : t10);
            af[3] = tf32r(odd ? u11 : u10);
#pragma unroll
            for (int nt2 = 0; nt2 < 8; nt2++) {
                const int n = nt2 * 8 + qr;
                uint32_t bf[2];
                bf[0] = __float_as_uint(Vs[(kt * 8 + qc) * FL_PAD + n]);
                bf[1] = __float_as_uint(Vs[(kt * 8 + qc + 4) * FL_PAD + n]);
                mma8(oacc[nt2], af, bf);
            }
        }
        __syncthreads();
        if (c + 2 < 8) { load_chunk(c + 2, buf); CPA_COMMIT(); }
    }

    // ---- write out ----
    const float il0 = 1.0f / lrow0, il1 = 1.0f / lrow1;
    const int r0 = m0row + qr, r1 = m0row + qr + 8;
#pragma unroll
    for (int nt2 = 0; nt2 < 8; nt2++) {
        const int col = nt2 * 8 + 2 * qc;
        *(float2*)(O + (size_t)r0 * 768 + col) =
            make_float2(oacc[nt2][0] * il0, oacc[nt2][1] * il0);
        *(float2*)(O + (size_t)r1 * 768 + col) =
            make_float2(oacc[nt2][2] * il1, oacc[nt2][3] * il1);
    }
}

// ---------------- tf32 mma.sync GEMM, 3-level batch ----------------
// mode: 0=none, 1=gelu, 2=tf32-round output. z = (i1*D2 + i2)*D3 + i3.
template <int BN, bool BT>
__global__ void __launch_bounds__(256, 2)
gemm_mma(const float* __restrict__ A, const float* __restrict__ Bm, float* __restrict__ C,
         const float* __restrict__ bias, const float* __restrict__ res,
         int lda, int ldb, int ldc, int ldres, int K, float scale, int mode,
         int D2, int D3,
         long long sA1, long long sA2, long long sA3,
         long long sB1, long long sB2, long long sB3,
         long long sC1, long long sC2, long long sC3,
         long long sb1, long long sb2, long long sb3) {
    constexpr int BM = 128;
    constexpr int NT = 256;
    constexpr int WN = BN / 4;
    constexpr int NTILES = WN / 8;
    constexpr int LA = (BM * 16) / (4 * NT);
    constexpr int LB = (BN * 16) / (4 * NT);
    constexpr int NQ = BN / 4;

    __shared__ float As[2][16][BM + 8];
    __shared__ float Bs[2][16][BN + 8];

    const int z = blockIdx.z;
    const int i1 = z / (D2 * D3);
    const int rem = z % (D2 * D3);
    const int i2 = rem / D3, i3 = rem % D3;
    A += i1 * sA1 + i2 * sA2 + i3 * sA3;
    Bm += i1 * sB1 + i2 * sB2 + i3 * sB3;
    C += i1 * sC1 + i2 * sC2 + i3 * sC3;
    const long long boff = i1 * sb1 + i2 * sb2 + i3 * sb3;

    const int x0 = blockIdx.x * BN, y0 = blockIdx.y * BM;
    const int tid = threadIdx.x;
    const int wid = tid >> 5, lane = tid & 31;
    const int wm0 = (wid >> 2) * 64;
    const int wn0 = (wid & 3) * WN;
    const int qr = lane >> 2, qc = lane & 3;

    float4 ra[LA], rb[LB];

    auto ldg = [&](int k0) {
#pragma unroll
        for (int i = 0; i < LA; i++) {
            int f = tid + i * NT;
            int m = f >> 2, kq = f & 3;
            ra[i] = *(const float4*)(A + (size_t)(y0 + m) * lda + k0 + kq * 4);
        }
#pragma unroll
        for (int i = 0; i < LB; i++) {
            int f = tid + i * NT;
            if (BT) {
                int n = f >> 2, kq = f & 3;
                rb[i] = *(const float4*)(Bm + (size_t)(x0 + n) * ldb + k0 + kq * 4);
            } else {
                int k = f / NQ, nq = f % NQ;
                rb[i] = *(const float4*)(Bm + (size_t)(k0 + k) * ldb + x0 + nq * 4);
            }
        }
    };
    auto sts = [&](int buf) {
#pragma unroll
        for (int i = 0; i < LA; i++) {
            int f = tid + i * NT;
            int m = f >> 2, kq = f & 3;
            As[buf][kq * 4 + 0][m] = __uint_as_float(tf32r(ra[i].x));
            As[buf][kq * 4 + 1][m] = __uint_as_float(tf32r(ra[i].y));
            As[buf][kq * 4 + 2][m] = __uint_as_float(tf32r(ra[i].z));
            As[buf][kq * 4 + 3][m] = __uint_as_float(tf32r(ra[i].w));
        }
#pragma unroll
        for (int i = 0; i < LB; i++) {
            int f = tid + i * NT;
            if (BT) {
                int n = f >> 2, kq = f & 3;
                Bs[buf][kq * 4 + 0][n] = __uint_as_float(tf32r(rb[i].x));
                Bs[buf][kq * 4 + 1][n] = __uint_as_float(tf32r(rb[i].y));
                Bs[buf][kq * 4 + 2][n] = __uint_as_float(tf32r(rb[i].z));
                Bs[buf][kq * 4 + 3][n] = __uint_as_float(tf32r(rb[i].w));
            } else {
                int k = f / NQ, nq = f % NQ;
                float4 t;
                t.x = __uint_as_float(tf32r(rb[i].x));
                t.y = __uint_as_float(tf32r(rb[i].y));
                t.z = __uint_as_float(tf32r(rb[i].z));
                t.w = __uint_as_float(tf32r(rb[i].w));
                *(float4*)&Bs[buf][k][nq * 4] = t;
            }
        }
    };

    float acc[4][NTILES][4];
#pragma unroll
    for (int i = 0; i < 4; i++)
#pragma unroll
        for (int j = 0; j < NTILES; j++)
#pragma unroll
            for (int l = 0; l < 4; l++) acc[i][j][l] = 0.0f;

    ldg(0);
    sts(0);
    __syncthreads();
    const int nb = K >> 4;
    for (int kb = 0; kb < nb; kb++) {
        const int cur = kb & 1;
        if (kb + 1 < nb) ldg((kb + 1) << 4);
#pragma unroll
        for (int kk = 0; kk < 16; kk += 8) {
            uint32_t af[4][4], bf[NTILES][2];
#pragma unroll
            for (int mt = 0; mt < 4; mt++) {
                int m = wm0 + mt * 16 + qr;
                af[mt][0] = __float_as_uint(As[cur][kk + qc][m]);
                af[mt][1] = __float_as_uint(As[cur][kk + qc][m + 8]);
                af[mt][2] = __float_as_uint(As[cur][kk + qc + 4][m]);
                af[mt][3] = __float_as_uint(As[cur][kk + qc + 4][m + 8]);
            }
#pragma unroll
            for (int nt = 0; nt < NTILES; nt++) {
                int n = wn0 + nt * 8 + qr;
                bf[nt][0] = __float_as_uint(Bs[cur][kk + qc][n]);
                bf[nt][1] = __float_as_uint(Bs[cur][kk + qc + 4][n]);
            }
#pragma unroll
            for (int mt = 0; mt < 4; mt++)
#pragma unroll
                for (int nt = 0; nt < NTILES; nt++) mma8(acc[mt][nt], af[mt], bf[nt]);
        }
        if (kb + 1 < nb) sts(cur ^ 1);
        __syncthreads();
    }

#pragma unroll
    for (int mt = 0; mt < 4; mt++) {
#pragma unroll
        for (int nt = 0; nt < NTILES; nt++) {
            const int n = x0 + wn0 + nt * 8 + qc * 2;
#pragma unroll
            for (int half = 0; half < 2; half++) {
                const int m = y0 + wm0 + mt * 16 + qr + half * 8;
                float v0 = acc[mt][nt][half * 2 + 0] * scale;
                float v1 = acc[mt][nt][half * 2 + 1] * scale;
                if (bias) { v0 += bias[boff + n]; v1 += bias[boff + n + 1]; }
                if (res) {
                    v0 += res[(size_t)m * ldres + n];
                    v1 += res[(size_t)m * ldres + n + 1];
                }
                if (mode == 1) { v0 = gelu_exact(v0); v1 = gelu_exact(v1); }
                else if (mode == 2) {
                    v0 = __uint_as_float(tf32r(v0));
                    v1 = __uint_as_float(tf32r(v1));
                }
                *(float2*)(C + (size_t)m * ldc + n) = make_float2(v0, v1);
            }
        }
    }
}

// ---------------- packing: P->W, V-factors, biases ----------------
__global__ void pack_all(const float* __restrict__ Pq, const float* __restrict__ Pk,
                         const float* __restrict__ Pv,
                         const float* __restrict__ Vq, const float* __restrict__ Vk,
                         const float* __restrict__ Vv,
                         const float* __restrict__ bq, const float* __restrict__ bk,
                         const float* __restrict__ bv,
                         float* __restrict__ W, float* __restrict__ VW,
                         float* __restrict__ VB) {
    int idx = blockIdx.x * blockDim.x + threadIdx.x;
    const int NW = 3 * 768 * 384;      // 884736
    const int NV = 3 * 24576;          // 73728
    if (idx < NW) {
        int q = idx / (768 * 384);
        int r2 = idx % (768 * 384);
        int k = r2 / 384, n = r2 % 384;
        const float* P = (q == 0) ? Pq : ((q == 1) ? Pk : Pv);
        W[idx] = P[((size_t)(n >> 5) * 768 + k) * 32 + (n & 31)];
    } else if (idx < NW + NV) {
        int e = idx - NW;
        int q = e / 24576, r = e % 24576;
        const float* S = (q == 0) ? Vq : ((q == 1) ? Vk : Vv);
        VW[e] = S[r];
    } else if (idx < NW + NV + 3 * 768) {
        int e = idx - NW - NV;
        int q = e / 768, r = e % 768;
        const float* S = (q == 0) ? bq : ((q == 1) ? bk : bv);
        VB[e] = S[r];
    }
}

// ---------------- LayerNorm over 768 cols ----------------
__global__ void ln_kernel(const float* __restrict__ in, float* __restrict__ out,
                          const float* __restrict__ g, const float* __restrict__ bb) {
    __shared__ float red[256];
    const float* xr = in + (size_t)blockIdx.x * 768;
    float* yr = out + (size_t)blockIdx.x * 768;
    const int tid = threadIdx.x;
    float v[3];
    float s = 0.0f;
#pragma unroll
    for (int i = 0; i < 3; i++) { v[i] = xr[tid + i * 256]; s += v[i]; }
    red[tid] = s; __syncthreads();
    for (int t = 128; t > 0; t >>= 1) {
        if (tid < t) red[tid] += red[tid + t];
        __syncthreads();
    }
    const float mu = red[0] * (1.0f / 768.0f);
    __syncthreads();
    float ss = 0.0f;
#pragma unroll
    for (int i = 0; i < 3; i++) { float d = v[i] - mu; ss += d * d; }
    red[tid] = ss; __syncthreads();
    for (int t = 128; t > 0; t >>= 1) {
        if (tid < t) red[tid] += red[tid + t];
        __syncthreads();
    }
    const float rs = rsqrtf(red[0] * (1.0f / 768.0f) + 1e-12f);
    __syncthreads();
#pragma unroll
    for (int i = 0; i < 3; i++) {
        int c = tid + i * 256;
        yr[c] = (v[i] - mu) * rs * g[c] + bb[c];
    }
}

extern "C" void kernel_launch(void* const* d_in, const int* in_sizes, int n_in,
                              void* d_out, int out_size) {
    const float* x    = (const float*)d_in[0];
    const float* mask = (const float*)d_in[1];
    const float* Pq   = (const float*)d_in[2];
    const float* Vq   = (const float*)d_in[3];
    const float* bq   = (const float*)d_in[4];
    const float* Pk   = (const float*)d_in[5];
    const float* Vk   = (const float*)d_in[6];
    const float* bk   = (const float*)d_in[7];
    const float* Pv   = (const float*)d_in[8];
    const float* Vv   = (const float*)d_in[9];
    const float* bv   = (const float*)d_in[10];
    const float* Uo   = (const float*)d_in[11];
    const float* Vo   = (const float*)d_in[12];
    const float* bo   = (const float*)d_in[13];
    const float* U1   = (const float*)d_in[14];
    const float* V1   = (const float*)d_in[15];
    const float* b1   = (const float*)d_in[16];
    const float* U2   = (const float*)d_in[17];
    const float* V2   = (const float*)d_in[18];
    const float* b2   = (const float*)d_in[19];
    const float* ln1g = (const float*)d_in[20];
    const float* ln1b = (const float*)d_in[21];
    const float* ln2g = (const float*)d_in[22];
    const float* ln2b = (const float*)d_in[23];
    float* out = (float*)d_out;

    float *w_p, *vw_p, *vb_p, *t_p, *qkv_p, *at2_p, *tmp_p, *x1_p, *y_p, *hdn_p;
    cudaGetSymbolAddress((void**)&w_p,   g_w);
    cudaGetSymbolAddress((void**)&vw_p,  g_vw);
    cudaGetSymbolAddress((void**)&vb_p,  g_vb);
    cudaGetSymbolAddress((void**)&t_p,   g_t);
    cudaGetSymbolAddress((void**)&qkv_p, g_qkv);
    cudaGetSymbolAddress((void**)&at2_p, g_at2);
    cudaGetSymbolAddress((void**)&tmp_p, g_tmp);
    cudaGetSymbolAddress((void**)&x1_p,  g_x1);
    cudaGetSymbolAddress((void**)&y_p,   g_y);
    cudaGetSymbolAddress((void**)&hdn_p, g_hdn);

    const long long T_QKV = 3145728, Q_QKV = 6291456, W_SZ = 294912;
    const int FL_SMEM = (2 * 2 * 128 * FL_PAD + 1024) * 4;   // ~160 KB
    cudaFuncSetAttribute(flash_attn, cudaFuncAttributeMaxDynamicSharedMemorySize, FL_SMEM);

    // 0) pack weights
    const int NPACK = 3 * 768 * 384 + 3 * 24576 + 3 * 768;
    pack_all<<<(NPACK + 255) / 256, 256>>>(Pq, Pk, Pv, Vq, Vk, Vv, bq, bk, bv,
                                           w_p, vw_p, vb_p);

    // 1) t = x @ W   (z over qkv)
    gemm_mma<128, false><<<dim3(3, 64, 3), 256>>>(
        x, w_p, t_p, nullptr, nullptr,
        768, 384, 384, 0, 768, 1.0f, 0, 1, 1,
        0LL, 0LL, 0LL, W_SZ, 0LL, 0LL, T_QKV, 0LL, 0LL, 0LL, 0LL, 0LL);

    // 2) Q/K/V = t @ Vqkv + b, tf32-rounded output. z=(q,b,h), K=32
    gemm_mma<64, false><<<dim3(1, 8, 288), 256>>>(
        t_p, vw_p, qkv_p, vb_p, nullptr,
        384, 64, 64, 0, 32, 1.0f, 2, 8, 12,
        T_QKV, 393216LL, 32LL,
        24576LL, 0LL, 2048LL,
        Q_QKV, 786432LL, 65536LL,
        768LL, 0LL, 64LL);

    // 3) fused attention -> at2 [B,M,768]
    flash_attn<<<dim3(8, 96), 256, FL_SMEM>>>(
        qkv_p, qkv_p + Q_QKV, qkv_p + 2 * Q_QKV, mask, at2_p);

    // 4) ao = attn @ Uo
    gemm_mma<128, false><<<dim3(3, 64, 1), 256>>>(
        at2_p, Uo, tmp_p, nullptr, nullptr,
        768, 384, 384, 0, 768, 1.0f, 0, 1, 1,
        0, 0, 0, 0, 0, 0, 0, 0, 0, 0, 0, 0);

    // 5) x1pre = ao @ Vo + bo + x
    gemm_mma<128, false><<<dim3(6, 64, 1), 256>>>(
        tmp_p, Vo, y_p, bo, x,
        384, 768, 768, 768, 384, 1.0f, 0, 1, 1,
        0, 0, 0, 0, 0, 0, 0, 0, 0, 0, 0, 0);

    // 6) LN1
    ln_kernel<<<8192, 256>>>(y_p, x1_p, ln1g, ln1b);

    // 7) mid = x1 @ U1
    gemm_mma<128, false><<<dim3(3, 64, 1), 256>>>(
        x1_p, U1, tmp_p, nullptr, nullptr,
        768, 384, 384, 0, 768, 1.0f, 0, 1, 1,
        0, 0, 0, 0, 0, 0, 0, 0, 0, 0, 0, 0);

    // 8) hdn = gelu(mid @ V1 + b1)
    gemm_mma<128, false><<<dim3(24, 64, 1), 256>>>(
        tmp_p, V1, hdn_p, b1, nullptr,
        384, 3072, 3072, 0, 384, 1.0f, 1, 1, 1,
        0, 0, 0, 0, 0, 0, 0, 0, 0, 0, 0, 0);

    // 9) h2 = hdn @ U2
    gemm_mma<128, false><<<dim3(3, 64, 1), 256>>>(
        hdn_p, U2, tmp_p, nullptr, nullptr,
        3072, 384, 384, 0, 3072, 1.0f, 0, 1, 1,
        0, 0, 0, 0, 0, 0, 0, 0, 0, 0, 0, 0);

    // 10) ypre = h2 @ V2 + b2 + x1
    gemm_mma<128, false><<<dim3(6, 64, 1), 256>>>(
        tmp_p, V2, y_p, b2, x1_p,
        384, 768, 768, 768, 384, 1.0f, 0, 1, 1,
        0, 0, 0, 0, 0, 0, 0, 0, 0, 0, 0, 0);

    // 11) LN2 -> out
    ln_kernel<<<8192, 256>>>(y_p, out, ln2g, ln2b);
}

// round 7
// speedup vs baseline: 5.7431x; 1.5786x over previous
#include <cuda_runtime.h>
#include <cuda_fp16.h>
#include <math.h>
#include <stdint.h>

// B=8, M=1024, DM=768, H=12, DH=64, R=32, RFF=384, DFF=3072, RWO=384

// ---------------- scratch (device globals) ----------------
__device__ float  g_w   [3ull * 768 * 384];
__device__ float  g_vw  [3ull * 12 * 32 * 64];
__device__ float  g_vb  [3ull * 12 * 64];
__device__ float  g_t   [3ull * 8 * 1024 * 384];
__device__ __half g_qkvh[3ull * 8 * 12 * 1024 * 64];
__device__ float  g_at2 [8ull * 1024 * 768];
__device__ float  g_tmp [8192ull * 384];
__device__ float  g_x1  [8192ull * 768];
__device__ float  g_y   [8192ull * 768];
__device__ float  g_hdn [8192ull * 3072];

__device__ __forceinline__ float gelu_exact(float v) {
    return 0.5f * v * (1.0f + erff(v * 0.70710678118654752440f));
}
__device__ __forceinline__ uint32_t h2u(float lo, float hi) {
    __half2 h = __halves2half2(__float2half_rn(lo), __float2half_rn(hi));
    return *(uint32_t*)&h;
}
__device__ __forceinline__ void mma16(float* c, const uint32_t* a, const uint32_t* b) {
    asm volatile(
        "mma.sync.aligned.m16n8k16.row.col.f32.f16.f16.f32 "
        "{%0,%1,%2,%3}, {%4,%5,%6,%7}, {%8,%9}, {%0,%1,%2,%3};"
        : "+f"(c[0]), "+f"(c[1]), "+f"(c[2]), "+f"(c[3])
        : "r"(a[0]), "r"(a[1]), "r"(a[2]), "r"(a[3]), "r"(b[0]), "r"(b[1]));
}
__device__ __forceinline__ uint32_t smem_u32(const void* p) {
    uint32_t a;
    asm("{ .reg .u64 t; cvta.to.shared.u64 t, %1; cvt.u32.u64 %0, t; }" : "=r"(a) : "l"(p));
    return a;
}
#define CPA16(dst, src) \
    asm volatile("cp.async.cg.shared.global [%0], [%1], 16;" ::"r"(dst), "l"(src) : "memory")
#define CPA_COMMIT() asm volatile("cp.async.commit_group;" ::: "memory")

// ================= fused flash attention (fp16 mma, no shuffles) =================
// grid (8 q-tiles, 96 bh), 256 threads (8 warps x 16 rows).
// smem: Ks[2][128][36]u32 (K pairs along d, natural) | Vs[2][64][72]u32 (pairs along kv) | Ms[1024]f
__global__ void __launch_bounds__(256, 1)
flash_attn(const __half* __restrict__ Qg, const __half* __restrict__ Kg,
           const __half* __restrict__ Vg, const float* __restrict__ maskg,
           float* __restrict__ Og) {
    extern __shared__ uint32_t smu[];
    float* Ms = (float*)(smu + 18432);

    const int bh = blockIdx.y;
    const int b = bh / 12, h = bh % 12;
    const __half* Q = Qg + (size_t)bh * 65536;
    const __half* K = Kg + (size_t)bh * 65536;
    const __half* V = Vg + (size_t)bh * 65536;
    const float* mask = maskg + b * 1024;
    float* O = Og + (size_t)b * 1024 * 768 + h * 64;

    const int tid = threadIdx.x;
    const int wid = tid >> 5, lane = tid & 31;
    const int qr = lane >> 2, qc = lane & 3;
    const int m0row = blockIdx.x * 128 + wid * 16;

    auto k_load = [&](int c, int buf) {
        uint32_t* Ks = smu + buf * 4608;
        const __half* Kc = K + ((size_t)(c << 7)) * 64;
#pragma unroll
        for (int i = 0; i < 4; i++) {
            int f = tid + (i << 8);
            int kv = f >> 3, c4 = f & 7;
            CPA16(smem_u32(Ks + kv * 36 + c4 * 4), Kc + kv * 64 + c4 * 8);
        }
    };
    CPA16(smem_u32(Ms + tid * 4), mask + tid * 4);
    k_load(0, 0);
    CPA_COMMIT();
    k_load(1, 1);
    CPA_COMMIT();

    // ---- Q fragments, scaled by 1/8 (exact) ----
    uint32_t qf[4][4];
    {
        const __half2 s2 = __float2half2_rn(0.125f);
        const __half* Qr0 = Q + (size_t)(m0row + qr) * 64;
        const __half* Qr1 = Q + (size_t)(m0row + qr + 8) * 64;
#pragma unroll
        for (int kd = 0; kd < 4; kd++) {
            __half2 a0 = __hmul2(*(const __half2*)(Qr0 + kd * 16 + 2 * qc), s2);
            __half2 a1 = __hmul2(*(const __half2*)(Qr1 + kd * 16 + 2 * qc), s2);
            __half2 a2 = __hmul2(*(const __half2*)(Qr0 + kd * 16 + 2 * qc + 8), s2);
            __half2 a3 = __hmul2(*(const __half2*)(Qr1 + kd * 16 + 2 * qc + 8), s2);
            qf[kd][0] = *(uint32_t*)&a0;
            qf[kd][1] = *(uint32_t*)&a1;
            qf[kd][2] = *(uint32_t*)&a2;
            qf[kd][3] = *(uint32_t*)&a3;
        }
    }

    float oacc[8][4];
#pragma unroll
    for (int i = 0; i < 8; i++)
#pragma unroll
        for (int j = 0; j < 4; j++) oacc[i][j] = 0.0f;
    float mrow0 = -INFINITY, mrow1 = -INFINITY, lrow0 = 0.0f, lrow1 = 0.0f;

    for (int c = 0; c < 8; c++) {
        const int buf = c & 1;
        uint32_t* Ks = smu + buf * 4608;
        uint32_t* Vs = smu + 9216 + buf * 4608;
        const int kvb = c << 7;

        if (c < 7) asm volatile("cp.async.wait_group 1;" ::: "memory");
        else       asm volatile("cp.async.wait_group 0;" ::: "memory");
        __syncthreads();

        // V gmem loads early (hidden under S compute)
        const __half* Vc = V + ((size_t)kvb) * 64;
        const int kv2 = tid >> 2, dbase = (tid & 3) << 4;
        uint4 ve0 = *(const uint4*)(Vc + (size_t)(2 * kv2) * 64 + dbase);
        uint4 ve1 = *(const uint4*)(Vc + (size_t)(2 * kv2) * 64 + dbase + 8);
        uint4 vo0 = *(const uint4*)(Vc + (size_t)(2 * kv2 + 1) * 64 + dbase);
        uint4 vo1 = *(const uint4*)(Vc + (size_t)(2 * kv2 + 1) * 64 + dbase + 8);

        // ---- S = (Q/8) @ K^T ----
        float sacc[16][4];
#pragma unroll
        for (int nt = 0; nt < 16; nt++) {
            sacc[nt][0] = sacc[nt][1] = sacc[nt][2] = sacc[nt][3] = 0.0f;
            const int n = nt * 8 + qr;
#pragma unroll
            for (int kd = 0; kd < 4; kd++) {
                uint32_t bf[2] = {Ks[n * 36 + kd * 8 + qc], Ks[n * 36 + kd * 8 + qc + 4]};
                mma16(sacc[nt], qf[kd], bf);
            }
        }

        // ---- online softmax ----
        float cm0 = -INFINITY, cm1 = -INFINITY;
#pragma unroll
        for (int nt = 0; nt < 16; nt++) {
            float mk0 = Ms[kvb + nt * 8 + 2 * qc], mk1 = Ms[kvb + nt * 8 + 2 * qc + 1];
            sacc[nt][0] += mk0; sacc[nt][1] += mk1;
            sacc[nt][2] += mk0; sacc[nt][3] += mk1;
            cm0 = fmaxf(cm0, fmaxf(sacc[nt][0], sacc[nt][1]));
            cm1 = fmaxf(cm1, fmaxf(sacc[nt][2], sacc[nt][3]));
        }
        cm0 = fmaxf(cm0, __shfl_xor_sync(0xffffffffu, cm0, 1));
        cm0 = fmaxf(cm0, __shfl_xor_sync(0xffffffffu, cm0, 2));
        cm1 = fmaxf(cm1, __shfl_xor_sync(0xffffffffu, cm1, 1));
        cm1 = fmaxf(cm1, __shfl_xor_sync(0xffffffffu, cm1, 2));
        const float mn0 = fmaxf(mrow0, cm0), mn1 = fmaxf(mrow1, cm1);
        const float al0 = __expf(mrow0 - mn0), al1 = __expf(mrow1 - mn1);
        mrow0 = mn0; mrow1 = mn1;
        float sum0 = 0.0f, sum1 = 0.0f;
#pragma unroll
        for (int nt = 0; nt < 16; nt++) {
            sacc[nt][0] = __expf(sacc[nt][0] - mn0);
            sacc[nt][1] = __expf(sacc[nt][1] - mn0);
            sacc[nt][2] = __expf(sacc[nt][2] - mn1);
            sacc[nt][3] = __expf(sacc[nt][3] - mn1);
            sum0 += sacc[nt][0] + sacc[nt][1];
            sum1 += sacc[nt][2] + sacc[nt][3];
        }
        sum0 += __shfl_xor_sync(0xffffffffu, sum0, 1);
        sum0 += __shfl_xor_sync(0xffffffffu, sum0, 2);
        sum1 += __shfl_xor_sync(0xffffffffu, sum1, 1);
        sum1 += __shfl_xor_sync(0xffffffffu, sum1, 2);
        lrow0 = lrow0 * al0 + sum0;
        lrow1 = lrow1 * al1 + sum1;
#pragma unroll
        for (int i = 0; i < 8; i++) {
            oacc[i][0] *= al0; oacc[i][1] *= al0;
            oacc[i][2] *= al1; oacc[i][3] *= al1;
        }

        // ---- V pair-transpose into smem ----
        {
            union { uint4 u4[2]; unsigned short us[16]; } e, o;
            e.u4[0] = ve0; e.u4[1] = ve1;
            o.u4[0] = vo0; o.u4[1] = vo1;
#pragma unroll
            for (int j = 0; j < 16; j++)
                Vs[kv2 * 72 + dbase + j] = (uint32_t)e.us[j] | ((uint32_t)o.us[j] << 16);
        }
        __syncthreads();
        if (c + 2 < 8) { k_load(c + 2, buf); CPA_COMMIT(); }

        // ---- O += P @ V (accumulator feeds A-fragment directly) ----
#pragma unroll
        for (int kt = 0; kt < 8; kt++) {
            uint32_t af[4];
            af[0] = h2u(sacc[2 * kt][0], sacc[2 * kt][1]);
            af[1] = h2u(sacc[2 * kt][2], sacc[2 * kt][3]);
            af[2] = h2u(sacc[2 * kt + 1][0], sacc[2 * kt + 1][1]);
            af[3] = h2u(sacc[2 * kt + 1][2], sacc[2 * kt + 1][3]);
#pragma unroll
            for (int nt2 = 0; nt2 < 8; nt2++) {
                const int n = nt2 * 8 + qr;
                uint32_t bf[2] = {Vs[(kt * 8 + qc) * 72 + n], Vs[(kt * 8 + qc + 4) * 72 + n]};
                mma16(oacc[nt2], af, bf);
            }
        }
    }

    // ---- write out ----
    const float il0 = 1.0f / lrow0, il1 = 1.0f / lrow1;
    const int r0 = m0row + qr, r1 = m0row + qr + 8;
#pragma unroll
    for (int nt2 = 0; nt2 < 8; nt2++) {
        const int col = nt2 * 8 + 2 * qc;
        *(float2*)(O + (size_t)r0 * 768 + col) =
            make_float2(oacc[nt2][0] * il0, oacc[nt2][1] * il0);
        *(float2*)(O + (size_t)r1 * 768 + col) =
            make_float2(oacc[nt2][2] * il1, oacc[nt2][3] * il1);
    }
}

// ---------------- fp16 mma GEMM (fp32 in gmem, fp16 in smem), 3-level batch ----------------
// mode: 0=none, 1=gelu, 3=half output. z = (i1*D2 + i2)*D3 + i3.
template <int BN>
__global__ void __launch_bounds__(256, 2)
gemm_mma(const float* __restrict__ A, const float* __restrict__ Bm, void* __restrict__ Cv,
         const float* __restrict__ bias, const float* __restrict__ res,
         int lda, int ldb, int ldc, int ldres, int K, float scale, int mode,
         int D2, int D3,
         long long sA1, long long sA2, long long sA3,
         long long sB1, long long sB2, long long sB3,
         long long sC1, long long sC2, long long sC3,
         long long sb1, long long sb2, long long sb3) {
    constexpr int BM = 128, NT = 256, WN = BN / 4, NTILES = WN / 8;
    constexpr int SA = BM + 12, SB = BN + 12;
    constexpr int LBI = BN / 32;

    __shared__ uint32_t As32[2][16][SA];
    __shared__ uint32_t Bs32[2][16][SB];

    const int z = blockIdx.z;
    const int i1 = z / (D2 * D3);
    const int rem = z % (D2 * D3);
    const int i2 = rem / D3, i3 = rem % D3;
    A += i1 * sA1 + i2 * sA2 + i3 * sA3;
    Bm += i1 * sB1 + i2 * sB2 + i3 * sB3;
    const long long coff = i1 * sC1 + i2 * sC2 + i3 * sC3;
    const long long boff = i1 * sb1 + i2 * sb2 + i3 * sb3;

    const int x0 = blockIdx.x * BN, y0 = blockIdx.y * BM;
    const int tid = threadIdx.x;
    const int wid = tid >> 5, lane = tid & 31;
    const int wm0 = (wid >> 2) * 64;
    const int wn0 = (wid & 3) * WN;
    const int qr = lane >> 2, qc = lane & 3;

    float4 ra[4];
    float2 rb0[LBI], rb1[LBI];

    auto ldg = [&](int k0) {
#pragma unroll
        for (int i = 0; i < 4; i++) {
            int f = tid + i * NT;
            int m = f >> 3, kq = f & 7;
            ra[i] = *(const float4*)(A + (size_t)(y0 + m) * lda + k0 + kq * 4);
        }
#pragma unroll
        for (int i = 0; i < LBI; i++) {
            int f = tid + i * NT;
            int k2 = f / (BN / 2), n2 = f % (BN / 2);
            rb0[i] = *(const float2*)(Bm + (size_t)(k0 + 2 * k2) * ldb + x0 + 2 * n2);
            rb1[i] = *(const float2*)(Bm + (size_t)(k0 + 2 * k2 + 1) * ldb + x0 + 2 * n2);
        }
    };
    auto sts = [&](int buf) {
#pragma unroll
        for (int i = 0; i < 4; i++) {
            int f = tid + i * NT;
            int m = f >> 3, kq = f & 7;
            As32[buf][2 * kq][m] = h2u(ra[i].x, ra[i].y);
            As32[buf][2 * kq + 1][m] = h2u(ra[i].z, ra[i].w);
        }
#pragma unroll
        for (int i = 0; i < LBI; i++) {
            int f = tid + i * NT;
            int k2 = f / (BN / 2), n2 = f % (BN / 2);
            Bs32[buf][k2][2 * n2] = h2u(rb0[i].x, rb1[i].x);
            Bs32[buf][k2][2 * n2 + 1] = h2u(rb0[i].y, rb1[i].y);
        }
    };

    float acc[4][NTILES][4];
#pragma unroll
    for (int i = 0; i < 4; i++)
#pragma unroll
        for (int j = 0; j < NTILES; j++)
#pragma unroll
            for (int l = 0; l < 4; l++) acc[i][j][l] = 0.0f;

    ldg(0);
    sts(0);
    __syncthreads();
    const int nb = K >> 5;
    for (int kb = 0; kb < nb; kb++) {
        const int cur = kb & 1;
        if (kb + 1 < nb) ldg((kb + 1) << 5);
#pragma unroll
        for (int kk2 = 0; kk2 < 16; kk2 += 8) {
            uint32_t af[4][4], bf[NTILES][2];
#pragma unroll
            for (int mt = 0; mt < 4; mt++) {
                int m = wm0 + mt * 16 + qr;
                af[mt][0] = As32[cur][kk2 + qc][m];
                af[mt][1] = As32[cur][kk2 + qc][m + 8];
                af[mt][2] = As32[cur][kk2 + qc + 4][m];
                af[mt][3] = As32[cur][kk2 + qc + 4][m + 8];
            }
#pragma unroll
            for (int nt = 0; nt < NTILES; nt++) {
                int n = wn0 + nt * 8 + qr;
                bf[nt][0] = Bs32[cur][kk2 + qc][n];
                bf[nt][1] = Bs32[cur][kk2 + qc + 4][n];
            }
#pragma unroll
            for (int mt = 0; mt < 4; mt++)
#pragma unroll
                for (int nt = 0; nt < NTILES; nt++) mma16(acc[mt][nt], af[mt], bf[nt]);
        }
        if (kb + 1 < nb) sts(cur ^ 1);
        __syncthreads();
    }

    float* Cf = (float*)Cv + coff;
    __half* Ch = (__half*)Cv + coff;
#pragma unroll
    for (int mt = 0; mt < 4; mt++) {
#pragma unroll
        for (int nt = 0; nt < NTILES; nt++) {
            const int n = x0 + wn0 + nt * 8 + qc * 2;
#pragma unroll
            for (int half_ = 0; half_ < 2; half_++) {
                const int m = y0 + wm0 + mt * 16 + qr + half_ * 8;
                float v0 = acc[mt][nt][half_ * 2 + 0] * scale;
                float v1 = acc[mt][nt][half_ * 2 + 1] * scale;
                if (bias) { v0 += bias[boff + n]; v1 += bias[boff + n + 1]; }
                if (res) {
                    v0 += res[(size_t)m * ldres + n];
                    v1 += res[(size_t)m * ldres + n + 1];
                }
                if (mode == 1) { v0 = gelu_exact(v0); v1 = gelu_exact(v1); }
                if (mode == 3) {
                    __half2 hv = __halves2half2(__float2half_rn(v0), __float2half_rn(v1));
                    *(__half2*)(Ch + (size_t)m * ldc + n) = hv;
                } else {
                    *(float2*)(Cf + (size_t)m * ldc + n) = make_float2(v0, v1);
                }
            }
        }
    }
}

// ---------------- packing: P->W, V-factors, biases ----------------
__global__ void pack_all(const float* __restrict__ Pq, const float* __restrict__ Pk,
                         const float* __restrict__ Pv,
                         const float* __restrict__ Vq, const float* __restrict__ Vk,
                         const float* __restrict__ Vv,
                         const float* __restrict__ bq, const float* __restrict__ bk,
                         const float* __restrict__ bv,
                         float* __restrict__ W, float* __restrict__ VW,
                         float* __restrict__ VB) {
    int idx = blockIdx.x * blockDim.x + threadIdx.x;
    const int NW = 3 * 768 * 384;
    const int NV = 3 * 24576;
    if (idx < NW) {
        int q = idx / (768 * 384);
        int r2 = idx % (768 * 384);
        int k = r2 / 384, n = r2 % 384;
        const float* P = (q == 0) ? Pq : ((q == 1) ? Pk : Pv);
        W[idx] = P[((size_t)(n >> 5) * 768 + k) * 32 + (n & 31)];
    } else if (idx < NW + NV) {
        int e = idx - NW;
        int q = e / 24576, r = e % 24576;
        const float* S = (q == 0) ? Vq : ((q == 1) ? Vk : Vv);
        VW[e] = S[r];
    } else if (idx < NW + NV + 3 * 768) {
        int e = idx - NW - NV;
        int q = e / 768, r = e % 768;
        const float* S = (q == 0) ? bq : ((q == 1) ? bk : bv);
        VB[e] = S[r];
    }
}

// ---------------- LayerNorm over 768 cols ----------------
__global__ void ln_kernel(const float* __restrict__ in, float* __restrict__ out,
                          const float* __restrict__ g, const float* __restrict__ bb) {
    __shared__ float red[256];
    const float* xr = in + (size_t)blockIdx.x * 768;
    float* yr = out + (size_t)blockIdx.x * 768;
    const int tid = threadIdx.x;
    float v[3];
    float s = 0.0f;
#pragma unroll
    for (int i = 0; i < 3; i++) { v[i] = xr[tid + i * 256]; s += v[i]; }
    red[tid] = s; __syncthreads();
    for (int t = 128; t > 0; t >>= 1) {
        if (tid < t) red[tid] += red[tid + t];
        __syncthreads();
    }
    const float mu = red[0] * (1.0f / 768.0f);
    __syncthreads();
    float ss = 0.0f;
#pragma unroll
    for (int i = 0; i < 3; i++) { float d = v[i] - mu; ss += d * d; }
    red[tid] = ss; __syncthreads();
    for (int t = 128; t > 0; t >>= 1) {
        if (tid < t) red[tid] += red[tid + t];
        __syncthreads();
    }
    const float rs = rsqrtf(red[0] * (1.0f / 768.0f) + 1e-12f);
    __syncthreads();
#pragma unroll
    for (int i = 0; i < 3; i++) {
        int c = tid + i * 256;
        yr[c] = (v[i] - mu) * rs * g[c] + bb[c];
    }
}

extern "C" void kernel_launch(void* const* d_in, const int* in_sizes, int n_in,
                              void* d_out, int out_size) {
    const float* x    = (const float*)d_in[0];
    const float* mask = (const float*)d_in[1];
    const float* Pq   = (const float*)d_in[2];
    const float* Vq   = (const float*)d_in[3];
    const float* bq   = (const float*)d_in[4];
    const float* Pk   = (const float*)d_in[5];
    const float* Vk   = (const float*)d_in[6];
    const float* bk   = (const float*)d_in[7];
    const float* Pv   = (const float*)d_in[8];
    const float* Vv   = (const float*)d_in[9];
    const float* bv   = (const float*)d_in[10];
    const float* Uo   = (const float*)d_in[11];
    const float* Vo   = (const float*)d_in[12];
    const float* bo   = (const float*)d_in[13];
    const float* U1   = (const float*)d_in[14];
    const float* V1   = (const float*)d_in[15];
    const float* b1   = (const float*)d_in[16];
    const float* U2   = (const float*)d_in[17];
    const float* V2   = (const float*)d_in[18];
    const float* b2   = (const float*)d_in[19];
    const float* ln1g = (const float*)d_in[20];
    const float* ln1b = (const float*)d_in[21];
    const float* ln2g = (const float*)d_in[22];
    const float* ln2b = (const float*)d_in[23];
    float* out = (float*)d_out;

    float *w_p, *vw_p, *vb_p, *t_p, *at2_p, *tmp_p, *x1_p, *y_p, *hdn_p;
    __half* qkv_p;
    cudaGetSymbolAddress((void**)&w_p,   g_w);
    cudaGetSymbolAddress((void**)&vw_p,  g_vw);
    cudaGetSymbolAddress((void**)&vb_p,  g_vb);
    cudaGetSymbolAddress((void**)&t_p,   g_t);
    cudaGetSymbolAddress((void**)&qkv_p, g_qkvh);
    cudaGetSymbolAddress((void**)&at2_p, g_at2);
    cudaGetSymbolAddress((void**)&tmp_p, g_tmp);
    cudaGetSymbolAddress((void**)&x1_p,  g_x1);
    cudaGetSymbolAddress((void**)&y_p,   g_y);
    cudaGetSymbolAddress((void**)&hdn_p, g_hdn);

    const long long T_QKV = 3145728, Q_QKV = 6291456, W_SZ = 294912;
    const int FL_SMEM = (18432 + 1024) * 4;   // 77824 B
    cudaFuncSetAttribute(flash_attn, cudaFuncAttributeMaxDynamicSharedMemorySize, FL_SMEM);

    // 0) pack weights
    const int NPACK = 3 * 768 * 384 + 3 * 24576 + 3 * 768;
    pack_all<<<(NPACK + 255) / 256, 256>>>(Pq, Pk, Pv, Vq, Vk, Vv, bq, bk, bv,
                                           w_p, vw_p, vb_p);

    // 1) t = x @ W   (z over qkv)
    gemm_mma<128><<<dim3(3, 64, 3), 256>>>(
        x, w_p, t_p, nullptr, nullptr,
        768, 384, 384, 0, 768, 1.0f, 0, 1, 1,
        0LL, 0LL, 0LL, W_SZ, 0LL, 0LL, T_QKV, 0LL, 0LL, 0LL, 0LL, 0LL);

    // 2) Q/K/V = t @ Vqkv + b -> fp16. z=(q,b,h), K=32
    gemm_mma<64><<<dim3(1, 8, 288), 256>>>(
        t_p, vw_p, qkv_p, vb_p, nullptr,
        384, 64, 64, 0, 32, 1.0f, 3, 8, 12,
        T_QKV, 393216LL, 32LL,
        24576LL, 0LL, 2048LL,
        Q_QKV, 786432LL, 65536LL,
        768LL, 0LL, 64LL);

    // 3) fused attention -> at2 [B,M,768]
    flash_attn<<<dim3(8, 96), 256, FL_SMEM>>>(
        qkv_p, qkv_p + Q_QKV, qkv_p + 2 * Q_QKV, mask, at2_p);

    // 4) ao = attn @ Uo
    gemm_mma<128><<<dim3(3, 64, 1), 256>>>(
        at2_p, Uo, tmp_p, nullptr, nullptr,
        768, 384, 384, 0, 768, 1.0f, 0, 1, 1,
        0, 0, 0, 0, 0, 0, 0, 0, 0, 0, 0, 0);

    // 5) x1pre = ao @ Vo + bo + x
    gemm_mma<128><<<dim3(6, 64, 1), 256>>>(
        tmp_p, Vo, y_p, bo, x,
        384, 768, 768, 768, 384, 1.0f, 0, 1, 1,
        0, 0, 0, 0, 0, 0, 0, 0, 0, 0, 0, 0);

    // 6) LN1
    ln_kernel<<<8192, 256>>>(y_p, x1_p, ln1g, ln1b);

    // 7) mid = x1 @ U1
    gemm_mma<128><<<dim3(3, 64, 1), 256>>>(
        x1_p, U1, tmp_p, nullptr, nullptr,
        768, 384, 384, 0, 768, 1.0f, 0, 1, 1,
        0, 0, 0, 0, 0, 0, 0, 0, 0, 0, 0, 0);

    // 8) hdn = gelu(mid @ V1 + b1)
    gemm_mma<128><<<dim3(24, 64, 1), 256>>>(
        tmp_p, V1, hdn_p, b1, nullptr,
        384, 3072, 3072, 0, 384, 1.0f, 1, 1, 1,
        0, 0, 0, 0, 0, 0, 0, 0, 0, 0, 0, 0);

    // 9) h2 = hdn @ U2
    gemm_mma<128><<<dim3(3, 64, 1), 256>>>(
        hdn_p, U2, tmp_p, nullptr, nullptr,
        3072, 384, 384, 0, 3072, 1.0f, 0, 1, 1,
        0, 0, 0, 0, 0, 0, 0, 0, 0, 0, 0, 0);

    // 10) ypre = h2 @ V2 + b2 + x1
    gemm_mma<128><<<dim3(6, 64, 1), 256>>>(
        tmp_p, V2, y_p, b2, x1_p,
        384, 768, 768, 768, 384, 1.0f, 0, 1, 1,
        0, 0, 0, 0, 0, 0, 0, 0, 0, 0, 0, 0);

    // 11) LN2 -> out
    ln_kernel<<<8192, 256>>>(y_p, out, ln2g, ln2b);
}

// round 8
// speedup vs baseline: 6.1630x; 1.0731x over previous
#include <cuda_runtime.h>
#include <cuda_fp16.h>
#include <math.h>
#include <stdint.h>

// B=8, M=1024, DM=768, H=12, DH=64, R=32, RFF=384, DFF=3072, RWO=384

// ---------------- scratch (device globals) ----------------
__device__ float  g_w   [3ull * 768 * 384];
__device__ float  g_vw  [3ull * 12 * 32 * 64];
__device__ float  g_vb  [3ull * 12 * 64];
__device__ float  g_t   [3ull * 8 * 1024 * 384];
__device__ __half g_qkvh[3ull * 8 * 12 * 1024 * 64];
__device__ float  g_at2 [8ull * 1024 * 768];
__device__ float  g_tmp [4ull * 8192 * 384];     // up to 4 split-K partials
__device__ float  g_x1  [8192ull * 768];
__device__ float  g_y   [8192ull * 768];
__device__ float  g_hdn [8192ull * 3072];

__device__ __forceinline__ float gelu_exact(float v) {
    return 0.5f * v * (1.0f + erff(v * 0.70710678118654752440f));
}
__device__ __forceinline__ uint32_t h2u(float lo, float hi) {
    __half2 h = __halves2half2(__float2half_rn(lo), __float2half_rn(hi));
    return *(uint32_t*)&h;
}
__device__ __forceinline__ void mma16(float* c, const uint32_t* a, const uint32_t* b) {
    asm volatile(
        "mma.sync.aligned.m16n8k16.row.col.f32.f16.f16.f32 "
        "{%0,%1,%2,%3}, {%4,%5,%6,%7}, {%8,%9}, {%0,%1,%2,%3};"
        : "+f"(c[0]), "+f"(c[1]), "+f"(c[2]), "+f"(c[3])
        : "r"(a[0]), "r"(a[1]), "r"(a[2]), "r"(a[3]), "r"(b[0]), "r"(b[1]));
}
__device__ __forceinline__ uint32_t smem_u32(const void* p) {
    uint32_t a;
    asm("{ .reg .u64 t; cvta.to.shared.u64 t, %1; cvt.u32.u64 %0, t; }" : "=r"(a) : "l"(p));
    return a;
}
#define CPA16(dst, src) \
    asm volatile("cp.async.cg.shared.global [%0], [%1], 16;" ::"r"(dst), "l"(src) : "memory")
#define CPA_COMMIT() asm volatile("cp.async.commit_group;" ::: "memory")

// ================= fused flash attention (fp16 mma) =================
__global__ void __launch_bounds__(256, 1)
flash_attn(const __half* __restrict__ Qg, const __half* __restrict__ Kg,
           const __half* __restrict__ Vg, const float* __restrict__ maskg,
           float* __restrict__ Og) {
    extern __shared__ uint32_t smu[];
    float* Ms = (float*)(smu + 18432);

    const int bh = blockIdx.y;
    const int b = bh / 12, h = bh % 12;
    const __half* Q = Qg + (size_t)bh * 65536;
    const __half* K = Kg + (size_t)bh * 65536;
    const __half* V = Vg + (size_t)bh * 65536;
    const float* mask = maskg + b * 1024;
    float* O = Og + (size_t)b * 1024 * 768 + h * 64;

    const int tid = threadIdx.x;
    const int wid = tid >> 5, lane = tid & 31;
    const int qr = lane >> 2, qc = lane & 3;
    const int m0row = blockIdx.x * 128 + wid * 16;

    auto k_load = [&](int c, int buf) {
        uint32_t* Ks = smu + buf * 4608;
        const __half* Kc = K + ((size_t)(c << 7)) * 64;
#pragma unroll
        for (int i = 0; i < 4; i++) {
            int f = tid + (i << 8);
            int kv = f >> 3, c4 = f & 7;
            CPA16(smem_u32(Ks + kv * 36 + c4 * 4), Kc + kv * 64 + c4 * 8);
        }
    };
    CPA16(smem_u32(Ms + tid * 4), mask + tid * 4);
    k_load(0, 0);
    CPA_COMMIT();
    k_load(1, 1);
    CPA_COMMIT();

    uint32_t qf[4][4];
    {
        const __half2 s2 = __float2half2_rn(0.125f);
        const __half* Qr0 = Q + (size_t)(m0row + qr) * 64;
        const __half* Qr1 = Q + (size_t)(m0row + qr + 8) * 64;
#pragma unroll
        for (int kd = 0; kd < 4; kd++) {
            __half2 a0 = __hmul2(*(const __half2*)(Qr0 + kd * 16 + 2 * qc), s2);
            __half2 a1 = __hmul2(*(const __half2*)(Qr1 + kd * 16 + 2 * qc), s2);
            __half2 a2 = __hmul2(*(const __half2*)(Qr0 + kd * 16 + 2 * qc + 8), s2);
            __half2 a3 = __hmul2(*(const __half2*)(Qr1 + kd * 16 + 2 * qc + 8), s2);
            qf[kd][0] = *(uint32_t*)&a0;
            qf[kd][1] = *(uint32_t*)&a1;
            qf[kd][2] = *(uint32_t*)&a2;
            qf[kd][3] = *(uint32_t*)&a3;
        }
    }

    float oacc[8][4];
#pragma unroll
    for (int i = 0; i < 8; i++)
#pragma unroll
        for (int j = 0; j < 4; j++) oacc[i][j] = 0.0f;
    float mrow0 = -INFINITY, mrow1 = -INFINITY, lrow0 = 0.0f, lrow1 = 0.0f;

    for (int c = 0; c < 8; c++) {
        const int buf = c & 1;
        uint32_t* Ks = smu + buf * 4608;
        uint32_t* Vs = smu + 9216 + buf * 4608;
        const int kvb = c << 7;

        if (c < 7) asm volatile("cp.async.wait_group 1;" ::: "memory");
        else       asm volatile("cp.async.wait_group 0;" ::: "memory");
        __syncthreads();

        const __half* Vc = V + ((size_t)kvb) * 64;
        const int kv2 = tid >> 2, dbase = (tid & 3) << 4;
        uint4 ve0 = *(const uint4*)(Vc + (size_t)(2 * kv2) * 64 + dbase);
        uint4 ve1 = *(const uint4*)(Vc + (size_t)(2 * kv2) * 64 + dbase + 8);
        uint4 vo0 = *(const uint4*)(Vc + (size_t)(2 * kv2 + 1) * 64 + dbase);
        uint4 vo1 = *(const uint4*)(Vc + (size_t)(2 * kv2 + 1) * 64 + dbase + 8);

        float sacc[16][4];
#pragma unroll
        for (int nt = 0; nt < 16; nt++) {
            sacc[nt][0] = sacc[nt][1] = sacc[nt][2] = sacc[nt][3] = 0.0f;
            const int n = nt * 8 + qr;
#pragma unroll
            for (int kd = 0; kd < 4; kd++) {
                uint32_t bf[2] = {Ks[n * 36 + kd * 8 + qc], Ks[n * 36 + kd * 8 + qc + 4]};
                mma16(sacc[nt], qf[kd], bf);
            }
        }

        float cm0 = -INFINITY, cm1 = -INFINITY;
#pragma unroll
        for (int nt = 0; nt < 16; nt++) {
            float mk0 = Ms[kvb + nt * 8 + 2 * qc], mk1 = Ms[kvb + nt * 8 + 2 * qc + 1];
            sacc[nt][0] += mk0; sacc[nt][1] += mk1;
            sacc[nt][2] += mk0; sacc[nt][3] += mk1;
            cm0 = fmaxf(cm0, fmaxf(sacc[nt][0], sacc[nt][1]));
            cm1 = fmaxf(cm1, fmaxf(sacc[nt][2], sacc[nt][3]));
        }
        cm0 = fmaxf(cm0, __shfl_xor_sync(0xffffffffu, cm0, 1));
        cm0 = fmaxf(cm0, __shfl_xor_sync(0xffffffffu, cm0, 2));
        cm1 = fmaxf(cm1, __shfl_xor_sync(0xffffffffu, cm1, 1));
        cm1 = fmaxf(cm1, __shfl_xor_sync(0xffffffffu, cm1, 2));
        const float mn0 = fmaxf(mrow0, cm0), mn1 = fmaxf(mrow1, cm1);
        const float al0 = __expf(mrow0 - mn0), al1 = __expf(mrow1 - mn1);
        mrow0 = mn0; mrow1 = mn1;
        float sum0 = 0.0f, sum1 = 0.0f;
#pragma unroll
        for (int nt = 0; nt < 16; nt++) {
            sacc[nt][0] = __expf(sacc[nt][0] - mn0);
            sacc[nt][1] = __expf(sacc[nt][1] - mn0);
            sacc[nt][2] = __expf(sacc[nt][2] - mn1);
            sacc[nt][3] = __expf(sacc[nt][3] - mn1);
            sum0 += sacc[nt][0] + sacc[nt][1];
            sum1 += sacc[nt][2] + sacc[nt][3];
        }
        sum0 += __shfl_xor_sync(0xffffffffu, sum0, 1);
        sum0 += __shfl_xor_sync(0xffffffffu, sum0, 2);
        sum1 += __shfl_xor_sync(0xffffffffu, sum1, 1);
        sum1 += __shfl_xor_sync(0xffffffffu, sum1, 2);
        lrow0 = lrow0 * al0 + sum0;
        lrow1 = lrow1 * al1 + sum1;
#pragma unroll
        for (int i = 0; i < 8; i++) {
            oacc[i][0] *= al0; oacc[i][1] *= al0;
            oacc[i][2] *= al1; oacc[i][3] *= al1;
        }

        {
            union { uint4 u4[2]; unsigned short us[16]; } e, o;
            e.u4[0] = ve0; e.u4[1] = ve1;
            o.u4[0] = vo0; o.u4[1] = vo1;
#pragma unroll
            for (int j = 0; j < 16; j++)
                Vs[kv2 * 72 + dbase + j] = (uint32_t)e.us[j] | ((uint32_t)o.us[j] << 16);
        }
        __syncthreads();
        if (c + 2 < 8) { k_load(c + 2, buf); CPA_COMMIT(); }

#pragma unroll
        for (int kt = 0; kt < 8; kt++) {
            uint32_t af[4];
            af[0] = h2u(sacc[2 * kt][0], sacc[2 * kt][1]);
            af[1] = h2u(sacc[2 * kt][2], sacc[2 * kt][3]);
            af[2] = h2u(sacc[2 * kt + 1][0], sacc[2 * kt + 1][1]);
            af[3] = h2u(sacc[2 * kt + 1][2], sacc[2 * kt + 1][3]);
#pragma unroll
            for (int nt2 = 0; nt2 < 8; nt2++) {
                const int n = nt2 * 8 + qr;
                uint32_t bf[2] = {Vs[(kt * 8 + qc) * 72 + n], Vs[(kt * 8 + qc + 4) * 72 + n]};
                mma16(oacc[nt2], af, bf);
            }
        }
    }

    const float il0 = 1.0f / lrow0, il1 = 1.0f / lrow1;
    const int r0 = m0row + qr, r1 = m0row + qr + 8;
#pragma unroll
    for (int nt2 = 0; nt2 < 8; nt2++) {
        const int col = nt2 * 8 + 2 * qc;
        *(float2*)(O + (size_t)r0 * 768 + col) =
            make_float2(oacc[nt2][0] * il0, oacc[nt2][1] * il0);
        *(float2*)(O + (size_t)r1 * 768 + col) =
            make_float2(oacc[nt2][2] * il1, oacc[nt2][3] * il1);
    }
}

// ---------------- fp16 mma GEMM, 3-level batch, NSUM A-partials ----------------
// mode: 0=none, 1=gelu, 3=half output. z = (i1*D2 + i2)*D3 + i3.
template <int BN, int NSUM>
__global__ void __launch_bounds__(256, 2)
gemm_mma(const float* __restrict__ A, const float* __restrict__ Bm, void* __restrict__ Cv,
         const float* __restrict__ bias, const float* __restrict__ res,
         int lda, int ldb, int ldc, int ldres, int K, float scale, int mode,
         int D2, int D3, long long sum_str,
         long long sA1, long long sA2, long long sA3,
         long long sB1, long long sB2, long long sB3,
         long long sC1, long long sC2, long long sC3,
         long long sb1, long long sb2, long long sb3) {
    constexpr int BM = 128, NT = 256, WN = BN / 4, NTILES = WN / 8;
    constexpr int SA = BM + 8, SB = BN + 8;   // pad 8 -> conflict-free fragment LDS
    constexpr int LBI = BN / 32;

    __shared__ uint32_t As32[2][16][SA];
    __shared__ uint32_t Bs32[2][16][SB];

    const int z = blockIdx.z;
    const int i1 = z / (D2 * D3);
    const int rem = z % (D2 * D3);
    const int i2 = rem / D3, i3 = rem % D3;
    A += i1 * sA1 + i2 * sA2 + i3 * sA3;
    Bm += i1 * sB1 + i2 * sB2 + i3 * sB3;
    const long long coff = i1 * sC1 + i2 * sC2 + i3 * sC3;
    const long long boff = i1 * sb1 + i2 * sb2 + i3 * sb3;

    const int x0 = blockIdx.x * BN, y0 = blockIdx.y * BM;
    const int tid = threadIdx.x;
    const int wid = tid >> 5, lane = tid & 31;
    const int wm0 = (wid >> 2) * 64;
    const int wn0 = (wid & 3) * WN;
    const int qr = lane >> 2, qc = lane & 3;

    float4 ra[4];
    float2 rb0[LBI], rb1[LBI];

    auto ldg = [&](int k0) {
#pragma unroll
        for (int i = 0; i < 4; i++) {
            int f = tid + i * NT;
            int m = f >> 3, kq = f & 7;
            const float* ap = A + (size_t)(y0 + m) * lda + k0 + kq * 4;
            float4 v = *(const float4*)ap;
#pragma unroll
            for (int s = 1; s < NSUM; s++) {
                float4 w = *(const float4*)(ap + (size_t)s * sum_str);
                v.x += w.x; v.y += w.y; v.z += w.z; v.w += w.w;
            }
            ra[i] = v;
        }
#pragma unroll
        for (int i = 0; i < LBI; i++) {
            int f = tid + i * NT;
            int k2 = f / (BN / 2), n2 = f % (BN / 2);
            rb0[i] = *(const float2*)(Bm + (size_t)(k0 + 2 * k2) * ldb + x0 + 2 * n2);
            rb1[i] = *(const float2*)(Bm + (size_t)(k0 + 2 * k2 + 1) * ldb + x0 + 2 * n2);
        }
    };
    auto sts = [&](int buf) {
#pragma unroll
        for (int i = 0; i < 4; i++) {
            int f = tid + i * NT;
            int m = f >> 3, kq = f & 7;
            As32[buf][2 * kq][m] = h2u(ra[i].x, ra[i].y);
            As32[buf][2 * kq + 1][m] = h2u(ra[i].z, ra[i].w);
        }
#pragma unroll
        for (int i = 0; i < LBI; i++) {
            int f = tid + i * NT;
            int k2 = f / (BN / 2), n2 = f % (BN / 2);
            Bs32[buf][k2][2 * n2] = h2u(rb0[i].x, rb1[i].x);
            Bs32[buf][k2][2 * n2 + 1] = h2u(rb0[i].y, rb1[i].y);
        }
    };

    float acc[4][NTILES][4];
#pragma unroll
    for (int i = 0; i < 4; i++)
#pragma unroll
        for (int j = 0; j < NTILES; j++)
#pragma unroll
            for (int l = 0; l < 4; l++) acc[i][j][l] = 0.0f;

    ldg(0);
    sts(0);
    __syncthreads();
    const int nb = K >> 5;
    for (int kb = 0; kb < nb; kb++) {
        const int cur = kb & 1;
        if (kb + 1 < nb) ldg((kb + 1) << 5);
#pragma unroll
        for (int kk2 = 0; kk2 < 16; kk2 += 8) {
            uint32_t af[4][4], bf[NTILES][2];
#pragma unroll
            for (int mt = 0; mt < 4; mt++) {
                int m = wm0 + mt * 16 + qr;
                af[mt][0] = As32[cur][kk2 + qc][m];
                af[mt][1] = As32[cur][kk2 + qc][m + 8];
                af[mt][2] = As32[cur][kk2 + qc + 4][m];
                af[mt][3] = As32[cur][kk2 + qc + 4][m + 8];
            }
#pragma unroll
            for (int nt = 0; nt < NTILES; nt++) {
                int n = wn0 + nt * 8 + qr;
                bf[nt][0] = Bs32[cur][kk2 + qc][n];
                bf[nt][1] = Bs32[cur][kk2 + qc + 4][n];
            }
#pragma unroll
            for (int mt = 0; mt < 4; mt++)
#pragma unroll
                for (int nt = 0; nt < NTILES; nt++) mma16(acc[mt][nt], af[mt], bf[nt]);
        }
        if (kb + 1 < nb) sts(cur ^ 1);
        __syncthreads();
    }

    float* Cf = (float*)Cv + coff;
    __half* Ch = (__half*)Cv + coff;
#pragma unroll
    for (int mt = 0; mt < 4; mt++) {
#pragma unroll
        for (int nt = 0; nt < NTILES; nt++) {
            const int n = x0 + wn0 + nt * 8 + qc * 2;
#pragma unroll
            for (int half_ = 0; half_ < 2; half_++) {
                const int m = y0 + wm0 + mt * 16 + qr + half_ * 8;
                float v0 = acc[mt][nt][half_ * 2 + 0] * scale;
                float v1 = acc[mt][nt][half_ * 2 + 1] * scale;
                if (bias) { v0 += bias[boff + n]; v1 += bias[boff + n + 1]; }
                if (res) {
                    v0 += res[(size_t)m * ldres + n];
                    v1 += res[(size_t)m * ldres + n + 1];
                }
                if (mode == 1) { v0 = gelu_exact(v0); v1 = gelu_exact(v1); }
                if (mode == 3) {
                    __half2 hv = __halves2half2(__float2half_rn(v0), __float2half_rn(v1));
                    *(__half2*)(Ch + (size_t)m * ldc + n) = hv;
                } else {
                    *(float2*)(Cf + (size_t)m * ldc + n) = make_float2(v0, v1);
                }
            }
        }
    }
}

// ---------------- packing ----------------
__global__ void pack_all(const float* __restrict__ Pq, const float* __restrict__ Pk,
                         const float* __restrict__ Pv,
                         const float* __restrict__ Vq, const float* __restrict__ Vk,
                         const float* __restrict__ Vv,
                         const float* __restrict__ bq, const float* __restrict__ bk,
                         const float* __restrict__ bv,
                         float* __restrict__ W, float* __restrict__ VW,
                         float* __restrict__ VB) {
    int idx = blockIdx.x * blockDim.x + threadIdx.x;
    const int NW = 3 * 768 * 384;
    const int NV = 3 * 24576;
    if (idx < NW) {
        int q = idx / (768 * 384);
        int r2 = idx % (768 * 384);
        int k = r2 / 384, n = r2 % 384;
        const float* P = (q == 0) ? Pq : ((q == 1) ? Pk : Pv);
        W[idx] = P[((size_t)(n >> 5) * 768 + k) * 32 + (n & 31)];
    } else if (idx < NW + NV) {
        int e = idx - NW;
        int q = e / 24576, r = e % 24576;
        const float* S = (q == 0) ? Vq : ((q == 1) ? Vk : Vv);
        VW[e] = S[r];
    } else if (idx < NW + NV + 3 * 768) {
        int e = idx - NW - NV;
        int q = e / 768, r = e % 768;
        const float* S = (q == 0) ? bq : ((q == 1) ? bk : bv);
        VB[e] = S[r];
    }
}

// ---------------- LayerNorm (single pass, shuffle reduce) ----------------
__global__ void ln_kernel(const float* __restrict__ in, float* __restrict__ out,
                          const float* __restrict__ g, const float* __restrict__ bb) {
    __shared__ float rs_[8], rss_[8];
    const float* xr = in + (size_t)blockIdx.x * 768;
    float* yr = out + (size_t)blockIdx.x * 768;
    const int tid = threadIdx.x;
    float v[3];
    float s = 0.0f, ss = 0.0f;
#pragma unroll
    for (int i = 0; i < 3; i++) {
        v[i] = xr[tid + i * 256];
        s += v[i];
        ss += v[i] * v[i];
    }
#pragma unroll
    for (int o = 16; o; o >>= 1) {
        s += __shfl_xor_sync(0xffffffffu, s, o);
        ss += __shfl_xor_sync(0xffffffffu, ss, o);
    }
    if ((tid & 31) == 0) { rs_[tid >> 5] = s; rss_[tid >> 5] = ss; }
    __syncthreads();
    s = 0.0f; ss = 0.0f;
#pragma unroll
    for (int w = 0; w < 8; w++) { s += rs_[w]; ss += rss_[w]; }
    const float mu = s * (1.0f / 768.0f);
    const float var = fmaxf(ss * (1.0f / 768.0f) - mu * mu, 0.0f);
    const float rstd = rsqrtf(var + 1e-12f);
#pragma unroll
    for (int i = 0; i < 3; i++) {
        int c = tid + i * 256;
        yr[c] = (v[i] - mu) * rstd * g[c] + bb[c];
    }
}

extern "C" void kernel_launch(void* const* d_in, const int* in_sizes, int n_in,
                              void* d_out, int out_size) {
    const float* x    = (const float*)d_in[0];
    const float* mask = (const float*)d_in[1];
    const float* Pq   = (const float*)d_in[2];
    const float* Vq   = (const float*)d_in[3];
    const float* bq   = (const float*)d_in[4];
    const float* Pk   = (const float*)d_in[5];
    const float* Vk   = (const float*)d_in[6];
    const float* bk   = (const float*)d_in[7];
    const float* Pv   = (const float*)d_in[8];
    const float* Vv   = (const float*)d_in[9];
    const float* bv   = (const float*)d_in[10];
    const float* Uo   = (const float*)d_in[11];
    const float* Vo   = (const float*)d_in[12];
    const float* bo   = (const float*)d_in[13];
    const float* U1   = (const float*)d_in[14];
    const float* V1   = (const float*)d_in[15];
    const float* b1   = (const float*)d_in[16];
    const float* U2   = (const float*)d_in[17];
    const float* V2   = (const float*)d_in[18];
    const float* b2   = (const float*)d_in[19];
    const float* ln1g = (const float*)d_in[20];
    const float* ln1b = (const float*)d_in[21];
    const float* ln2g = (const float*)d_in[22];
    const float* ln2b = (const float*)d_in[23];
    float* out = (float*)d_out;

    float *w_p, *vw_p, *vb_p, *t_p, *at2_p, *tmp_p, *x1_p, *y_p, *hdn_p;
    __half* qkv_p;
    cudaGetSymbolAddress((void**)&w_p,   g_w);
    cudaGetSymbolAddress((void**)&vw_p,  g_vw);
    cudaGetSymbolAddress((void**)&vb_p,  g_vb);
    cudaGetSymbolAddress((void**)&t_p,   g_t);
    cudaGetSymbolAddress((void**)&qkv_p, g_qkvh);
    cudaGetSymbolAddress((void**)&at2_p, g_at2);
    cudaGetSymbolAddress((void**)&tmp_p, g_tmp);
    cudaGetSymbolAddress((void**)&x1_p,  g_x1);
    cudaGetSymbolAddress((void**)&y_p,   g_y);
    cudaGetSymbolAddress((void**)&hdn_p, g_hdn);

    const long long T_QKV = 3145728, Q_QKV = 6291456, W_SZ = 294912;
    const long long PART = 3145728;   // 8192*384 partial slice
    const int FL_SMEM = (18432 + 1024) * 4;
    cudaFuncSetAttribute(flash_attn, cudaFuncAttributeMaxDynamicSharedMemorySize, FL_SMEM);

    // 0) pack weights
    const int NPACK = 3 * 768 * 384 + 3 * 24576 + 3 * 768;
    pack_all<<<(NPACK + 255) / 256, 256>>>(Pq, Pk, Pv, Vq, Vk, Vv, bq, bk, bv,
                                           w_p, vw_p, vb_p);

    // 1) t = x @ W   (z over qkv)
    gemm_mma<128, 1><<<dim3(3, 64, 3), 256>>>(
        x, w_p, t_p, nullptr, nullptr,
        768, 384, 384, 0, 768, 1.0f, 0, 1, 1, 0LL,
        0LL, 0LL, 0LL, W_SZ, 0LL, 0LL, T_QKV, 0LL, 0LL, 0LL, 0LL, 0LL);

    // 2) Q/K/V = t @ Vqkv + b -> fp16. z=(q,b,h), K=32
    gemm_mma<64, 1><<<dim3(1, 8, 288), 256>>>(
        t_p, vw_p, qkv_p, vb_p, nullptr,
        384, 64, 64, 0, 32, 1.0f, 3, 8, 12, 0LL,
        T_QKV, 393216LL, 32LL,
        24576LL, 0LL, 2048LL,
        Q_QKV, 786432LL, 65536LL,
        768LL, 0LL, 64LL);

    // 3) fused attention -> at2
    flash_attn<<<dim3(8, 96), 256, FL_SMEM>>>(
        qkv_p, qkv_p + Q_QKV, qkv_p + 2 * Q_QKV, mask, at2_p);

    // 4) ao partials = attn @ Uo  (split-K x2)
    gemm_mma<128, 1><<<dim3(3, 64, 2), 256>>>(
        at2_p, Uo, tmp_p, nullptr, nullptr,
        768, 384, 384, 0, 384, 1.0f, 0, 1, 2, 0LL,
        0LL, 0LL, 384LL, 0LL, 0LL, 147456LL, 0LL, 0LL, PART, 0, 0, 0);

    // 5) x1pre = sum(ao) @ Vo + bo + x
    gemm_mma<128, 2><<<dim3(6, 64, 1), 256>>>(
        tmp_p, Vo, y_p, bo, x,
        384, 768, 768, 768, 384, 1.0f, 0, 1, 1, PART,
        0, 0, 0, 0, 0, 0, 0, 0, 0, 0, 0, 0);

    // 6) LN1
    ln_kernel<<<8192, 256>>>(y_p, x1_p, ln1g, ln1b);

    // 7) mid partials = x1 @ U1  (split-K x2)
    gemm_mma<128, 1><<<dim3(3, 64, 2), 256>>>(
        x1_p, U1, tmp_p, nullptr, nullptr,
        768, 384, 384, 0, 384, 1.0f, 0, 1, 2, 0LL,
        0LL, 0LL, 384LL, 0LL, 0LL, 147456LL, 0LL, 0LL, PART, 0, 0, 0);

    // 8) hdn = gelu(sum(mid) @ V1 + b1)
    gemm_mma<128, 2><<<dim3(24, 64, 1), 256>>>(
        tmp_p, V1, hdn_p, b1, nullptr,
        384, 3072, 3072, 0, 384, 1.0f, 1, 1, 1, PART,
        0, 0, 0, 0, 0, 0, 0, 0, 0, 0, 0, 0);

    // 9) h2 partials = hdn @ U2  (split-K x4)
    gemm_mma<128, 1><<<dim3(3, 64, 4), 256>>>(
        hdn_p, U2, tmp_p, nullptr, nullptr,
        3072, 384, 384, 0, 768, 1.0f, 0, 1, 4, 0LL,
        0LL, 0LL, 768LL, 0LL, 0LL, 294912LL, 0LL, 0LL, PART, 0, 0, 0);

    // 10) ypre = sum(h2) @ V2 + b2 + x1
    gemm_mma<128, 4><<<dim3(6, 64, 1), 256>>>(
        tmp_p, V2, y_p, b2, x1_p,
        384, 768, 768, 768, 384, 1.0f, 0, 1, 1, PART,
        0, 0, 0, 0, 0, 0, 0, 0, 0, 0, 0, 0);

    // 11) LN2 -> out
    ln_kernel<<<8192, 256>>>(y_p, out, ln2g, ln2b);
}

// round 10
// speedup vs baseline: 6.5813x; 1.0679x over previous
#include <cuda_runtime.h>
#include <cuda_fp16.h>
#include <math.h>
#include <stdint.h>

// B=8, M=1024, DM=768, H=12, DH=64, R=32, RFF=384, DFF=3072, RWO=384

// ---------------- scratch (device globals) ----------------
__device__ float  g_w   [3ull * 768 * 384];
__device__ float  g_vw  [3ull * 12 * 32 * 64];
__device__ float  g_vb  [3ull * 12 * 64];
__device__ float  g_t   [3ull * 8 * 1024 * 384];
__device__ __half g_qkvh[3ull * 8 * 12 * 1024 * 64];
__device__ float  g_at2 [8ull * 1024 * 768];
__device__ float  g_tmp [4ull * 8192 * 384];
__device__ float  g_x1  [8192ull * 768];
__device__ float  g_y   [8192ull * 768];
__device__ float  g_hdn [8192ull * 3072];

__device__ __forceinline__ float gelu_exact(float v) {
    return 0.5f * v * (1.0f + erff(v * 0.70710678118654752440f));
}
__device__ __forceinline__ uint32_t h2u(float lo, float hi) {
    __half2 h = __halves2half2(__float2half_rn(lo), __float2half_rn(hi));
    return *(uint32_t*)&h;
}
__device__ __forceinline__ void mma16(float* c, const uint32_t* a, const uint32_t* b) {
    asm volatile(
        "mma.sync.aligned.m16n8k16.row.col.f32.f16.f16.f32 "
        "{%0,%1,%2,%3}, {%4,%5,%6,%7}, {%8,%9}, {%0,%1,%2,%3};"
        : "+f"(c[0]), "+f"(c[1]), "+f"(c[2]), "+f"(c[3])
        : "r"(a[0]), "r"(a[1]), "r"(a[2]), "r"(a[3]), "r"(b[0]), "r"(b[1]));
}
__device__ __forceinline__ void mma16b(float* c, const uint32_t* a, uint32_t b0, uint32_t b1) {
    asm volatile(
        "mma.sync.aligned.m16n8k16.row.col.f32.f16.f16.f32 "
        "{%0,%1,%2,%3}, {%4,%5,%6,%7}, {%8,%9}, {%0,%1,%2,%3};"
        : "+f"(c[0]), "+f"(c[1]), "+f"(c[2]), "+f"(c[3])
        : "r"(a[0]), "r"(a[1]), "r"(a[2]), "r"(a[3]), "r"(b0), "r"(b1));
}
__device__ __forceinline__ void ldsm4(uint32_t* r, uint32_t addr) {
    asm volatile("ldmatrix.sync.aligned.m8n8.x4.shared.b16 {%0,%1,%2,%3}, [%4];"
                 : "=r"(r[0]), "=r"(r[1]), "=r"(r[2]), "=r"(r[3]) : "r"(addr));
}
__device__ __forceinline__ void ldsm4t(uint32_t* r, uint32_t addr) {
    asm volatile("ldmatrix.sync.aligned.m8n8.x4.trans.shared.b16 {%0,%1,%2,%3}, [%4];"
                 : "=r"(r[0]), "=r"(r[1]), "=r"(r[2]), "=r"(r[3]) : "r"(addr));
}
__device__ __forceinline__ uint32_t smem_u32(const void* p) {
    uint32_t a;
    asm("{ .reg .u64 t; cvta.to.shared.u64 t, %1; cvt.u32.u64 %0, t; }" : "=r"(a) : "l"(p));
    return a;
}
#define CPA16(dst, src) \
    asm volatile("cp.async.cg.shared.global [%0], [%1], 16;" ::"r"(dst), "l"(src) : "memory")
#define CPA_COMMIT() asm volatile("cp.async.commit_group;" ::: "memory")

// ================= fused flash attention (fp16 mma + ldmatrix) =================
// K/V tiles: [128 kv][64 d] fp16, row stride 144 B.
__global__ void __launch_bounds__(256, 1)
flash_attn(const __half* __restrict__ Qg, const __half* __restrict__ Kg,
           const __half* __restrict__ Vg, const float* __restrict__ maskg,
           float* __restrict__ Og) {
    extern __shared__ uint32_t smu[];
    float* Ms = (float*)(smu + 18432);
    const uint32_t sbase = smem_u32(smu);

    const int bh = blockIdx.y;
    const int b = bh / 12, h = bh % 12;
    const __half* Q = Qg + (size_t)bh * 65536;
    const __half* K = Kg + (size_t)bh * 65536;
    const __half* V = Vg + (size_t)bh * 65536;
    const float* mask = maskg + b * 1024;
    float* O = Og + (size_t)b * 1024 * 768 + h * 64;

    const int tid = threadIdx.x;
    const int wid = tid >> 5, lane = tid & 31;
    const int qr = lane >> 2, qc = lane & 3;
    const int m0row = blockIdx.x * 128 + wid * 16;

    // K (non-trans) lane map: matrices in order {n0-7,klo},{n0-7,khi},{n8-15,klo},{n8-15,khi}
    const int nrow = (lane & 7) | ((lane >> 4) << 3);
    const int koff8 = ((lane >> 3) & 1) << 3;
    // V (trans) lane map: matrices {klo,n0-7},{khi,n0-7},{klo,n8-15},{khi,n8-15}
    const int krow = (lane & 7) + ((lane >> 3) & 1) * 8;
    const int noff8 = ((lane >> 4) << 3);

    auto kv_load = [&](int c, int buf) {
        uint32_t dstK = sbase + buf * 36864;
        uint32_t dstV = dstK + 18432;
        const __half* Kc = K + ((size_t)(c << 7)) * 64;
        const __half* Vc = V + ((size_t)(c << 7)) * 64;
#pragma unroll
        for (int j = 0; j < 4; j++) {
            int idx = tid + (j << 8);
            int kv = idx >> 3, c4 = idx & 7;
            CPA16(dstK + kv * 144 + c4 * 16, Kc + (size_t)kv * 64 + c4 * 8);
            CPA16(dstV + kv * 144 + c4 * 16, Vc + (size_t)kv * 64 + c4 * 8);
        }
    };
    CPA16(smem_u32(Ms + tid * 4), mask + tid * 4);
    kv_load(0, 0);
    CPA_COMMIT();
    kv_load(1, 1);
    CPA_COMMIT();

    // ---- Q fragments, scaled by 1/8 (exact) ----
    uint32_t qf[4][4];
    {
        const __half2 s2 = __float2half2_rn(0.125f);
        const __half* Qr0 = Q + (size_t)(m0row + qr) * 64;
        const __half* Qr1 = Q + (size_t)(m0row + qr + 8) * 64;
#pragma unroll
        for (int kd = 0; kd < 4; kd++) {
            __half2 a0 = __hmul2(*(const __half2*)(Qr0 + kd * 16 + 2 * qc), s2);
            __half2 a1 = __hmul2(*(const __half2*)(Qr1 + kd * 16 + 2 * qc), s2);
            __half2 a2 = __hmul2(*(const __half2*)(Qr0 + kd * 16 + 2 * qc + 8), s2);
            __half2 a3 = __hmul2(*(const __half2*)(Qr1 + kd * 16 + 2 * qc + 8), s2);
            qf[kd][0] = *(uint32_t*)&a0;
            qf[kd][1] = *(uint32_t*)&a1;
            qf[kd][2] = *(uint32_t*)&a2;
            qf[kd][3] = *(uint32_t*)&a3;
        }
    }

    float oacc[8][4];
#pragma unroll
    for (int i = 0; i < 8; i++)
#pragma unroll
        for (int j = 0; j < 4; j++) oacc[i][j] = 0.0f;
    float mrow0 = -INFINITY, mrow1 = -INFINITY, lrow0 = 0.0f, lrow1 = 0.0f;

    for (int c = 0; c < 8; c++) {
        const int buf = c & 1;
        const uint32_t ksb = sbase + buf * 36864;
        const uint32_t vsb = ksb + 18432;
        const int kvb = c << 7;

        if (c < 7) asm volatile("cp.async.wait_group 1;" ::: "memory");
        else       asm volatile("cp.async.wait_group 0;" ::: "memory");
        __syncthreads();

        // ---- S = (Q/8) @ K^T ----
        float sacc[16][4];
#pragma unroll
        for (int nt = 0; nt < 16; nt++)
            sacc[nt][0] = sacc[nt][1] = sacc[nt][2] = sacc[nt][3] = 0.0f;
#pragma unroll
        for (int ntp = 0; ntp < 8; ntp++) {
            const uint32_t rowb = ksb + (uint32_t)(ntp * 16 + nrow) * 144;
#pragma unroll
            for (int kd = 0; kd < 4; kd++) {
                uint32_t bb[4];
                ldsm4(bb, rowb + (uint32_t)(kd * 16 + koff8) * 2);
                mma16b(sacc[2 * ntp], qf[kd], bb[0], bb[1]);
                mma16b(sacc[2 * ntp + 1], qf[kd], bb[2], bb[3]);
            }
        }

        // ---- online softmax ----
        float cm0 = -INFINITY, cm1 = -INFINITY;
#pragma unroll
        for (int nt = 0; nt < 16; nt++) {
            float mk0 = Ms[kvb + nt * 8 + 2 * qc], mk1 = Ms[kvb + nt * 8 + 2 * qc + 1];
            sacc[nt][0] += mk0; sacc[nt][1] += mk1;
            sacc[nt][2] += mk0; sacc[nt][3] += mk1;
            cm0 = fmaxf(cm0, fmaxf(sacc[nt][0], sacc[nt][1]));
            cm1 = fmaxf(cm1, fmaxf(sacc[nt][2], sacc[nt][3]));
        }
        cm0 = fmaxf(cm0, __shfl_xor_sync(0xffffffffu, cm0, 1));
        cm0 = fmaxf(cm0, __shfl_xor_sync(0xffffffffu, cm0, 2));
        cm1 = fmaxf(cm1, __shfl_xor_sync(0xffffffffu, cm1, 1));
        cm1 = fmaxf(cm1, __shfl_xor_sync(0xffffffffu, cm1, 2));
        const float mn0 = fmaxf(mrow0, cm0), mn1 = fmaxf(mrow1, cm1);
        const float al0 = __expf(mrow0 - mn0), al1 = __expf(mrow1 - mn1);
        mrow0 = mn0; mrow1 = mn1;
        float sum0 = 0.0f, sum1 = 0.0f;
#pragma unroll
        for (int nt = 0; nt < 16; nt++) {
            sacc[nt][0] = __expf(sacc[nt][0] - mn0);
            sacc[nt][1] = __expf(sacc[nt][1] - mn0);
            sacc[nt][2] = __expf(sacc[nt][2] - mn1);
            sacc[nt][3] = __expf(sacc[nt][3] - mn1);
            sum0 += sacc[nt][0] + sacc[nt][1];
            sum1 += sacc[nt][2] + sacc[nt][3];
        }
        sum0 += __shfl_xor_sync(0xffffffffu, sum0, 1);
        sum0 += __shfl_xor_sync(0xffffffffu, sum0, 2);
        sum1 += __shfl_xor_sync(0xffffffffu, sum1, 1);
        sum1 += __shfl_xor_sync(0xffffffffu, sum1, 2);
        lrow0 = lrow0 * al0 + sum0;
        lrow1 = lrow1 * al1 + sum1;
#pragma unroll
        for (int i = 0; i < 8; i++) {
            oacc[i][0] *= al0; oacc[i][1] *= al0;
            oacc[i][2] *= al1; oacc[i][3] *= al1;
        }

        // ---- O += P @ V ----
#pragma unroll
        for (int kt2 = 0; kt2 < 8; kt2++) {
            uint32_t af[4];
            af[0] = h2u(sacc[2 * kt2][0], sacc[2 * kt2][1]);
            af[1] = h2u(sacc[2 * kt2][2], sacc[2 * kt2][3]);
            af[2] = h2u(sacc[2 * kt2 + 1][0], sacc[2 * kt2 + 1][1]);
            af[3] = h2u(sacc[2 * kt2 + 1][2], sacc[2 * kt2 + 1][3]);
            const uint32_t rowb = vsb + (uint32_t)(kt2 * 16 + krow) * 144;
#pragma unroll
            for (int dtp = 0; dtp < 4; dtp++) {
                uint32_t bb[4];
                ldsm4t(bb, rowb + (uint32_t)(dtp * 16 + noff8) * 2);
                mma16b(oacc[2 * dtp], af, bb[0], bb[1]);
                mma16b(oacc[2 * dtp + 1], af, bb[2], bb[3]);
            }
        }
        __syncthreads();
        if (c + 2 < 8) { kv_load(c + 2, buf); CPA_COMMIT(); }
    }

    const float il0 = 1.0f / lrow0, il1 = 1.0f / lrow1;
    const int r0 = m0row + qr, r1 = m0row + qr + 8;
#pragma unroll
    for (int nt2 = 0; nt2 < 8; nt2++) {
        const int col = nt2 * 8 + 2 * qc;
        *(float2*)(O + (size_t)r0 * 768 + col) =
            make_float2(oacc[nt2][0] * il0, oacc[nt2][1] * il0);
        *(float2*)(O + (size_t)r1 * 768 + col) =
            make_float2(oacc[nt2][2] * il1, oacc[nt2][3] * il1);
    }
}

// ---------------- fp16 mma GEMM + ldmatrix, 3-level batch, NSUM A-partials ----------------
template <int BN, int NSUM>
__global__ void __launch_bounds__(256, 2)
gemm_mma(const float* __restrict__ A, const float* __restrict__ Bm, void* __restrict__ Cv,
         const float* __restrict__ bias, const float* __restrict__ res,
         int lda, int ldb, int ldc, int ldres, int K, float scale, int mode,
         int D2, int D3, long long sum_str,
         long long sA1, long long sA2, long long sA3,
         long long sB1, long long sB2, long long sB3,
         long long sC1, long long sC2, long long sC3,
         long long sb1, long long sb2, long long sb3) {
    constexpr int BM = 128, NT = 256, WN = BN / 4, NTILES = WN / 8, NPAIR = NTILES / 2;
    constexpr int AROW = 20;
    constexpr int BROW = BN / 2 + 4;
    constexpr int LBI = BN / 32;

    __shared__ uint32_t As32[2][BM * AROW];
    __shared__ uint32_t Bs32[2][32 * BROW];

    const int z = blockIdx.z;
    const int i1 = z / (D2 * D3);
    const int rem = z % (D2 * D3);
    const int i2 = rem / D3, i3 = rem % D3;
    A += i1 * sA1 + i2 * sA2 + i3 * sA3;
    Bm += i1 * sB1 + i2 * sB2 + i3 * sB3;
    const long long coff = i1 * sC1 + i2 * sC2 + i3 * sC3;
    const long long boff = i1 * sb1 + i2 * sb2 + i3 * sb3;

    const int x0 = blockIdx.x * BN, y0 = blockIdx.y * BM;
    const int tid = threadIdx.x;
    const int wid = tid >> 5, lane = tid & 31;
    const int wm0 = (wid >> 2) * 64;
    const int wn0 = (wid & 3) * WN;
    const int qr = lane >> 2, qc = lane & 3;

    const uint32_t aBase = smem_u32(As32);
    const uint32_t bBase = smem_u32(Bs32);
    const int arow_l = lane & 15, akoff = ((lane >> 4) << 3);
    const int bkrow = (lane & 7) + ((lane >> 3) & 1) * 8, bnoff = ((lane >> 4) << 3);

    float4 ra[4], rbv[LBI];

    auto ldg = [&](int k0) {
#pragma unroll
        for (int i = 0; i < 4; i++) {
            int f = tid + i * NT;
            int m = f >> 3, kq = f & 7;
            const float* ap = A + (size_t)(y0 + m) * lda + k0 + kq * 4;
            float4 v = *(const float4*)ap;
#pragma unroll
            for (int s = 1; s < NSUM; s++) {
                float4 w = *(const float4*)(ap + (size_t)s * sum_str);
                v.x += w.x; v.y += w.y; v.z += w.z; v.w += w.w;
            }
            ra[i] = v;
        }
#pragma unroll
        for (int i = 0; i < LBI; i++) {
            int f = tid + i * NT;
            int k = f / (BN / 4), nq = f % (BN / 4);
            rbv[i] = *(const float4*)(Bm + (size_t)(k0 + k) * ldb + x0 + 4 * nq);
        }
    };
    auto sts = [&](int buf) {
#pragma unroll
        for (int i = 0; i < 4; i++) {
            int f = tid + i * NT;
            int m = f >> 3, kq = f & 7;
            As32[buf][m * AROW + 2 * kq] = h2u(ra[i].x, ra[i].y);
            As32[buf][m * AROW + 2 * kq + 1] = h2u(ra[i].z, ra[i].w);
        }
#pragma unroll
        for (int i = 0; i < LBI; i++) {
            int f = tid + i * NT;
            int k = f / (BN / 4), nq = f % (BN / 4);
            Bs32[buf][k * BROW + 2 * nq] = h2u(rbv[i].x, rbv[i].y);
            Bs32[buf][k * BROW + 2 * nq + 1] = h2u(rbv[i].z, rbv[i].w);
        }
    };

    float acc[4][NTILES][4];
#pragma unroll
    for (int i = 0; i < 4; i++)
#pragma unroll
        for (int j = 0; j < NTILES; j++)
#pragma unroll
            for (int l = 0; l < 4; l++) acc[i][j][l] = 0.0f;

    ldg(0);
    sts(0);
    __syncthreads();
    const int nb = K >> 5;
    for (int kb = 0; kb < nb; kb++) {
        const int cur = kb & 1;
        if (kb + 1 < nb) ldg((kb + 1) << 5);
        const uint32_t aB = aBase + cur * (BM * AROW * 4);
        const uint32_t bB = bBase + cur * (32 * BROW * 4);
#pragma unroll
        for (int kk = 0; kk < 2; kk++) {
            uint32_t af[4][4], bb[NPAIR][4];
#pragma unroll
            for (int mt = 0; mt < 4; mt++)
                ldsm4(af[mt], aB + (uint32_t)(wm0 + mt * 16 + arow_l) * 80 +
                                  (uint32_t)(kk * 16 + akoff) * 2);
#pragma unroll
            for (int p = 0; p < NPAIR; p++)
                ldsm4t(bb[p], bB + (uint32_t)(kk * 16 + bkrow) * (BROW * 4) +
                                  (uint32_t)(wn0 + p * 16 + bnoff) * 2);
#pragma unroll
            for (int mt = 0; mt < 4; mt++)
#pragma unroll
                for (int p = 0; p < NPAIR; p++) {
                    mma16b(acc[mt][2 * p], af[mt], bb[p][0], bb[p][1]);
                    mma16b(acc[mt][2 * p + 1], af[mt], bb[p][2], bb[p][3]);
                }
        }
        if (kb + 1 < nb) sts(cur ^ 1);
        __syncthreads();
    }

    float* Cf = (float*)Cv + coff;
    __half* Ch = (__half*)Cv + coff;
#pragma unroll
    for (int mt = 0; mt < 4; mt++) {
#pragma unroll
        for (int nt = 0; nt < NTILES; nt++) {
            const int n = x0 + wn0 + nt * 8 + qc * 2;
#pragma unroll
            for (int half_ = 0; half_ < 2; half_++) {
                const int m = y0 + wm0 + mt * 16 + qr + half_ * 8;
                float v0 = acc[mt][nt][half_ * 2 + 0] * scale;
                float v1 = acc[mt][nt][half_ * 2 + 1] * scale;
                if (bias) { v0 += bias[boff + n]; v1 += bias[boff + n + 1]; }
                if (res) {
                    v0 += res[(size_t)m * ldres + n];
                    v1 += res[(size_t)m * ldres + n + 1];
                }
                if (mode == 1) { v0 = gelu_exact(v0); v1 = gelu_exact(v1); }
                if (mode == 3) {
                    __half2 hv = __halves2half2(__float2half_rn(v0), __float2half_rn(v1));
                    *(__half2*)(Ch + (size_t)m * ldc + n) = hv;
                } else {
                    *(float2*)(Cf + (size_t)m * ldc + n) = make_float2(v0, v1);
                }
            }
        }
    }
}

// ---------------- packing ----------------
__global__ void pack_all(const float* __restrict__ Pq, const float* __restrict__ Pk,
                         const float* __restrict__ Pv,
                         const float* __restrict__ Vq, const float* __restrict__ Vk,
                         const float* __restrict__ Vv,
                         const float* __restrict__ bq, const float* __restrict__ bk,
                         const float* __restrict__ bv,
                         float* __restrict__ W, float* __restrict__ VW,
                         float* __restrict__ VB) {
    int idx = blockIdx.x * blockDim.x + threadIdx.x;
    const int NW = 3 * 768 * 384;
    const int NV = 3 * 24576;
    if (idx < NW) {
        int q = idx / (768 * 384);
        int r2 = idx % (768 * 384);
        int k = r2 / 384, n = r2 % 384;
        const float* P = (q == 0) ? Pq : ((q == 1) ? Pk : Pv);
        W[idx] = P[((size_t)(n >> 5) * 768 + k) * 32 + (n & 31)];
    } else if (idx < NW + NV) {
        int e = idx - NW;
        int q = e / 24576, r = e % 24576;
        const float* S = (q == 0) ? Vq : ((q == 1) ? Vk : Vv);
        VW[e] = S[r];
    } else if (idx < NW + NV + 3 * 768) {
        int e = idx - NW - NV;
        int q = e / 768, r = e % 768;
        const float* S = (q == 0) ? bq : ((q == 1) ? bk : bv);
        VB[e] = S[r];
    }
}

// ---------------- LayerNorm (single pass) ----------------
__global__ void ln_kernel(const float* __restrict__ in, float* __restrict__ out,
                          const float* __restrict__ g, const float* __restrict__ bb) {
    __shared__ float rs_[8], rss_[8];
    const float* xr = in + (size_t)blockIdx.x * 768;
    float* yr = out + (size_t)blockIdx.x * 768;
    const int tid = threadIdx.x;
    float v[3];
    float s = 0.0f, ss = 0.0f;
#pragma unroll
    for (int i = 0; i < 3; i++) {
        v[i] = xr[tid + i * 256];
        s += v[i];
        ss += v[i] * v[i];
    }
#pragma unroll
    for (int o = 16; o; o >>= 1) {
        s += __shfl_xor_sync(0xffffffffu, s, o);
        ss += __shfl_xor_sync(0xffffffffu, ss, o);
    }
    if ((tid & 31) == 0) { rs_[tid >> 5] = s; rss_[tid >> 5] = ss; }
    __syncthreads();
    s = 0.0f; ss = 0.0f;
#pragma unroll
    for (int w = 0; w < 8; w++) { s += rs_[w]; ss += rss_[w]; }
    const float mu = s * (1.0f / 768.0f);
    const float var = fmaxf(ss * (1.0f / 768.0f) - mu * mu, 0.0f);
    const float rstd = rsqrtf(var + 1e-12f);
#pragma unroll
    for (int i = 0; i < 3; i++) {
        int c = tid + i * 256;
        yr[c] = (v[i] - mu) * rstd * g[c] + bb[c];
    }
}

extern "C" void kernel_launch(void* const* d_in, const int* in_sizes, int n_in,
                              void* d_out, int out_size) {
    const float* x    = (const float*)d_in[0];
    const float* mask = (const float*)d_in[1];
    const float* Pq   = (const float*)d_in[2];
    const float* Vq   = (const float*)d_in[3];
    const float* bq   = (const float*)d_in[4];
    const float* Pk   = (const float*)d_in[5];
    const float* Vk   = (const float*)d_in[6];
    const float* bk   = (const float*)d_in[7];
    const float* Pv   = (const float*)d_in[8];
    const float* Vv   = (const float*)d_in[9];
    const float* bv   = (const float*)d_in[10];
    const float* Uo   = (const float*)d_in[11];
    const float* Vo   = (const float*)d_in[12];
    const float* bo   = (const float*)d_in[13];
    const float* U1   = (const float*)d_in[14];
    const float* V1   = (const float*)d_in[15];
    const float* b1   = (const float*)d_in[16];
    const float* U2   = (const float*)d_in[17];
    const float* V2   = (const float*)d_in[18];
    const float* b2   = (const float*)d_in[19];
    const float* ln1g = (const float*)d_in[20];
    const float* ln1b = (const float*)d_in[21];
    const float* ln2g = (const float*)d_in[22];
    const float* ln2b = (const float*)d_in[23];
    float* out = (float*)d_out;

    float *w_p, *vw_p, *vb_p, *t_p, *at2_p, *tmp_p, *x1_p, *y_p, *hdn_p;
    __half* qkv_p;
    cudaGetSymbolAddress((void**)&w_p,   g_w);
    cudaGetSymbolAddress((void**)&vw_p,  g_vw);
    cudaGetSymbolAddress((void**)&vb_p,  g_vb);
    cudaGetSymbolAddress((void**)&t_p,   g_t);
    cudaGetSymbolAddress((void**)&qkv_p, g_qkvh);
    cudaGetSymbolAddress((void**)&at2_p, g_at2);
    cudaGetSymbolAddress((void**)&tmp_p, g_tmp);
    cudaGetSymbolAddress((void**)&x1_p,  g_x1);
    cudaGetSymbolAddress((void**)&y_p,   g_y);
    cudaGetSymbolAddress((void**)&hdn_p, g_hdn);

    const long long T_QKV = 3145728, Q_QKV = 6291456, W_SZ = 294912;
    const long long PART = 3145728;
    const int FL_SMEM = 77824;
    cudaFuncSetAttribute(flash_attn, cudaFuncAttributeMaxDynamicSharedMemorySize, FL_SMEM);

    // 0) pack weights
    const int NPACK = 3 * 768 * 384 + 3 * 24576 + 3 * 768;
    pack_all<<<(NPACK + 255) / 256, 256>>>(Pq, Pk, Pv, Vq, Vk, Vv, bq, bk, bv,
                                           w_p, vw_p, vb_p);

    // 1) t = x @ W   (z over qkv)
    gemm_mma<128, 1><<<dim3(3, 64, 3), 256>>>(
        x, w_p, t_p, nullptr, nullptr,
        768, 384, 384, 0, 768, 1.0f, 0, 1, 1, 0LL,
        0LL, 0LL, 0LL, W_SZ, 0LL, 0LL, T_QKV, 0LL, 0LL, 0LL, 0LL, 0LL);

    // 2) Q/K/V = t @ Vqkv + b -> fp16. z=(q,b,h), K=32
    gemm_mma<64, 1><<<dim3(1, 8, 288), 256>>>(
        t_p, vw_p, qkv_p, vb_p, nullptr,
        384, 64, 64, 0, 32, 1.0f, 3, 8, 12, 0LL,
        T_QKV, 393216LL, 32LL,
        24576LL, 0LL, 2048LL,
        Q_QKV, 786432LL, 65536LL,
        768LL, 0LL, 64LL);

    // 3) fused attention -> at2
    flash_attn<<<dim3(8, 96), 256, FL_SMEM>>>(
        qkv_p, qkv_p + Q_QKV, qkv_p + 2 * Q_QKV, mask, at2_p);

    // 4) ao partials = attn @ Uo  (split-K x2)
    gemm_mma<128, 1><<<dim3(3, 64, 2), 256>>>(
        at2_p, Uo, tmp_p, nullptr, nullptr,
        768, 384, 384, 0, 384, 1.0f, 0, 1, 2, 0LL,
        0LL, 0LL, 384LL, 0LL, 0LL, 147456LL, 0LL, 0LL, PART, 0, 0, 0);

    // 5) x1pre = sum(ao) @ Vo + bo + x
    gemm_mma<128, 2><<<dim3(6, 64, 1), 256>>>(
        tmp_p, Vo, y_p, bo, x,
        384, 768, 768, 768, 384, 1.0f, 0, 1, 1, PART,
        0, 0, 0, 0, 0, 0, 0, 0, 0, 0, 0, 0);

    // 6) LN1
    ln_kernel<<<8192, 256>>>(y_p, x1_p, ln1g, ln1b);

    // 7) mid partials = x1 @ U1  (split-K x2)
    gemm_mma<128, 1><<<dim3(3, 64, 2), 256>>>(
        x1_p, U1, tmp_p, nullptr, nullptr,
        768, 384, 384, 0, 384, 1.0f, 0, 1, 2, 0LL,
        0LL, 0LL, 384LL, 0LL, 0LL, 147456LL, 0LL, 0LL, PART, 0, 0, 0);

    // 8) hdn = gelu(sum(mid) @ V1 + b1)
    gemm_mma<128, 2><<<dim3(24, 64, 1), 256>>>(
        tmp_p, V1, hdn_p, b1, nullptr,
        384, 3072, 3072, 0, 384, 1.0f, 1, 1, 1, PART,
        0, 0, 0, 0, 0, 0, 0, 0, 0, 0, 0, 0);

    // 9) h2 partials = hdn @ U2  (split-K x4)
    gemm_mma<128, 1><<<dim3(3, 64, 4), 256>>>(
        hdn_p, U2, tmp_p, nullptr, nullptr,
        3072, 384, 384, 0, 768, 1.0f, 0, 1, 4, 0LL,
        0LL, 0LL, 768LL, 0LL, 0LL, 294912LL, 0LL, 0LL, PART, 0, 0, 0);

    // 10) ypre = sum(h2) @ V2 + b2 + x1
    gemm_mma<128, 4><<<dim3(6, 64, 1), 256>>>(
        tmp_p, V2, y_p, b2, x1_p,
        384, 768, 768, 768, 384, 1.0f, 0, 1, 1, PART,
        0, 0, 0, 0, 0, 0, 0, 0, 0, 0, 0, 0);

    // 11) LN2 -> out
    ln_kernel<<<8192, 256>>>(y_p, out, ln2g, ln2b);
}

// round 12
// speedup vs baseline: 6.7071x; 1.0191x over previous
#include <cuda_runtime.h>
#include <cuda_fp16.h>
#include <math.h>
#include <stdint.h>

// B=8, M=1024, DM=768, H=12, DH=64, R=32, RFF=384, DFF=3072, RWO=384

// ---------------- scratch (device globals) ----------------
__device__ float  g_w   [3ull * 768 * 384];
__device__ float  g_vw  [3ull * 12 * 32 * 64];
__device__ float  g_vb  [3ull * 12 * 64];
__device__ float  g_t   [3ull * 8 * 1024 * 384];
__device__ __half g_qkvh[3ull * 8 * 12 * 1024 * 64];
__device__ float  g_at2 [8ull * 1024 * 768];
__device__ float  g_tmp [4ull * 8192 * 384];
__device__ float  g_x1  [8192ull * 768];
__device__ float  g_y   [8192ull * 768];
__device__ __half g_hdnh[8192ull * 3072];

__device__ __forceinline__ float gelu_exact(float v) {
    return 0.5f * v * (1.0f + erff(v * 0.70710678118654752440f));
}
__device__ __forceinline__ uint32_t h2u(float lo, float hi) {
    __half2 h = __halves2half2(__float2half_rn(lo), __float2half_rn(hi));
    return *(uint32_t*)&h;
}
__device__ __forceinline__ void mma16b(float* c, const uint32_t* a, uint32_t b0, uint32_t b1) {
    asm volatile(
        "mma.sync.aligned.m16n8k16.row.col.f32.f16.f16.f32 "
        "{%0,%1,%2,%3}, {%4,%5,%6,%7}, {%8,%9}, {%0,%1,%2,%3};"
        : "+f"(c[0]), "+f"(c[1]), "+f"(c[2]), "+f"(c[3])
        : "r"(a[0]), "r"(a[1]), "r"(a[2]), "r"(a[3]), "r"(b0), "r"(b1));
}
__device__ __forceinline__ void ldsm4(uint32_t* r, uint32_t addr) {
    asm volatile("ldmatrix.sync.aligned.m8n8.x4.shared.b16 {%0,%1,%2,%3}, [%4];"
                 : "=r"(r[0]), "=r"(r[1]), "=r"(r[2]), "=r"(r[3]) : "r"(addr));
}
__device__ __forceinline__ void ldsm4t(uint32_t* r, uint32_t addr) {
    asm volatile("ldmatrix.sync.aligned.m8n8.x4.trans.shared.b16 {%0,%1,%2,%3}, [%4];"
                 : "=r"(r[0]), "=r"(r[1]), "=r"(r[2]), "=r"(r[3]) : "r"(addr));
}
__device__ __forceinline__ uint32_t smem_u32(const void* p) {
    uint32_t a;
    asm("{ .reg .u64 t; cvta.to.shared.u64 t, %1; cvt.u32.u64 %0, t; }" : "=r"(a) : "l"(p));
    return a;
}
#define CPA16(dst, src) \
    asm volatile("cp.async.cg.shared.global [%0], [%1], 16;" ::"r"(dst), "l"(src) : "memory")
#define CPA_COMMIT() asm volatile("cp.async.commit_group;" ::: "memory")

// ================= fused flash attention (fp16 mma + ldmatrix, 128 threads) =================
// 4 warps x 16 q-rows = 64 q-rows/CTA; grid (16 q-tiles, 96 bh); 2 CTAs/SM.
// K/V tiles: [128 kv][64 d] fp16, row stride 144 B.
__global__ void __launch_bounds__(128, 2)
flash_attn(const __half* __restrict__ Qg, const __half* __restrict__ Kg,
           const __half* __restrict__ Vg, const float* __restrict__ maskg,
           float* __restrict__ Og) {
    extern __shared__ uint32_t smu[];
    float* Ms = (float*)(smu + 18432);
    const uint32_t sbase = smem_u32(smu);

    const int bh = blockIdx.y;
    const int b = bh / 12, h = bh % 12;
    const __half* Q = Qg + (size_t)bh * 65536;
    const __half* K = Kg + (size_t)bh * 65536;
    const __half* V = Vg + (size_t)bh * 65536;
    const float* mask = maskg + b * 1024;
    float* O = Og + (size_t)b * 1024 * 768 + h * 64;

    const int tid = threadIdx.x;
    const int wid = tid >> 5, lane = tid & 31;
    const int qr = lane >> 2, qc = lane & 3;
    const int m0row = blockIdx.x * 64 + wid * 16;

    // K (non-trans) lane map: matrices {n0-7,klo},{n0-7,khi},{n8-15,klo},{n8-15,khi}
    const int nrow = (lane & 7) | ((lane >> 4) << 3);
    const int koff8 = ((lane >> 3) & 1) << 3;
    // V (trans) lane map
    const int krow = (lane & 7) + ((lane >> 3) & 1) * 8;
    const int noff8 = ((lane >> 4) << 3);

    auto kv_load = [&](int c, int buf) {
        uint32_t dstK = sbase + buf * 36864;
        uint32_t dstV = dstK + 18432;
        const __half* Kc = K + ((size_t)(c << 7)) * 64;
        const __half* Vc = V + ((size_t)(c << 7)) * 64;
#pragma unroll
        for (int j = 0; j < 8; j++) {
            int idx = tid + (j << 7);
            int kv = idx >> 3, c4 = idx & 7;
            CPA16(dstK + kv * 144 + c4 * 16, Kc + (size_t)kv * 64 + c4 * 8);
            CPA16(dstV + kv * 144 + c4 * 16, Vc + (size_t)kv * 64 + c4 * 8);
        }
    };
#pragma unroll
    for (int j = 0; j < 2; j++) {
        int idx = tid + (j << 7);
        CPA16(smem_u32(Ms + idx * 4), mask + idx * 4);
    }
    kv_load(0, 0);
    CPA_COMMIT();
    kv_load(1, 1);
    CPA_COMMIT();

    // ---- Q fragments, scaled by 1/8 (exact) ----
    uint32_t qf[4][4];
    {
        const __half2 s2 = __float2half2_rn(0.125f);
        const __half* Qr0 = Q + (size_t)(m0row + qr) * 64;
        const __half* Qr1 = Q + (size_t)(m0row + qr + 8) * 64;
#pragma unroll
        for (int kd = 0; kd < 4; kd++) {
            __half2 a0 = __hmul2(*(const __half2*)(Qr0 + kd * 16 + 2 * qc), s2);
            __half2 a1 = __hmul2(*(const __half2*)(Qr1 + kd * 16 + 2 * qc), s2);
            __half2 a2 = __hmul2(*(const __half2*)(Qr0 + kd * 16 + 2 * qc + 8), s2);
            __half2 a3 = __hmul2(*(const __half2*)(Qr1 + kd * 16 + 2 * qc + 8), s2);
            qf[kd][0] = *(uint32_t*)&a0;
            qf[kd][1] = *(uint32_t*)&a1;
            qf[kd][2] = *(uint32_t*)&a2;
            qf[kd][3] = *(uint32_t*)&a3;
        }
    }

    float oacc[8][4];
#pragma unroll
    for (int i = 0; i < 8; i++)
#pragma unroll
        for (int j = 0; j < 4; j++) oacc[i][j] = 0.0f;
    float mrow0 = -INFINITY, mrow1 = -INFINITY, lrow0 = 0.0f, lrow1 = 0.0f;

    for (int c = 0; c < 8; c++) {
        const int buf = c & 1;
        const uint32_t ksb = sbase + buf * 36864;
        const uint32_t vsb = ksb + 18432;
        const int kvb = c << 7;

        if (c < 7) asm volatile("cp.async.wait_group 1;" ::: "memory");
        else       asm volatile("cp.async.wait_group 0;" ::: "memory");
        __syncthreads();

        // ---- S = (Q/8) @ K^T ----
        float sacc[16][4];
#pragma unroll
        for (int nt = 0; nt < 16; nt++)
            sacc[nt][0] = sacc[nt][1] = sacc[nt][2] = sacc[nt][3] = 0.0f;
#pragma unroll
        for (int ntp = 0; ntp < 8; ntp++) {
            const uint32_t rowb = ksb + (uint32_t)(ntp * 16 + nrow) * 144;
#pragma unroll
            for (int kd = 0; kd < 4; kd++) {
                uint32_t bb[4];
                ldsm4(bb, rowb + (uint32_t)(kd * 16 + koff8) * 2);
                mma16b(sacc[2 * ntp], qf[kd], bb[0], bb[1]);
                mma16b(sacc[2 * ntp + 1], qf[kd], bb[2], bb[3]);
            }
        }

        // ---- online softmax ----
        float cm0 = -INFINITY, cm1 = -INFINITY;
#pragma unroll
        for (int nt = 0; nt < 16; nt++) {
            float mk0 = Ms[kvb + nt * 8 + 2 * qc], mk1 = Ms[kvb + nt * 8 + 2 * qc + 1];
            sacc[nt][0] += mk0; sacc[nt][1] += mk1;
            sacc[nt][2] += mk0; sacc[nt][3] += mk1;
            cm0 = fmaxf(cm0, fmaxf(sacc[nt][0], sacc[nt][1]));
            cm1 = fmaxf(cm1, fmaxf(sacc[nt][2], sacc[nt][3]));
        }
        cm0 = fmaxf(cm0, __shfl_xor_sync(0xffffffffu, cm0, 1));
        cm0 = fmaxf(cm0, __shfl_xor_sync(0xffffffffu, cm0, 2));
        cm1 = fmaxf(cm1, __shfl_xor_sync(0xffffffffu, cm1, 1));
        cm1 = fmaxf(cm1, __shfl_xor_sync(0xffffffffu, cm1, 2));
        const float mn0 = fmaxf(mrow0, cm0), mn1 = fmaxf(mrow1, cm1);
        const float al0 = __expf(mrow0 - mn0), al1 = __expf(mrow1 - mn1);
        mrow0 = mn0; mrow1 = mn1;
        float sum0 = 0.0f, sum1 = 0.0f;
#pragma unroll
        for (int nt = 0; nt < 16; nt++) {
            sacc[nt][0] = __expf(sacc[nt][0] - mn0);
            sacc[nt][1] = __expf(sacc[nt][1] - mn0);
            sacc[nt][2] = __expf(sacc[nt][2] - mn1);
            sacc[nt][3] = __expf(sacc[nt][3] - mn1);
            sum0 += sacc[nt][0] + sacc[nt][1];
            sum1 += sacc[nt][2] + sacc[nt][3];
        }
        sum0 += __shfl_xor_sync(0xffffffffu, sum0, 1);
        sum0 += __shfl_xor_sync(0xffffffffu, sum0, 2);
        sum1 += __shfl_xor_sync(0xffffffffu, sum1, 1);
        sum1 += __shfl_xor_sync(0xffffffffu, sum1, 2);
        lrow0 = lrow0 * al0 + sum0;
        lrow1 = lrow1 * al1 + sum1;
#pragma unroll
        for (int i = 0; i < 8; i++) {
            oacc[i][0] *= al0; oacc[i][1] *= al0;
            oacc[i][2] *= al1; oacc[i][3] *= al1;
        }

        // ---- O += P @ V ----
#pragma unroll
        for (int kt2 = 0; kt2 < 8; kt2++) {
            uint32_t af[4];
            af[0] = h2u(sacc[2 * kt2][0], sacc[2 * kt2][1]);
            af[1] = h2u(sacc[2 * kt2][2], sacc[2 * kt2][3]);
            af[2] = h2u(sacc[2 * kt2 + 1][0], sacc[2 * kt2 + 1][1]);
            af[3] = h2u(sacc[2 * kt2 + 1][2], sacc[2 * kt2 + 1][3]);
            const uint32_t rowb = vsb + (uint32_t)(kt2 * 16 + krow) * 144;
#pragma unroll
            for (int dtp = 0; dtp < 4; dtp++) {
                uint32_t bb[4];
                ldsm4t(bb, rowb + (uint32_t)(dtp * 16 + noff8) * 2);
                mma16b(oacc[2 * dtp], af, bb[0], bb[1]);
                mma16b(oacc[2 * dtp + 1], af, bb[2], bb[3]);
            }
        }
        __syncthreads();
        if (c + 2 < 8) { kv_load(c + 2, buf); CPA_COMMIT(); }
    }

    const float il0 = 1.0f / lrow0, il1 = 1.0f / lrow1;
    const int r0 = m0row + qr, r1 = m0row + qr + 8;
#pragma unroll
    for (int nt2 = 0; nt2 < 8; nt2++) {
        const int col = nt2 * 8 + 2 * qc;
        *(float2*)(O + (size_t)r0 * 768 + col) =
            make_float2(oacc[nt2][0] * il0, oacc[nt2][1] * il0);
        *(float2*)(O + (size_t)r1 * 768 + col) =
            make_float2(oacc[nt2][2] * il1, oacc[nt2][3] * il1);
    }
}

// ---------------- fp16 mma GEMM + ldmatrix ----------------
// AH=1: A is fp16 in gmem (lda/strides in halfs; NSUM must be 1).
// mode bits: 1 = gelu, 2 = fp16 output. z = (i1*D2 + i2)*D3 + i3.
template <int BN, int NSUM, int AH = 0>
__global__ void __launch_bounds__(256, 2)
gemm_mma(const float* __restrict__ A, const float* __restrict__ Bm, void* __restrict__ Cv,
         const float* __restrict__ bias, const float* __restrict__ res,
         int lda, int ldb, int ldc, int ldres, int K, float scale, int mode,
         int D2, int D3, long long sum_str,
         long long sA1, long long sA2, long long sA3,
         long long sB1, long long sB2, long long sB3,
         long long sC1, long long sC2, long long sC3,
         long long sb1, long long sb2, long long sb3) {
    constexpr int BM = 128, NT = 256, WN = BN / 4, NTILES = WN / 8, NPAIR = NTILES / 2;
    constexpr int AROW = 20;
    constexpr int BROW = BN / 2 + 4;
    constexpr int LBI = BN / 32;

    __shared__ uint32_t As32[2][BM * AROW];
    __shared__ uint32_t Bs32[2][32 * BROW];

    const int z = blockIdx.z;
    const int i1 = z / (D2 * D3);
    const int rem = z % (D2 * D3);
    const int i2 = rem / D3, i3 = rem % D3;
    const __half* Ah = (const __half*)A;
    if (AH) Ah += i1 * sA1 + i2 * sA2 + i3 * sA3;
    else A += i1 * sA1 + i2 * sA2 + i3 * sA3;
    Bm += i1 * sB1 + i2 * sB2 + i3 * sB3;
    const long long coff = i1 * sC1 + i2 * sC2 + i3 * sC3;
    const long long boff = i1 * sb1 + i2 * sb2 + i3 * sb3;

    const int x0 = blockIdx.x * BN, y0 = blockIdx.y * BM;
    const int tid = threadIdx.x;
    const int wid = tid >> 5, lane = tid & 31;
    const int wm0 = (wid >> 2) * 64;
    const int wn0 = (wid & 3) * WN;
    const int qr = lane >> 2, qc = lane & 3;

    const uint32_t aBase = smem_u32(As32);
    const uint32_t bBase = smem_u32(Bs32);
    const int arow_l = lane & 15, akoff = ((lane >> 4) << 3);
    const int bkrow = (lane & 7) + ((lane >> 3) & 1) * 8, bnoff = ((lane >> 4) << 3);

    float4 ra[4], rbv[LBI];
    uint4 rah[2];

    auto ldg = [&](int k0) {
        if (AH) {
#pragma unroll
            for (int i = 0; i < 2; i++) {
                int f = tid + i * NT;
                int m = f >> 2, kq = f & 3;
                rah[i] = *(const uint4*)(Ah + (size_t)(y0 + m) * lda + k0 + kq * 8);
            }
        } else {
#pragma unroll
            for (int i = 0; i < 4; i++) {
                int f = tid + i * NT;
                int m = f >> 3, kq = f & 7;
                const float* ap = A + (size_t)(y0 + m) * lda + k0 + kq * 4;
                float4 v = *(const float4*)ap;
#pragma unroll
                for (int s = 1; s < NSUM; s++) {
                    float4 w = *(const float4*)(ap + (size_t)s * sum_str);
                    v.x += w.x; v.y += w.y; v.z += w.z; v.w += w.w;
                }
                ra[i] = v;
            }
        }
#pragma unroll
        for (int i = 0; i < LBI; i++) {
            int f = tid + i * NT;
            int k = f / (BN / 4), nq = f % (BN / 4);
            rbv[i] = *(const float4*)(Bm + (size_t)(k0 + k) * ldb + x0 + 4 * nq);
        }
    };
    auto sts = [&](int buf) {
        if (AH) {
#pragma unroll
            for (int i = 0; i < 2; i++) {
                int f = tid + i * NT;
                int m = f >> 2, kq = f & 3;
                As32[buf][m * AROW + 4 * kq + 0] = rah[i].x;
                As32[buf][m * AROW + 4 * kq + 1] = rah[i].y;
                As32[buf][m * AROW + 4 * kq + 2] = rah[i].z;
                As32[buf][m * AROW + 4 * kq + 3] = rah[i].w;
            }
        } else {
#pragma unroll
            for (int i = 0; i < 4; i++) {
                int f = tid + i * NT;
                int m = f >> 3, kq = f & 7;
                As32[buf][m * AROW + 2 * kq] = h2u(ra[i].x, ra[i].y);
                As32[buf][m * AROW + 2 * kq + 1] = h2u(ra[i].z, ra[i].w);
            }
        }
#pragma unroll
        for (int i = 0; i < LBI; i++) {
            int f = tid + i * NT;
            int k = f / (BN / 4), nq = f % (BN / 4);
            Bs32[buf][k * BROW + 2 * nq] = h2u(rbv[i].x, rbv[i].y);
            Bs32[buf][k * BROW + 2 * nq + 1] = h2u(rbv[i].z, rbv[i].w);
        }
    };

    float acc[4][NTILES][4];
#pragma unroll
    for (int i = 0; i < 4; i++)
#pragma unroll
        for (int j = 0; j < NTILES; j++)
#pragma unroll
            for (int l = 0; l < 4; l++) acc[i][j][l] = 0.0f;

    ldg(0);
    sts(0);
    __syncthreads();
    const int nb = K >> 5;
    for (int kb = 0; kb < nb; kb++) {
        const int cur = kb & 1;
        if (kb + 1 < nb) ldg((kb + 1) << 5);
        const uint32_t aB = aBase + cur * (BM * AROW * 4);
        const uint32_t bB = bBase + cur * (32 * BROW * 4);
#pragma unroll
        for (int kk = 0; kk < 2; kk++) {
            uint32_t af[4][4], bb[NPAIR][4];
#pragma unroll
            for (int mt = 0; mt < 4; mt++)
                ldsm4(af[mt], aB + (uint32_t)(wm0 + mt * 16 + arow_l) * 80 +
                                  (uint32_t)(kk * 16 + akoff) * 2);
#pragma unroll
            for (int p = 0; p < NPAIR; p++)
                ldsm4t(bb[p], bB + (uint32_t)(kk * 16 + bkrow) * (BROW * 4) +
                                  (uint32_t)(wn0 + p * 16 + bnoff) * 2);
#pragma unroll
            for (int mt = 0; mt < 4; mt++)
#pragma unroll
                for (int p = 0; p < NPAIR; p++) {
                    mma16b(acc[mt][2 * p], af[mt], bb[p][0], bb[p][1]);
                    mma16b(acc[mt][2 * p + 1], af[mt], bb[p][2], bb[p][3]);
                }
        }
        if (kb + 1 < nb) sts(cur ^ 1);
        __syncthreads();
    }

    float* Cf = (float*)Cv + coff;
    __half* Ch = (__half*)Cv + coff;
#pragma unroll
    for (int mt = 0; mt < 4; mt++) {
#pragma unroll
        for (int nt = 0; nt < NTILES; nt++) {
            const int n = x0 + wn0 + nt * 8 + qc * 2;
#pragma unroll
            for (int half_ = 0; half_ < 2; half_++) {
                const int m = y0 + wm0 + mt * 16 + qr + half_ * 8;
                float v0 = acc[mt][nt][half_ * 2 + 0] * scale;
                float v1 = acc[mt][nt][half_ * 2 + 1] * scale;
                if (bias) { v0 += bias[boff + n]; v1 += bias[boff + n + 1]; }
                if (res) {
                    v0 += res[(size_t)m * ldres + n];
                    v1 += res[(size_t)m * ldres + n + 1];
                }
                if (mode & 1) { v0 = gelu_exact(v0); v1 = gelu_exact(v1); }
                if (mode & 2) {
                    __half2 hv = __halves2half2(__float2half_rn(v0), __float2half_rn(v1));
                    *(__half2*)(Ch + (size_t)m * ldc + n) = hv;
                } else {
                    *(float2*)(Cf + (size_t)m * ldc + n) = make_float2(v0, v1);
                }
            }
        }
    }
}

// ---------------- packing ----------------
__global__ void pack_all(const float* __restrict__ Pq, const float* __restrict__ Pk,
                         const float* __restrict__ Pv,
                         const float* __restrict__ Vq, const float* __restrict__ Vk,
                         const float* __restrict__ Vv,
                         const float* __restrict__ bq, const float* __restrict__ bk,
                         const float* __restrict__ bv,
                         float* __restrict__ W, float* __restrict__ VW,
                         float* __restrict__ VB) {
    int idx = blockIdx.x * blockDim.x + threadIdx.x;
    const int NW = 3 * 768 * 384;
    const int NV = 3 * 24576;
    if (idx < NW) {
        int q = idx / (768 * 384);
        int r2 = idx % (768 * 384);
        int k = r2 / 384, n = r2 % 384;
        const float* P = (q == 0) ? Pq : ((q == 1) ? Pk : Pv);
        W[idx] = P[((size_t)(n >> 5) * 768 + k) * 32 + (n & 31)];
    } else if (idx < NW + NV) {
        int e = idx - NW;
        int q = e / 24576, r = e % 24576;
        const float* S = (q == 0) ? Vq : ((q == 1) ? Vk : Vv);
        VW[e] = S[r];
    } else if (idx < NW + NV + 3 * 768) {
        int e = idx - NW - NV;
        int q = e / 768, r = e % 768;
        const float* S = (q == 0) ? bq : ((q == 1) ? bk : bv);
        VB[e] = S[r];
    }
}

// ---------------- LayerNorm (single pass) ----------------
__global__ void ln_kernel(const float* __restrict__ in, float* __restrict__ out,
                          const float* __restrict__ g, const float* __restrict__ bb) {
    __shared__ float rs_[8], rss_[8];
    const float* xr = in + (size_t)blockIdx.x * 768;
    float* yr = out + (size_t)blockIdx.x * 768;
    const int tid = threadIdx.x;
    float v[3];
    float s = 0.0f, ss = 0.0f;
#pragma unroll
    for (int i = 0; i < 3; i++) {
        v[i] = xr[tid + i * 256];
        s += v[i];
        ss += v[i] * v[i];
    }
#pragma unroll
    for (int o = 16; o; o >>= 1) {
        s += __shfl_xor_sync(0xffffffffu, s, o);
        ss += __shfl_xor_sync(0xffffffffu, ss, o);
    }
    if ((tid & 31) == 0) { rs_[tid >> 5] = s; rss_[tid >> 5] = ss; }
    __syncthreads();
    s = 0.0f; ss = 0.0f;
#pragma unroll
    for (int w = 0; w < 8; w++) { s += rs_[w]; ss += rss_[w]; }
    const float mu = s * (1.0f / 768.0f);
    const float var = fmaxf(ss * (1.0f / 768.0f) - mu * mu, 0.0f);
    const float rstd = rsqrtf(var + 1e-12f);
#pragma unroll
    for (int i = 0; i < 3; i++) {
        int c = tid + i * 256;
        yr[c] = (v[i] - mu) * rstd * g[c] + bb[c];
    }
}

extern "C" void kernel_launch(void* const* d_in, const int* in_sizes, int n_in,
                              void* d_out, int out_size) {
    const float* x    = (const float*)d_in[0];
    const float* mask = (const float*)d_in[1];
    const float* Pq   = (const float*)d_in[2];
    const float* Vq   = (const float*)d_in[3];
    const float* bq   = (const float*)d_in[4];
    const float* Pk   = (const float*)d_in[5];
    const float* Vk   = (const float*)d_in[6];
    const float* bk   = (const float*)d_in[7];
    const float* Pv   = (const float*)d_in[8];
    const float* Vv   = (const float*)d_in[9];
    const float* bv   = (const float*)d_in[10];
    const float* Uo   = (const float*)d_in[11];
    const float* Vo   = (const float*)d_in[12];
    const float* bo   = (const float*)d_in[13];
    const float* U1   = (const float*)d_in[14];
    const float* V1   = (const float*)d_in[15];
    const float* b1   = (const float*)d_in[16];
    const float* U2   = (const float*)d_in[17];
    const float* V2   = (const float*)d_in[18];
    const float* b2   = (const float*)d_in[19];
    const float* ln1g = (const float*)d_in[20];
    const float* ln1b = (const float*)d_in[21];
    const float* ln2g = (const float*)d_in[22];
    const float* ln2b = (const float*)d_in[23];
    float* out = (float*)d_out;

    float *w_p, *vw_p, *vb_p, *t_p, *at2_p, *tmp_p, *x1_p, *y_p;
    __half *qkv_p, *hdnh_p;
    cudaGetSymbolAddress((void**)&w_p,    g_w);
    cudaGetSymbolAddress((void**)&vw_p,   g_vw);
    cudaGetSymbolAddress((void**)&vb_p,   g_vb);
    cudaGetSymbolAddress((void**)&t_p,    g_t);
    cudaGetSymbolAddress((void**)&qkv_p,  g_qkvh);
    cudaGetSymbolAddress((void**)&at2_p,  g_at2);
    cudaGetSymbolAddress((void**)&tmp_p,  g_tmp);
    cudaGetSymbolAddress((void**)&x1_p,   g_x1);
    cudaGetSymbolAddress((void**)&y_p,    g_y);
    cudaGetSymbolAddress((void**)&hdnh_p, g_hdnh);

    const long long T_QKV = 3145728, Q_QKV = 6291456, W_SZ = 294912;
    const long long PART = 3145728;
    const int FL_SMEM = 77824;
    cudaFuncSetAttribute(flash_attn, cudaFuncAttributeMaxDynamicSharedMemorySize, FL_SMEM);

    // 0) pack weights
    const int NPACK = 3 * 768 * 384 + 3 * 24576 + 3 * 768;
    pack_all<<<(NPACK + 255) / 256, 256>>>(Pq, Pk, Pv, Vq, Vk, Vv, bq, bk, bv,
                                           w_p, vw_p, vb_p);

    // 1) t = x @ W   (z over qkv)
    gemm_mma<128, 1><<<dim3(3, 64, 3), 256>>>(
        x, w_p, t_p, nullptr, nullptr,
        768, 384, 384, 0, 768, 1.0f, 0, 1, 1, 0LL,
        0LL, 0LL, 0LL, W_SZ, 0LL, 0LL, T_QKV, 0LL, 0LL, 0LL, 0LL, 0LL);

    // 2) Q/K/V = t @ Vqkv + b -> fp16. z=(q,b,h), K=32
    gemm_mma<64, 1><<<dim3(1, 8, 288), 256>>>(
        t_p, vw_p, qkv_p, vb_p, nullptr,
        384, 64, 64, 0, 32, 1.0f, 2, 8, 12, 0LL,
        T_QKV, 393216LL, 32LL,
        24576LL, 0LL, 2048LL,
        Q_QKV, 786432LL, 65536LL,
        768LL, 0LL, 64LL);

    // 3) fused attention -> at2 (64-row q-tiles, 2 CTAs/SM)
    flash_attn<<<dim3(16, 96), 128, FL_SMEM>>>(
        qkv_p, qkv_p + Q_QKV, qkv_p + 2 * Q_QKV, mask, at2_p);

    // 4) ao partials = attn @ Uo  (split-K x2)
    gemm_mma<128, 1><<<dim3(3, 64, 2), 256>>>(
        at2_p, Uo, tmp_p, nullptr, nullptr,
        768, 384, 384, 0, 384, 1.0f, 0, 1, 2, 0LL,
        0LL, 0LL, 384LL, 0LL, 0LL, 147456LL, 0LL, 0LL, PART, 0, 0, 0);

    // 5) x1pre = sum(ao) @ Vo + bo + x
    gemm_mma<128, 2><<<dim3(6, 64, 1), 256>>>(
        tmp_p, Vo, y_p, bo, x,
        384, 768, 768, 768, 384, 1.0f, 0, 1, 1, PART,
        0, 0, 0, 0, 0, 0, 0, 0, 0, 0, 0, 0);

    // 6) LN1
    ln_kernel<<<8192, 256>>>(y_p, x1_p, ln1g, ln1b);

    // 7) mid partials = x1 @ U1  (split-K x2)
    gemm_mma<128, 1><<<dim3(3, 64, 2), 256>>>(
        x1_p, U1, tmp_p, nullptr, nullptr,
        768, 384, 384, 0, 384, 1.0f, 0, 1, 2, 0LL,
        0LL, 0LL, 384LL, 0LL, 0LL, 147456LL, 0LL, 0LL, PART, 0, 0, 0);

    // 8) hdn = gelu(sum(mid) @ V1 + b1) -> fp16
    gemm_mma<128, 2><<<dim3(24, 64, 1), 256>>>(
        tmp_p, V1, hdnh_p, b1, nullptr,
        384, 3072, 3072, 0, 384, 1.0f, 3, 1, 1, PART,
        0, 0, 0, 0, 0, 0, 0, 0, 0, 0, 0, 0);

    // 9) h2 partials = hdn(fp16) @ U2  (split-K x4; A strides in halfs)
    gemm_mma<128, 1, 1><<<dim3(3, 64, 4), 256>>>(
        (const float*)hdnh_p, U2, tmp_p, nullptr, nullptr,
        3072, 384, 384, 0, 768, 1.0f, 0, 1, 4, 0LL,
        0LL, 0LL, 768LL, 0LL, 0LL, 294912LL, 0LL, 0LL, PART, 0, 0, 0);

    // 10) ypre = sum(h2) @ V2 + b2 + x1
    gemm_mma<128, 4><<<dim3(6, 64, 1), 256>>>(
        tmp_p, V2, y_p, b2, x1_p,
        384, 768, 768, 768, 384, 1.0f, 0, 1, 1, PART,
        0, 0, 0, 0, 0, 0, 0, 0, 0, 0, 0, 0);

    // 11) LN2 -> out
    ln_kernel<<<8192, 256>>>(y_p, out, ln2g, ln2b);
}

// round 13
// speedup vs baseline: 7.3217x; 1.0916x over previous
#include <cuda_runtime.h>
#include <cuda_fp16.h>
#include <math.h>
#include <stdint.h>

// B=8, M=1024, DM=768, H=12, DH=64, R=32, RFF=384, DFF=3072, RWO=384

// ---------------- scratch (device globals) ----------------
__device__ __half g_wh  [4497408];               // all fp16 weights (see offsets)
__device__ float  g_vb  [3ull * 12 * 64];
__device__ float  g_t   [3ull * 8 * 1024 * 384];
__device__ __half g_qkvh[3ull * 8 * 12 * 1024 * 64];
__device__ float  g_at2 [8ull * 1024 * 768];
__device__ float  g_tmp [4ull * 8192 * 384];
__device__ float  g_x1  [8192ull * 768];
__device__ float  g_y   [8192ull * 768];
__device__ __half g_hdnh[8192ull * 3072];

#define LOG2E 1.44269504088896340736f

__device__ __forceinline__ float gelu_exact(float v) {
    return 0.5f * v * (1.0f + erff(v * 0.70710678118654752440f));
}
__device__ __forceinline__ uint32_t h2u(float lo, float hi) {
    __half2 h = __halves2half2(__float2half_rn(lo), __float2half_rn(hi));
    return *(uint32_t*)&h;
}
// pack (lo,hi) to half2 then 2^x elementwise
__device__ __forceinline__ uint32_t ex2h2(float lo, float hi) {
    uint32_t p;
    asm("cvt.rn.f16x2.f32 %0, %2, %1;" : "=r"(p) : "f"(lo), "f"(hi));
    asm("ex2.approx.f16x2 %0, %0;" : "+r"(p));
    return p;
}
__device__ __forceinline__ float ex2f(float x) {
    float r;
    asm("ex2.approx.f32 %0, %1;" : "=f"(r) : "f"(x));
    return r;
}
__device__ __forceinline__ void mma16b(float* c, const uint32_t* a, uint32_t b0, uint32_t b1) {
    asm volatile(
        "mma.sync.aligned.m16n8k16.row.col.f32.f16.f16.f32 "
        "{%0,%1,%2,%3}, {%4,%5,%6,%7}, {%8,%9}, {%0,%1,%2,%3};"
        : "+f"(c[0]), "+f"(c[1]), "+f"(c[2]), "+f"(c[3])
        : "r"(a[0]), "r"(a[1]), "r"(a[2]), "r"(a[3]), "r"(b0), "r"(b1));
}
__device__ __forceinline__ void ldsm4(uint32_t* r, uint32_t addr) {
    asm volatile("ldmatrix.sync.aligned.m8n8.x4.shared.b16 {%0,%1,%2,%3}, [%4];"
                 : "=r"(r[0]), "=r"(r[1]), "=r"(r[2]), "=r"(r[3]) : "r"(addr));
}
__device__ __forceinline__ void ldsm4t(uint32_t* r, uint32_t addr) {
    asm volatile("ldmatrix.sync.aligned.m8n8.x4.trans.shared.b16 {%0,%1,%2,%3}, [%4];"
                 : "=r"(r[0]), "=r"(r[1]), "=r"(r[2]), "=r"(r[3]) : "r"(addr));
}
__device__ __forceinline__ uint32_t smem_u32(const void* p) {
    uint32_t a;
    asm("{ .reg .u64 t; cvta.to.shared.u64 t, %1; cvt.u32.u64 %0, t; }" : "=r"(a) : "l"(p));
    return a;
}
#define CPA16(dst, src) \
    asm volatile("cp.async.cg.shared.global [%0], [%1], 16;" ::"r"(dst), "l"(src) : "memory")
#define CPA_COMMIT() asm volatile("cp.async.commit_group;" ::: "memory")

// ================= fused flash attention (log2-domain softmax, f16x2 ex2) =================
// 4 warps x 16 q-rows; grid (16, 96); 2 CTAs/SM. K/V tiles [128][64] fp16, stride 144 B.
__global__ void __launch_bounds__(128, 2)
flash_attn(const __half* __restrict__ Qg, const __half* __restrict__ Kg,
           const __half* __restrict__ Vg, const float* __restrict__ maskg,
           float* __restrict__ Og) {
    extern __shared__ uint32_t smu[];
    float* Ms = (float*)(smu + 18432);
    const uint32_t sbase = smem_u32(smu);

    const int bh = blockIdx.y;
    const int b = bh / 12, h = bh % 12;
    const __half* Q = Qg + (size_t)bh * 65536;
    const __half* K = Kg + (size_t)bh * 65536;
    const __half* V = Vg + (size_t)bh * 65536;
    const float* mask = maskg + b * 1024;
    float* O = Og + (size_t)b * 1024 * 768 + h * 64;

    const int tid = threadIdx.x;
    const int wid = tid >> 5, lane = tid & 31;
    const int qr = lane >> 2, qc = lane & 3;
    const int m0row = blockIdx.x * 64 + wid * 16;

    const int nrow = (lane & 7) | ((lane >> 4) << 3);
    const int koff8 = ((lane >> 3) & 1) << 3;
    const int krow = (lane & 7) + ((lane >> 3) & 1) * 8;
    const int noff8 = ((lane >> 4) << 3);
    const uint32_t ONE2 = 0x3C003C00u;

    auto kv_load = [&](int c, int buf) {
        uint32_t dstK = sbase + buf * 36864;
        uint32_t dstV = dstK + 18432;
        const __half* Kc = K + ((size_t)(c << 7)) * 64;
        const __half* Vc = V + ((size_t)(c << 7)) * 64;
#pragma unroll
        for (int j = 0; j < 8; j++) {
            int idx = tid + (j << 7);
            int kv = idx >> 3, c4 = idx & 7;
            CPA16(dstK + kv * 144 + c4 * 16, Kc + (size_t)kv * 64 + c4 * 8);
            CPA16(dstV + kv * 144 + c4 * 16, Vc + (size_t)kv * 64 + c4 * 8);
        }
    };
#pragma unroll
    for (int j = 0; j < 2; j++) {
        int idx = tid + (j << 7);
        CPA16(smem_u32(Ms + idx * 4), mask + idx * 4);
    }
    kv_load(0, 0);
    CPA_COMMIT();
    kv_load(1, 1);
    CPA_COMMIT();

    // ---- Q fragments, scaled by log2e/8 (fp32 multiply, rn to fp16) ----
    uint32_t qf[4][4];
    {
        const float qs = 0.125f * LOG2E;
        const __half* Qr0 = Q + (size_t)(m0row + qr) * 64;
        const __half* Qr1 = Q + (size_t)(m0row + qr + 8) * 64;
#pragma unroll
        for (int kd = 0; kd < 4; kd++) {
            float2 t0 = __half22float2(*(const __half2*)(Qr0 + kd * 16 + 2 * qc));
            float2 t1 = __half22float2(*(const __half2*)(Qr1 + kd * 16 + 2 * qc));
            float2 t2 = __half22float2(*(const __half2*)(Qr0 + kd * 16 + 2 * qc + 8));
            float2 t3 = __half22float2(*(const __half2*)(Qr1 + kd * 16 + 2 * qc + 8));
            qf[kd][0] = h2u(t0.x * qs, t0.y * qs);
            qf[kd][1] = h2u(t1.x * qs, t1.y * qs);
            qf[kd][2] = h2u(t2.x * qs, t2.y * qs);
            qf[kd][3] = h2u(t3.x * qs, t3.y * qs);
        }
    }

    float oacc[8][4];
#pragma unroll
    for (int i = 0; i < 8; i++)
#pragma unroll
        for (int j = 0; j < 4; j++) oacc[i][j] = 0.0f;
    float lacc[4] = {0.0f, 0.0f, 0.0f, 0.0f};
    float mrow0 = -INFINITY, mrow1 = -INFINITY;

    for (int c = 0; c < 8; c++) {
        const int buf = c & 1;
        const uint32_t ksb = sbase + buf * 36864;
        const uint32_t vsb = ksb + 18432;
        const int kvb = c << 7;

        if (c < 7) asm volatile("cp.async.wait_group 1;" ::: "memory");
        else       asm volatile("cp.async.wait_group 0;" ::: "memory");
        __syncthreads();

        // ---- S (log2 domain) = (Q*log2e/8) @ K^T ----
        float sacc[16][4];
#pragma unroll
        for (int nt = 0; nt < 16; nt++)
            sacc[nt][0] = sacc[nt][1] = sacc[nt][2] = sacc[nt][3] = 0.0f;
#pragma unroll
        for (int ntp = 0; ntp < 8; ntp++) {
            const uint32_t rowb = ksb + (uint32_t)(ntp * 16 + nrow) * 144;
#pragma unroll
            for (int kd = 0; kd < 4; kd++) {
                uint32_t bb[4];
                ldsm4(bb, rowb + (uint32_t)(kd * 16 + koff8) * 2);
                mma16b(sacc[2 * ntp], qf[kd], bb[0], bb[1]);
                mma16b(sacc[2 * ntp + 1], qf[kd], bb[2], bb[3]);
            }
        }

        // ---- add mask (log2-scaled), row max ----
        float cm0 = -INFINITY, cm1 = -INFINITY;
#pragma unroll
        for (int nt = 0; nt < 16; nt++) {
            float mk0 = Ms[kvb + nt * 8 + 2 * qc] * LOG2E;
            float mk1 = Ms[kvb + nt * 8 + 2 * qc + 1] * LOG2E;
            sacc[nt][0] += mk0; sacc[nt][1] += mk1;
            sacc[nt][2] += mk0; sacc[nt][3] += mk1;
            cm0 = fmaxf(cm0, fmaxf(sacc[nt][0], sacc[nt][1]));
            cm1 = fmaxf(cm1, fmaxf(sacc[nt][2], sacc[nt][3]));
        }
        cm0 = fmaxf(cm0, __shfl_xor_sync(0xffffffffu, cm0, 1));
        cm0 = fmaxf(cm0, __shfl_xor_sync(0xffffffffu, cm0, 2));
        cm1 = fmaxf(cm1, __shfl_xor_sync(0xffffffffu, cm1, 1));
        cm1 = fmaxf(cm1, __shfl_xor_sync(0xffffffffu, cm1, 2));
        const float mn0 = fmaxf(mrow0, cm0), mn1 = fmaxf(mrow1, cm1);
        const float al0 = ex2f(mrow0 - mn0), al1 = ex2f(mrow1 - mn1);
        mrow0 = mn0; mrow1 = mn1;
#pragma unroll
        for (int i = 0; i < 8; i++) {
            oacc[i][0] *= al0; oacc[i][1] *= al0;
            oacc[i][2] *= al1; oacc[i][3] *= al1;
        }
        lacc[0] *= al0; lacc[1] *= al0; lacc[2] *= al1; lacc[3] *= al1;

        // ---- P = 2^(s-mn) as fp16 pairs; O += P@V; l += P@1 ----
#pragma unroll
        for (int kt2 = 0; kt2 < 8; kt2++) {
            uint32_t af[4];
            af[0] = ex2h2(sacc[2 * kt2][0] - mn0, sacc[2 * kt2][1] - mn0);
            af[1] = ex2h2(sacc[2 * kt2][2] - mn1, sacc[2 * kt2][3] - mn1);
            af[2] = ex2h2(sacc[2 * kt2 + 1][0] - mn0, sacc[2 * kt2 + 1][1] - mn0);
            af[3] = ex2h2(sacc[2 * kt2 + 1][2] - mn1, sacc[2 * kt2 + 1][3] - mn1);
            mma16b(lacc, af, ONE2, ONE2);
            const uint32_t rowb = vsb + (uint32_t)(kt2 * 16 + krow) * 144;
#pragma unroll
            for (int dtp = 0; dtp < 4; dtp++) {
                uint32_t bb[4];
                ldsm4t(bb, rowb + (uint32_t)(dtp * 16 + noff8) * 2);
                mma16b(oacc[2 * dtp], af, bb[0], bb[1]);
                mma16b(oacc[2 * dtp + 1], af, bb[2], bb[3]);
            }
        }
        __syncthreads();
        if (c + 2 < 8) { kv_load(c + 2, buf); CPA_COMMIT(); }
    }

    const float il0 = 1.0f / lacc[0], il1 = 1.0f / lacc[2];
    const int r0 = m0row + qr, r1 = m0row + qr + 8;
#pragma unroll
    for (int nt2 = 0; nt2 < 8; nt2++) {
        const int col = nt2 * 8 + 2 * qc;
        *(float2*)(O + (size_t)r0 * 768 + col) =
            make_float2(oacc[nt2][0] * il0, oacc[nt2][1] * il0);
        *(float2*)(O + (size_t)r1 * 768 + col) =
            make_float2(oacc[nt2][2] * il1, oacc[nt2][3] * il1);
    }
}

// ---------------- fp16 mma GEMM + ldmatrix ----------------
// AH: A fp16 gmem (strides in halfs; NSUM==1). BH: B fp16 gmem (strides in halfs).
// mode bits: 1 = gelu, 2 = fp16 output. z = (i1*D2 + i2)*D3 + i3.
template <int BN, int NSUM, int AH = 0, int BH = 0>
__global__ void __launch_bounds__(256, 2)
gemm_mma(const float* __restrict__ A, const float* __restrict__ Bm, void* __restrict__ Cv,
         const float* __restrict__ bias, const float* __restrict__ res,
         int lda, int ldb, int ldc, int ldres, int K, float scale, int mode,
         int D2, int D3, long long sum_str,
         long long sA1, long long sA2, long long sA3,
         long long sB1, long long sB2, long long sB3,
         long long sC1, long long sC2, long long sC3,
         long long sb1, long long sb2, long long sb3) {
    constexpr int BM = 128, NT = 256, WN = BN / 4, NTILES = WN / 8, NPAIR = NTILES / 2;
    constexpr int AROW = 20;
    constexpr int BROW = BN / 2 + 4;
    constexpr int LBI = BN / 32;
    constexpr int LBH = (BN / 64 > 0) ? BN / 64 : 1;

    __shared__ uint32_t As32[2][BM * AROW];
    __shared__ uint32_t Bs32[2][32 * BROW];

    const int z = blockIdx.z;
    const int i1 = z / (D2 * D3);
    const int rem = z % (D2 * D3);
    const int i2 = rem / D3, i3 = rem % D3;
    const __half* Ah = (const __half*)A;
    const __half* Bh = (const __half*)Bm;
    if (AH) Ah += i1 * sA1 + i2 * sA2 + i3 * sA3;
    else A += i1 * sA1 + i2 * sA2 + i3 * sA3;
    if (BH) Bh += i1 * sB1 + i2 * sB2 + i3 * sB3;
    else Bm += i1 * sB1 + i2 * sB2 + i3 * sB3;
    const long long coff = i1 * sC1 + i2 * sC2 + i3 * sC3;
    const long long boff = i1 * sb1 + i2 * sb2 + i3 * sb3;

    const int x0 = blockIdx.x * BN, y0 = blockIdx.y * BM;
    const int tid = threadIdx.x;
    const int wid = tid >> 5, lane = tid & 31;
    const int wm0 = (wid >> 2) * 64;
    const int wn0 = (wid & 3) * WN;
    const int qr = lane >> 2, qc = lane & 3;

    const uint32_t aBase = smem_u32(As32);
    const uint32_t bBase = smem_u32(Bs32);
    const int arow_l = lane & 15, akoff = ((lane >> 4) << 3);
    const int bkrow = (lane & 7) + ((lane >> 3) & 1) * 8, bnoff = ((lane >> 4) << 3);

    float4 ra[4], rbv[LBI];
    uint4 rah[2], rbh[LBH];

    auto ldg = [&](int k0) {
        if (AH) {
#pragma unroll
            for (int i = 0; i < 2; i++) {
                int f = tid + i * NT;
                int m = f >> 2, kq = f & 3;
                rah[i] = *(const uint4*)(Ah + (size_t)(y0 + m) * lda + k0 + kq * 8);
            }
        } else {
#pragma unroll
            for (int i = 0; i < 4; i++) {
                int f = tid + i * NT;
                int m = f >> 3, kq = f & 7;
                const float* ap = A + (size_t)(y0 + m) * lda + k0 + kq * 4;
                float4 v = *(const float4*)ap;
#pragma unroll
                for (int s = 1; s < NSUM; s++) {
                    float4 w = *(const float4*)(ap + (size_t)s * sum_str);
                    v.x += w.x; v.y += w.y; v.z += w.z; v.w += w.w;
                }
                ra[i] = v;
            }
        }
        if (BH) {
#pragma unroll
            for (int i = 0; i < LBH; i++) {
                int f = tid + i * NT;
                int k = f / (BN / 8), n8 = f % (BN / 8);
                rbh[i] = *(const uint4*)(Bh + (size_t)(k0 + k) * ldb + x0 + 8 * n8);
            }
        } else {
#pragma unroll
            for (int i = 0; i < LBI; i++) {
                int f = tid + i * NT;
                int k = f / (BN / 4), nq = f % (BN / 4);
                rbv[i] = *(const float4*)(Bm + (size_t)(k0 + k) * ldb + x0 + 4 * nq);
            }
        }
    };
    auto sts = [&](int buf) {
        if (AH) {
#pragma unroll
            for (int i = 0; i < 2; i++) {
                int f = tid + i * NT;
                int m = f >> 2, kq = f & 3;
                As32[buf][m * AROW + 4 * kq + 0] = rah[i].x;
                As32[buf][m * AROW + 4 * kq + 1] = rah[i].y;
                As32[buf][m * AROW + 4 * kq + 2] = rah[i].z;
                As32[buf][m * AROW + 4 * kq + 3] = rah[i].w;
            }
        } else {
#pragma unroll
            for (int i = 0; i < 4; i++) {
                int f = tid + i * NT;
                int m = f >> 3, kq = f & 7;
                As32[buf][m * AROW + 2 * kq] = h2u(ra[i].x, ra[i].y);
                As32[buf][m * AROW + 2 * kq + 1] = h2u(ra[i].z, ra[i].w);
            }
        }
        if (BH) {
#pragma unroll
            for (int i = 0; i < LBH; i++) {
                int f = tid + i * NT;
                int k = f / (BN / 8), n8 = f % (BN / 8);
                Bs32[buf][k * BROW + 4 * n8 + 0] = rbh[i].x;
                Bs32[buf][k * BROW + 4 * n8 + 1] = rbh[i].y;
                Bs32[buf][k * BROW + 4 * n8 + 2] = rbh[i].z;
                Bs32[buf][k * BROW + 4 * n8 + 3] = rbh[i].w;
            }
        } else {
#pragma unroll
            for (int i = 0; i < LBI; i++) {
                int f = tid + i * NT;
                int k = f / (BN / 4), nq = f % (BN / 4);
                Bs32[buf][k * BROW + 2 * nq] = h2u(rbv[i].x, rbv[i].y);
                Bs32[buf][k * BROW + 2 * nq + 1] = h2u(rbv[i].z, rbv[i].w);
            }
        }
    };

    float acc[4][NTILES][4];
#pragma unroll
    for (int i = 0; i < 4; i++)
#pragma unroll
        for (int j = 0; j < NTILES; j++)
#pragma unroll
            for (int l = 0; l < 4; l++) acc[i][j][l] = 0.0f;

    ldg(0);
    sts(0);
    __syncthreads();
    const int nb = K >> 5;
    for (int kb = 0; kb < nb; kb++) {
        const int cur = kb & 1;
        if (kb + 1 < nb) ldg((kb + 1) << 5);
        const uint32_t aB = aBase + cur * (BM * AROW * 4);
        const uint32_t bB = bBase + cur * (32 * BROW * 4);
#pragma unroll
        for (int kk = 0; kk < 2; kk++) {
            uint32_t af[4][4], bb[NPAIR][4];
#pragma unroll
            for (int mt = 0; mt < 4; mt++)
                ldsm4(af[mt], aB + (uint32_t)(wm0 + mt * 16 + arow_l) * 80 +
                                  (uint32_t)(kk * 16 + akoff) * 2);
#pragma unroll
            for (int p = 0; p < NPAIR; p++)
                ldsm4t(bb[p], bB + (uint32_t)(kk * 16 + bkrow) * (BROW * 4) +
                                  (uint32_t)(wn0 + p * 16 + bnoff) * 2);
#pragma unroll
            for (int mt = 0; mt < 4; mt++)
#pragma unroll
                for (int p = 0; p < NPAIR; p++) {
                    mma16b(acc[mt][2 * p], af[mt], bb[p][0], bb[p][1]);
                    mma16b(acc[mt][2 * p + 1], af[mt], bb[p][2], bb[p][3]);
                }
        }
        if (kb + 1 < nb) sts(cur ^ 1);
        __syncthreads();
    }

    float* Cf = (float*)Cv + coff;
    __half* Ch = (__half*)Cv + coff;
#pragma unroll
    for (int mt = 0; mt < 4; mt++) {
#pragma unroll
        for (int nt = 0; nt < NTILES; nt++) {
            const int n = x0 + wn0 + nt * 8 + qc * 2;
#pragma unroll
            for (int half_ = 0; half_ < 2; half_++) {
                const int m = y0 + wm0 + mt * 16 + qr + half_ * 8;
                float v0 = acc[mt][nt][half_ * 2 + 0] * scale;
                float v1 = acc[mt][nt][half_ * 2 + 1] * scale;
                if (bias) { v0 += bias[boff + n]; v1 += bias[boff + n + 1]; }
                if (res) {
                    v0 += res[(size_t)m * ldres + n];
                    v1 += res[(size_t)m * ldres + n + 1];
                }
                if (mode & 1) { v0 = gelu_exact(v0); v1 = gelu_exact(v1); }
                if (mode & 2) {
                    __half2 hv = __halves2half2(__float2half_rn(v0), __float2half_rn(v1));
                    *(__half2*)(Ch + (size_t)m * ldc + n) = hv;
                } else {
                    *(float2*)(Cf + (size_t)m * ldc + n) = make_float2(v0, v1);
                }
            }
        }
    }
}

// ---------------- packing: everything to fp16 ----------------
// WH layout (halfs): W@0 (884736) | VW@884736 (73728) | Uo@958464 | Vo@1253376 |
//                    U1@1548288 | V1@1843200 | U2@3022848 | V2@4202496 | end 4497408
__global__ void pack_all(const float* __restrict__ Pq, const float* __restrict__ Pk,
                         const float* __restrict__ Pv,
                         const float* __restrict__ Vq, const float* __restrict__ Vk,
                         const float* __restrict__ Vv,
                         const float* __restrict__ bq, const float* __restrict__ bk,
                         const float* __restrict__ bv,
                         const float* __restrict__ Uo, const float* __restrict__ Vo,
                         const float* __restrict__ U1, const float* __restrict__ V1,
                         const float* __restrict__ U2, const float* __restrict__ V2,
                         __half* __restrict__ WH, float* __restrict__ VB) {
    int idx = blockIdx.x * blockDim.x + threadIdx.x;
    if (idx < 884736) {
        int q = idx / (768 * 384);
        int r2 = idx % (768 * 384);
        int k = r2 / 384, n = r2 % 384;
        const float* P = (q == 0) ? Pq : ((q == 1) ? Pk : Pv);
        WH[idx] = __float2half_rn(P[((size_t)(n >> 5) * 768 + k) * 32 + (n & 31)]);
    } else if (idx < 958464) {
        int e = idx - 884736;
        int q = e / 24576, r = e % 24576;
        const float* S = (q == 0) ? Vq : ((q == 1) ? Vk : Vv);
        WH[idx] = __float2half_rn(S[r]);
    } else if (idx < 1253376) {
        WH[idx] = __float2half_rn(Uo[idx - 958464]);
    } else if (idx < 1548288) {
        WH[idx] = __float2half_rn(Vo[idx - 1253376]);
    } else if (idx < 1843200) {
        WH[idx] = __float2half_rn(U1[idx - 1548288]);
    } else if (idx < 3022848) {
        WH[idx] = __float2half_rn(V1[idx - 1843200]);
    } else if (idx < 4202496) {
        WH[idx] = __float2half_rn(U2[idx - 3022848]);
    } else if (idx < 4497408) {
        WH[idx] = __float2half_rn(V2[idx - 4202496]);
    } else if (idx < 4497408 + 2304) {
        int e = idx - 4497408;
        int q = e / 768, r = e % 768;
        const float* S = (q == 0) ? bq : ((q == 1) ? bk : bv);
        VB[e] = S[r];
    }
}

// ---------------- LayerNorm (single pass) ----------------
__global__ void ln_kernel(const float* __restrict__ in, float* __restrict__ out,
                          const float* __restrict__ g, const float* __restrict__ bb) {
    __shared__ float rs_[8], rss_[8];
    const float* xr = in + (size_t)blockIdx.x * 768;
    float* yr = out + (size_t)blockIdx.x * 768;
    const int tid = threadIdx.x;
    float v[3];
    float s = 0.0f, ss = 0.0f;
#pragma unroll
    for (int i = 0; i < 3; i++) {
        v[i] = xr[tid + i * 256];
        s += v[i];
        ss += v[i] * v[i];
    }
#pragma unroll
    for (int o = 16; o; o >>= 1) {
        s += __shfl_xor_sync(0xffffffffu, s, o);
        ss += __shfl_xor_sync(0xffffffffu, ss, o);
    }
    if ((tid & 31) == 0) { rs_[tid >> 5] = s; rss_[tid >> 5] = ss; }
    __syncthreads();
    s = 0.0f; ss = 0.0f;
#pragma unroll
    for (int w = 0; w < 8; w++) { s += rs_[w]; ss += rss_[w]; }
    const float mu = s * (1.0f / 768.0f);
    const float var = fmaxf(ss * (1.0f / 768.0f) - mu * mu, 0.0f);
    const float rstd = rsqrtf(var + 1e-12f);
#pragma unroll
    for (int i = 0; i < 3; i++) {
        int c = tid + i * 256;
        yr[c] = (v[i] - mu) * rstd * g[c] + bb[c];
    }
}

extern "C" void kernel_launch(void* const* d_in, const int* in_sizes, int n_in,
                              void* d_out, int out_size) {
    const float* x    = (const float*)d_in[0];
    const float* mask = (const float*)d_in[1];
    const float* Pq   = (const float*)d_in[2];
    const float* Vq   = (const float*)d_in[3];
    const float* bq   = (const float*)d_in[4];
    const float* Pk   = (const float*)d_in[5];
    const float* Vk   = (const float*)d_in[6];
    const float* bk   = (const float*)d_in[7];
    const float* Pv   = (const float*)d_in[8];
    const float* Vv   = (const float*)d_in[9];
    const float* bv   = (const float*)d_in[10];
    const float* Uo   = (const float*)d_in[11];
    const float* Vo   = (const float*)d_in[12];
    const float* bo   = (const float*)d_in[13];
    const float* U1   = (const float*)d_in[14];
    const float* V1   = (const float*)d_in[15];
    const float* b1   = (const float*)d_in[16];
    const float* U2   = (const float*)d_in[17];
    const float* V2   = (const float*)d_in[18];
    const float* b2   = (const float*)d_in[19];
    const float* ln1g = (const float*)d_in[20];
    const float* ln1b = (const float*)d_in[21];
    const float* ln2g = (const float*)d_in[22];
    const float* ln2b = (const float*)d_in[23];
    float* out = (float*)d_out;

    float *vb_p, *t_p, *at2_p, *tmp_p, *x1_p, *y_p;
    __half *wh_p, *qkv_p, *hdnh_p;
    cudaGetSymbolAddress((void**)&wh_p,   g_wh);
    cudaGetSymbolAddress((void**)&vb_p,   g_vb);
    cudaGetSymbolAddress((void**)&t_p,    g_t);
    cudaGetSymbolAddress((void**)&qkv_p,  g_qkvh);
    cudaGetSymbolAddress((void**)&at2_p,  g_at2);
    cudaGetSymbolAddress((void**)&tmp_p,  g_tmp);
    cudaGetSymbolAddress((void**)&x1_p,   g_x1);
    cudaGetSymbolAddress((void**)&y_p,    g_y);
    cudaGetSymbolAddress((void**)&hdnh_p, g_hdnh);

    const long long T_QKV = 3145728, Q_QKV = 6291456, W_SZ = 294912;
    const long long PART = 3145728;
    const long long OFF_VW = 884736, OFF_UO = 958464, OFF_VO = 1253376,
                    OFF_U1 = 1548288, OFF_V1 = 1843200, OFF_U2 = 3022848,
                    OFF_V2 = 4202496;
    const int FL_SMEM = 77824;
    cudaFuncSetAttribute(flash_attn, cudaFuncAttributeMaxDynamicSharedMemorySize, FL_SMEM);

    // 0) pack all weights to fp16
    const int NPACK = 4497408 + 2304;
    pack_all<<<(NPACK + 255) / 256, 256>>>(Pq, Pk, Pv, Vq, Vk, Vv, bq, bk, bv,
                                           Uo, Vo, U1, V1, U2, V2, wh_p, vb_p);

    // 1) t = x @ W   (z over qkv)
    gemm_mma<128, 1, 0, 1><<<dim3(3, 64, 3), 256>>>(
        x, (const float*)wh_p, t_p, nullptr, nullptr,
        768, 384, 384, 0, 768, 1.0f, 0, 1, 1, 0LL,
        0LL, 0LL, 0LL, W_SZ, 0LL, 0LL, T_QKV, 0LL, 0LL, 0LL, 0LL, 0LL);

    // 2) Q/K/V = t @ Vqkv + b -> fp16. z=(q,b,h), K=32
    gemm_mma<64, 1, 0, 1><<<dim3(1, 8, 288), 256>>>(
        t_p, (const float*)(wh_p + OFF_VW), qkv_p, vb_p, nullptr,
        384, 64, 64, 0, 32, 1.0f, 2, 8, 12, 0LL,
        T_QKV, 393216LL, 32LL,
        24576LL, 0LL, 2048LL,
        Q_QKV, 786432LL, 65536LL,
        768LL, 0LL, 64LL);

    // 3) fused attention -> at2 (64-row q-tiles, 2 CTAs/SM)
    flash_attn<<<dim3(16, 96), 128, FL_SMEM>>>(
        qkv_p, qkv_p + Q_QKV, qkv_p + 2 * Q_QKV, mask, at2_p);

    // 4) ao partials = attn @ Uo  (split-K x2)
    gemm_mma<128, 1, 0, 1><<<dim3(3, 64, 2), 256>>>(
        at2_p, (const float*)(wh_p + OFF_UO), tmp_p, nullptr, nullptr,
        768, 384, 384, 0, 384, 1.0f, 0, 1, 2, 0LL,
        0LL, 0LL, 384LL, 0LL, 0LL, 147456LL, 0LL, 0LL, PART, 0, 0, 0);

    // 5) x1pre = sum(ao) @ Vo + bo + x
    gemm_mma<128, 2, 0, 1><<<dim3(6, 64, 1), 256>>>(
        tmp_p, (const float*)(wh_p + OFF_VO), y_p, bo, x,
        384, 768, 768, 768, 384, 1.0f, 0, 1, 1, PART,
        0, 0, 0, 0, 0, 0, 0, 0, 0, 0, 0, 0);

    // 6) LN1
    ln_kernel<<<8192, 256>>>(y_p, x1_p, ln1g, ln1b);

    // 7) mid partials = x1 @ U1  (split-K x2)
    gemm_mma<128, 1, 0, 1><<<dim3(3, 64, 2), 256>>>(
        x1_p, (const float*)(wh_p + OFF_U1), tmp_p, nullptr, nullptr,
        768, 384, 384, 0, 384, 1.0f, 0, 1, 2, 0LL,
        0LL, 0LL, 384LL, 0LL, 0LL, 147456LL, 0LL, 0LL, PART, 0, 0, 0);

    // 8) hdn = gelu(sum(mid) @ V1 + b1) -> fp16
    gemm_mma<128, 2, 0, 1><<<dim3(24, 64, 1), 256>>>(
        tmp_p, (const float*)(wh_p + OFF_V1), hdnh_p, b1, nullptr,
        384, 3072, 3072, 0, 384, 1.0f, 3, 1, 1, PART,
        0, 0, 0, 0, 0, 0, 0, 0, 0, 0, 0, 0);

    // 9) h2 partials = hdn(fp16) @ U2(fp16)  (split-K x4)
    gemm_mma<128, 1, 1, 1><<<dim3(3, 64, 4), 256>>>(
        (const float*)hdnh_p, (const float*)(wh_p + OFF_U2), tmp_p, nullptr, nullptr,
        3072, 384, 384, 0, 768, 1.0f, 0, 1, 4, 0LL,
        0LL, 0LL, 768LL, 0LL, 0LL, 294912LL, 0LL, 0LL, PART, 0, 0, 0);

    // 10) ypre = sum(h2) @ V2 + b2 + x1
    gemm_mma<128, 4, 0, 1><<<dim3(6, 64, 1), 256>>>(
        tmp_p, (const float*)(wh_p + OFF_V2), y_p, b2, x1_p,
        384, 768, 768, 768, 384, 1.0f, 0, 1, 1, PART,
        0, 0, 0, 0, 0, 0, 0, 0, 0, 0, 0, 0);

    // 11) LN2 -> out
    ln_kernel<<<8192, 256>>>(y_p, out, ln2g, ln2b);
}

// round 14
// speedup vs baseline: 7.3712x; 1.0068x over previous
#include <cuda_runtime.h>
#include <cuda_fp16.h>
#include <math.h>
#include <stdint.h>

// B=8, M=1024, DM=768, H=12, DH=64, R=32, RFF=384, DFF=3072, RWO=384

// ---------------- scratch (device globals) ----------------
__device__ __half g_wh  [4497408];               // all fp16 weights
__device__ float  g_vb  [3ull * 12 * 64];
__device__ float  g_t   [3ull * 8 * 1024 * 384];
__device__ __half g_qkvh[3ull * 8 * 12 * 1024 * 64];
__device__ __half g_at2h[8ull * 1024 * 768];
__device__ float  g_tmp [4ull * 8192 * 384];
__device__ float  g_x1  [8192ull * 768];
__device__ float  g_y   [8192ull * 768];
__device__ __half g_hdnh[8192ull * 3072];

#define LOG2E 1.44269504088896340736f

__device__ __forceinline__ float gelu_exact(float v) {
    return 0.5f * v * (1.0f + erff(v * 0.70710678118654752440f));
}
__device__ __forceinline__ uint32_t h2u(float lo, float hi) {
    __half2 h = __halves2half2(__float2half_rn(lo), __float2half_rn(hi));
    return *(uint32_t*)&h;
}
__device__ __forceinline__ uint32_t ex2h2(float lo, float hi) {
    uint32_t p;
    asm("cvt.rn.f16x2.f32 %0, %2, %1;" : "=r"(p) : "f"(lo), "f"(hi));
    asm("ex2.approx.f16x2 %0, %0;" : "+r"(p));
    return p;
}
__device__ __forceinline__ float ex2f(float x) {
    float r;
    asm("ex2.approx.f32 %0, %1;" : "=f"(r) : "f"(x));
    return r;
}
__device__ __forceinline__ void mma16b(float* c, const uint32_t* a, uint32_t b0, uint32_t b1) {
    asm volatile(
        "mma.sync.aligned.m16n8k16.row.col.f32.f16.f16.f32 "
        "{%0,%1,%2,%3}, {%4,%5,%6,%7}, {%8,%9}, {%0,%1,%2,%3};"
        : "+f"(c[0]), "+f"(c[1]), "+f"(c[2]), "+f"(c[3])
        : "r"(a[0]), "r"(a[1]), "r"(a[2]), "r"(a[3]), "r"(b0), "r"(b1));
}
__device__ __forceinline__ void ldsm4(uint32_t* r, uint32_t addr) {
    asm volatile("ldmatrix.sync.aligned.m8n8.x4.shared.b16 {%0,%1,%2,%3}, [%4];"
                 : "=r"(r[0]), "=r"(r[1]), "=r"(r[2]), "=r"(r[3]) : "r"(addr));
}
__device__ __forceinline__ void ldsm4t(uint32_t* r, uint32_t addr) {
    asm volatile("ldmatrix.sync.aligned.m8n8.x4.trans.shared.b16 {%0,%1,%2,%3}, [%4];"
                 : "=r"(r[0]), "=r"(r[1]), "=r"(r[2]), "=r"(r[3]) : "r"(addr));
}
__device__ __forceinline__ uint32_t smem_u32(const void* p) {
    uint32_t a;
    asm("{ .reg .u64 t; cvta.to.shared.u64 t, %1; cvt.u32.u64 %0, t; }" : "=r"(a) : "l"(p));
    return a;
}
#define CPA16(dst, src) \
    asm volatile("cp.async.cg.shared.global [%0], [%1], 16;" ::"r"(dst), "l"(src) : "memory")
#define CPA_COMMIT() asm volatile("cp.async.commit_group;" ::: "memory")

// ================= fused flash attention (log2 softmax, fp16 output) =================
__global__ void __launch_bounds__(128, 2)
flash_attn(const __half* __restrict__ Qg, const __half* __restrict__ Kg,
           const __half* __restrict__ Vg, const float* __restrict__ maskg,
           __half* __restrict__ Og) {
    extern __shared__ uint32_t smu[];
    float* Ms = (float*)(smu + 18432);
    const uint32_t sbase = smem_u32(smu);

    const int bh = blockIdx.y;
    const int b = bh / 12, h = bh % 12;
    const __half* Q = Qg + (size_t)bh * 65536;
    const __half* K = Kg + (size_t)bh * 65536;
    const __half* V = Vg + (size_t)bh * 65536;
    const float* mask = maskg + b * 1024;
    __half* O = Og + (size_t)b * 1024 * 768 + h * 64;

    const int tid = threadIdx.x;
    const int wid = tid >> 5, lane = tid & 31;
    const int qr = lane >> 2, qc = lane & 3;
    const int m0row = blockIdx.x * 64 + wid * 16;

    const int nrow = (lane & 7) | ((lane >> 4) << 3);
    const int koff8 = ((lane >> 3) & 1) << 3;
    const int krow = (lane & 7) + ((lane >> 3) & 1) * 8;
    const int noff8 = ((lane >> 4) << 3);
    const uint32_t ONE2 = 0x3C003C00u;

    auto kv_load = [&](int c, int buf) {
        uint32_t dstK = sbase + buf * 36864;
        uint32_t dstV = dstK + 18432;
        const __half* Kc = K + ((size_t)(c << 7)) * 64;
        const __half* Vc = V + ((size_t)(c << 7)) * 64;
#pragma unroll
        for (int j = 0; j < 8; j++) {
            int idx = tid + (j << 7);
            int kv = idx >> 3, c4 = idx & 7;
            CPA16(dstK + kv * 144 + c4 * 16, Kc + (size_t)kv * 64 + c4 * 8);
            CPA16(dstV + kv * 144 + c4 * 16, Vc + (size_t)kv * 64 + c4 * 8);
        }
    };
#pragma unroll
    for (int j = 0; j < 2; j++) {
        int idx = tid + (j << 7);
        CPA16(smem_u32(Ms + idx * 4), mask + idx * 4);
    }
    kv_load(0, 0);
    CPA_COMMIT();
    kv_load(1, 1);
    CPA_COMMIT();

    uint32_t qf[4][4];
    {
        const float qs = 0.125f * LOG2E;
        const __half* Qr0 = Q + (size_t)(m0row + qr) * 64;
        const __half* Qr1 = Q + (size_t)(m0row + qr + 8) * 64;
#pragma unroll
        for (int kd = 0; kd < 4; kd++) {
            float2 t0 = __half22float2(*(const __half2*)(Qr0 + kd * 16 + 2 * qc));
            float2 t1 = __half22float2(*(const __half2*)(Qr1 + kd * 16 + 2 * qc));
            float2 t2 = __half22float2(*(const __half2*)(Qr0 + kd * 16 + 2 * qc + 8));
            float2 t3 = __half22float2(*(const __half2*)(Qr1 + kd * 16 + 2 * qc + 8));
            qf[kd][0] = h2u(t0.x * qs, t0.y * qs);
            qf[kd][1] = h2u(t1.x * qs, t1.y * qs);
            qf[kd][2] = h2u(t2.x * qs, t2.y * qs);
            qf[kd][3] = h2u(t3.x * qs, t3.y * qs);
        }
    }

    float oacc[8][4];
#pragma unroll
    for (int i = 0; i < 8; i++)
#pragma unroll
        for (int j = 0; j < 4; j++) oacc[i][j] = 0.0f;
    float lacc[4] = {0.0f, 0.0f, 0.0f, 0.0f};
    float mrow0 = -INFINITY, mrow1 = -INFINITY;

    for (int c = 0; c < 8; c++) {
        const int buf = c & 1;
        const uint32_t ksb = sbase + buf * 36864;
        const uint32_t vsb = ksb + 18432;
        const int kvb = c << 7;

        if (c < 7) asm volatile("cp.async.wait_group 1;" ::: "memory");
        else       asm volatile("cp.async.wait_group 0;" ::: "memory");
        __syncthreads();

        float sacc[16][4];
#pragma unroll
        for (int nt = 0; nt < 16; nt++)
            sacc[nt][0] = sacc[nt][1] = sacc[nt][2] = sacc[nt][3] = 0.0f;
#pragma unroll
        for (int ntp = 0; ntp < 8; ntp++) {
            const uint32_t rowb = ksb + (uint32_t)(ntp * 16 + nrow) * 144;
#pragma unroll
            for (int kd = 0; kd < 4; kd++) {
                uint32_t bb[4];
                ldsm4(bb, rowb + (uint32_t)(kd * 16 + koff8) * 2);
                mma16b(sacc[2 * ntp], qf[kd], bb[0], bb[1]);
                mma16b(sacc[2 * ntp + 1], qf[kd], bb[2], bb[3]);
            }
        }

        float cm0 = -INFINITY, cm1 = -INFINITY;
#pragma unroll
        for (int nt = 0; nt < 16; nt++) {
            float mk0 = Ms[kvb + nt * 8 + 2 * qc] * LOG2E;
            float mk1 = Ms[kvb + nt * 8 + 2 * qc + 1] * LOG2E;
            sacc[nt][0] += mk0; sacc[nt][1] += mk1;
            sacc[nt][2] += mk0; sacc[nt][3] += mk1;
            cm0 = fmaxf(cm0, fmaxf(sacc[nt][0], sacc[nt][1]));
            cm1 = fmaxf(cm1, fmaxf(sacc[nt][2], sacc[nt][3]));
        }
        cm0 = fmaxf(cm0, __shfl_xor_sync(0xffffffffu, cm0, 1));
        cm0 = fmaxf(cm0, __shfl_xor_sync(0xffffffffu, cm0, 2));
        cm1 = fmaxf(cm1, __shfl_xor_sync(0xffffffffu, cm1, 1));
        cm1 = fmaxf(cm1, __shfl_xor_sync(0xffffffffu, cm1, 2));
        const float mn0 = fmaxf(mrow0, cm0), mn1 = fmaxf(mrow1, cm1);
        const float al0 = ex2f(mrow0 - mn0), al1 = ex2f(mrow1 - mn1);
        mrow0 = mn0; mrow1 = mn1;
#pragma unroll
        for (int i = 0; i < 8; i++) {
            oacc[i][0] *= al0; oacc[i][1] *= al0;
            oacc[i][2] *= al1; oacc[i][3] *= al1;
        }
        lacc[0] *= al0; lacc[1] *= al0; lacc[2] *= al1; lacc[3] *= al1;

#pragma unroll
        for (int kt2 = 0; kt2 < 8; kt2++) {
            uint32_t af[4];
            af[0] = ex2h2(sacc[2 * kt2][0] - mn0, sacc[2 * kt2][1] - mn0);
            af[1] = ex2h2(sacc[2 * kt2][2] - mn1, sacc[2 * kt2][3] - mn1);
            af[2] = ex2h2(sacc[2 * kt2 + 1][0] - mn0, sacc[2 * kt2 + 1][1] - mn0);
            af[3] = ex2h2(sacc[2 * kt2 + 1][2] - mn1, sacc[2 * kt2 + 1][3] - mn1);
            mma16b(lacc, af, ONE2, ONE2);
            const uint32_t rowb = vsb + (uint32_t)(kt2 * 16 + krow) * 144;
#pragma unroll
            for (int dtp = 0; dtp < 4; dtp++) {
                uint32_t bb[4];
                ldsm4t(bb, rowb + (uint32_t)(dtp * 16 + noff8) * 2);
                mma16b(oacc[2 * dtp], af, bb[0], bb[1]);
                mma16b(oacc[2 * dtp + 1], af, bb[2], bb[3]);
            }
        }
        __syncthreads();
        if (c + 2 < 8) { kv_load(c + 2, buf); CPA_COMMIT(); }
    }

    const float il0 = 1.0f / lacc[0], il1 = 1.0f / lacc[2];
    const int r0 = m0row + qr, r1 = m0row + qr + 8;
#pragma unroll
    for (int nt2 = 0; nt2 < 8; nt2++) {
        const int col = nt2 * 8 + 2 * qc;
        *(uint32_t*)(O + (size_t)r0 * 768 + col) =
            h2u(oacc[nt2][0] * il0, oacc[nt2][1] * il0);
        *(uint32_t*)(O + (size_t)r1 * 768 + col) =
            h2u(oacc[nt2][2] * il1, oacc[nt2][3] * il1);
    }
}

// ---------------- fp16 mma GEMM; B always fp16 via cp.async; A fp32(reg) or fp16(cp.async) ----------------
// mode bits: 1 = gelu, 2 = fp16 output. z = (i1*D2 + i2)*D3 + i3. Strides in elements.
template <int BN, int NSUM, int AH = 0>
__global__ void __launch_bounds__(256, 2)
gemm_mma(const float* __restrict__ A, const __half* __restrict__ Bh, void* __restrict__ Cv,
         const float* __restrict__ bias, const float* __restrict__ res,
         int lda, int ldb, int ldc, int ldres, int K, float scale, int mode,
         int D2, int D3, long long sum_str,
         long long sA1, long long sA2, long long sA3,
         long long sB1, long long sB2, long long sB3,
         long long sC1, long long sC2, long long sC3,
         long long sb1, long long sb2, long long sb3) {
    constexpr int BM = 128, NT = 256, WN = BN / 4, NTILES = WN / 8, NPAIR = NTILES / 2;
    constexpr int AROW = 20;            // u32/row for A (32 halfs + 8 pad)
    constexpr int BROW = BN / 2 + 4;    // u32/row for B
    constexpr int BCH = BN / 8;         // 16B chunks per B row
    constexpr int LB = (32 * BCH) / NT > 0 ? (32 * BCH) / NT : 1;

    __shared__ uint32_t As32[2][BM * AROW];
    __shared__ uint32_t Bs32[2][32 * BROW];

    const int z = blockIdx.z;
    const int i1 = z / (D2 * D3);
    const int rem = z % (D2 * D3);
    const int i2 = rem / D3, i3 = rem % D3;
    const __half* Ah = (const __half*)A;
    if (AH) Ah += i1 * sA1 + i2 * sA2 + i3 * sA3;
    else A += i1 * sA1 + i2 * sA2 + i3 * sA3;
    Bh += i1 * sB1 + i2 * sB2 + i3 * sB3;
    const long long coff = i1 * sC1 + i2 * sC2 + i3 * sC3;
    const long long boff = i1 * sb1 + i2 * sb2 + i3 * sb3;

    const int x0 = blockIdx.x * BN, y0 = blockIdx.y * BM;
    const int tid = threadIdx.x;
    const int wid = tid >> 5, lane = tid & 31;
    const int wm0 = (wid >> 2) * 64;
    const int wn0 = (wid & 3) * WN;
    const int qr = lane >> 2, qc = lane & 3;

    const uint32_t aBase = smem_u32(As32);
    const uint32_t bBase = smem_u32(Bs32);
    const int arow_l = lane & 15, akoff = ((lane >> 4) << 3);
    const int bkrow = (lane & 7) + ((lane >> 3) & 1) * 8, bnoff = ((lane >> 4) << 3);

    float4 ra[4];

    // async copies (A fp16 and B) into stage `buf`
    auto cpa = [&](int k0, int buf) {
        const uint32_t bB = bBase + buf * (32 * BROW * 4);
#pragma unroll
        for (int i = 0; i < LB; i++) {
            int f = tid + i * NT;
            int k = f / BCH, c8 = f % BCH;
            CPA16(bB + (uint32_t)(k * BROW * 4 + c8 * 16),
                  Bh + (size_t)(k0 + k) * ldb + x0 + c8 * 8);
        }
        if (AH) {
            const uint32_t aB = aBase + buf * (BM * AROW * 4);
#pragma unroll
            for (int i = 0; i < 2; i++) {
                int f = tid + i * NT;
                int m = f >> 2, c4 = f & 3;
                CPA16(aB + (uint32_t)(m * AROW * 4 + c4 * 16),
                      Ah + (size_t)(y0 + m) * lda + k0 + c4 * 8);
            }
        }
    };
    auto ldgA = [&](int k0) {
        if (!AH) {
#pragma unroll
            for (int i = 0; i < 4; i++) {
                int f = tid + i * NT;
                int m = f >> 3, kq = f & 7;
                const float* ap = A + (size_t)(y0 + m) * lda + k0 + kq * 4;
                float4 v = *(const float4*)ap;
#pragma unroll
                for (int s = 1; s < NSUM; s++) {
                    float4 w = *(const float4*)(ap + (size_t)s * sum_str);
                    v.x += w.x; v.y += w.y; v.z += w.z; v.w += w.w;
                }
                ra[i] = v;
            }
        }
    };
    auto stsA = [&](int buf) {
        if (!AH) {
#pragma unroll
            for (int i = 0; i < 4; i++) {
                int f = tid + i * NT;
                int m = f >> 3, kq = f & 7;
                As32[buf][m * AROW + 2 * kq] = h2u(ra[i].x, ra[i].y);
                As32[buf][m * AROW + 2 * kq + 1] = h2u(ra[i].z, ra[i].w);
            }
        }
    };

    float acc[4][NTILES][4];
#pragma unroll
    for (int i = 0; i < 4; i++)
#pragma unroll
        for (int j = 0; j < NTILES; j++)
#pragma unroll
            for (int l = 0; l < 4; l++) acc[i][j][l] = 0.0f;

    ldgA(0);
    cpa(0, 0);
    CPA_COMMIT();
    stsA(0);
    asm volatile("cp.async.wait_group 0;" ::: "memory");
    __syncthreads();

    const int nb = K >> 5;
    for (int kb = 0; kb < nb; kb++) {
        const int cur = kb & 1;
        if (kb + 1 < nb) {
            ldgA((kb + 1) << 5);
            cpa((kb + 1) << 5, cur ^ 1);
            CPA_COMMIT();
        }
        const uint32_t aB = aBase + cur * (BM * AROW * 4);
        const uint32_t bB = bBase + cur * (32 * BROW * 4);
#pragma unroll
        for (int kk = 0; kk < 2; kk++) {
            uint32_t af[4][4], bb[NPAIR][4];
#pragma unroll
            for (int mt = 0; mt < 4; mt++)
                ldsm4(af[mt], aB + (uint32_t)(wm0 + mt * 16 + arow_l) * 80 +
                                  (uint32_t)(kk * 16 + akoff) * 2);
#pragma unroll
            for (int p = 0; p < NPAIR; p++)
                ldsm4t(bb[p], bB + (uint32_t)(kk * 16 + bkrow) * (BROW * 4) +
                                  (uint32_t)(wn0 + p * 16 + bnoff) * 2);
#pragma unroll
            for (int mt = 0; mt < 4; mt++)
#pragma unroll
                for (int p = 0; p < NPAIR; p++) {
                    mma16b(acc[mt][2 * p], af[mt], bb[p][0], bb[p][1]);
                    mma16b(acc[mt][2 * p + 1], af[mt], bb[p][2], bb[p][3]);
                }
        }
        if (kb + 1 < nb) {
            stsA(cur ^ 1);
            asm volatile("cp.async.wait_group 0;" ::: "memory");
        }
        __syncthreads();
    }

    float* Cf = (float*)Cv + coff;
    __half* Ch = (__half*)Cv + coff;
#pragma unroll
    for (int mt = 0; mt < 4; mt++) {
#pragma unroll
        for (int nt = 0; nt < NTILES; nt++) {
            const int n = x0 + wn0 + nt * 8 + qc * 2;
#pragma unroll
            for (int half_ = 0; half_ < 2; half_++) {
                const int m = y0 + wm0 + mt * 16 + qr + half_ * 8;
                float v0 = acc[mt][nt][half_ * 2 + 0] * scale;
                float v1 = acc[mt][nt][half_ * 2 + 1] * scale;
                if (bias) { v0 += bias[boff + n]; v1 += bias[boff + n + 1]; }
                if (res) {
                    v0 += res[(size_t)m * ldres + n];
                    v1 += res[(size_t)m * ldres + n + 1];
                }
                if (mode & 1) { v0 = gelu_exact(v0); v1 = gelu_exact(v1); }
                if (mode & 2) {
                    *(uint32_t*)(Ch + (size_t)m * ldc + n) = h2u(v0, v1);
                } else {
                    *(float2*)(Cf + (size_t)m * ldc + n) = make_float2(v0, v1);
                }
            }
        }
    }
}

// ---------------- packing: all weights to fp16 ----------------
// WH layout (halfs): W@0 | VW@884736 | Uo@958464 | Vo@1253376 | U1@1548288 |
//                    V1@1843200 | U2@3022848 | V2@4202496 | end 4497408
__global__ void pack_all(const float* __restrict__ Pq, const float* __restrict__ Pk,
                         const float* __restrict__ Pv,
                         const float* __restrict__ Vq, const float* __restrict__ Vk,
                         const float* __restrict__ Vv,
                         const float* __restrict__ bq, const float* __restrict__ bk,
                         const float* __restrict__ bv,
                         const float* __restrict__ Uo, const float* __restrict__ Vo,
                         const float* __restrict__ U1, const float* __restrict__ V1,
                         const float* __restrict__ U2, const float* __restrict__ V2,
                         __half* __restrict__ WH, float* __restrict__ VB) {
    int idx = blockIdx.x * blockDim.x + threadIdx.x;
    if (idx < 884736) {
        int q = idx / (768 * 384);
        int r2 = idx % (768 * 384);
        int k = r2 / 384, n = r2 % 384;
        const float* P = (q == 0) ? Pq : ((q == 1) ? Pk : Pv);
        WH[idx] = __float2half_rn(P[((size_t)(n >> 5) * 768 + k) * 32 + (n & 31)]);
    } else if (idx < 958464) {
        int e = idx - 884736;
        int q = e / 24576, r = e % 24576;
        const float* S = (q == 0) ? Vq : ((q == 1) ? Vk : Vv);
        WH[idx] = __float2half_rn(S[r]);
    } else if (idx < 1253376) {
        WH[idx] = __float2half_rn(Uo[idx - 958464]);
    } else if (idx < 1548288) {
        WH[idx] = __float2half_rn(Vo[idx - 1253376]);
    } else if (idx < 1843200) {
        WH[idx] = __float2half_rn(U1[idx - 1548288]);
    } else if (idx < 3022848) {
        WH[idx] = __float2half_rn(V1[idx - 1843200]);
    } else if (idx < 4202496) {
        WH[idx] = __float2half_rn(U2[idx - 3022848]);
    } else if (idx < 4497408) {
        WH[idx] = __float2half_rn(V2[idx - 4202496]);
    } else if (idx < 4497408 + 2304) {
        int e = idx - 4497408;
        int q = e / 768, r = e % 768;
        const float* S = (q == 0) ? bq : ((q == 1) ? bk : bv);
        VB[e] = S[r];
    }
}

// ---------------- LayerNorm (single pass) ----------------
__global__ void ln_kernel(const float* __restrict__ in, float* __restrict__ out,
                          const float* __restrict__ g, const float* __restrict__ bb) {
    __shared__ float rs_[8], rss_[8];
    const float* xr = in + (size_t)blockIdx.x * 768;
    float* yr = out + (size_t)blockIdx.x * 768;
    const int tid = threadIdx.x;
    float v[3];
    float s = 0.0f, ss = 0.0f;
#pragma unroll
    for (int i = 0; i < 3; i++) {
        v[i] = xr[tid + i * 256];
        s += v[i];
        ss += v[i] * v[i];
    }
#pragma unroll
    for (int o = 16; o; o >>= 1) {
        s += __shfl_xor_sync(0xffffffffu, s, o);
        ss += __shfl_xor_sync(0xffffffffu, ss, o);
    }
    if ((tid & 31) == 0) { rs_[tid >> 5] = s; rss_[tid >> 5] = ss; }
    __syncthreads();
    s = 0.0f; ss = 0.0f;
#pragma unroll
    for (int w = 0; w < 8; w++) { s += rs_[w]; ss += rss_[w]; }
    const float mu = s * (1.0f / 768.0f);
    const float var = fmaxf(ss * (1.0f / 768.0f) - mu * mu, 0.0f);
    const float rstd = rsqrtf(var + 1e-12f);
#pragma unroll
    for (int i = 0; i < 3; i++) {
        int c = tid + i * 256;
        yr[c] = (v[i] - mu) * rstd * g[c] + bb[c];
    }
}

extern "C" void kernel_launch(void* const* d_in, const int* in_sizes, int n_in,
                              void* d_out, int out_size) {
    const float* x    = (const float*)d_in[0];
    const float* mask = (const float*)d_in[1];
    const float* Pq   = (const float*)d_in[2];
    const float* Vq   = (const float*)d_in[3];
    const float* bq   = (const float*)d_in[4];
    const float* Pk   = (const float*)d_in[5];
    const float* Vk   = (const float*)d_in[6];
    const float* bk   = (const float*)d_in[7];
    const float* Pv   = (const float*)d_in[8];
    const float* Vv   = (const float*)d_in[9];
    const float* bv   = (const float*)d_in[10];
    const float* Uo   = (const float*)d_in[11];
    const float* Vo   = (const float*)d_in[12];
    const float* bo   = (const float*)d_in[13];
    const float* U1   = (const float*)d_in[14];
    const float* V1   = (const float*)d_in[15];
    const float* b1   = (const float*)d_in[16];
    const float* U2   = (const float*)d_in[17];
    const float* V2   = (const float*)d_in[18];
    const float* b2   = (const float*)d_in[19];
    const float* ln1g = (const float*)d_in[20];
    const float* ln1b = (const float*)d_in[21];
    const float* ln2g = (const float*)d_in[22];
    const float* ln2b = (const float*)d_in[23];
    float* out = (float*)d_out;

    float *vb_p, *t_p, *tmp_p, *x1_p, *y_p;
    __half *wh_p, *qkv_p, *at2_p, *hdnh_p;
    cudaGetSymbolAddress((void**)&wh_p,   g_wh);
    cudaGetSymbolAddress((void**)&vb_p,   g_vb);
    cudaGetSymbolAddress((void**)&t_p,    g_t);
    cudaGetSymbolAddress((void**)&qkv_p,  g_qkvh);
    cudaGetSymbolAddress((void**)&at2_p,  g_at2h);
    cudaGetSymbolAddress((void**)&tmp_p,  g_tmp);
    cudaGetSymbolAddress((void**)&x1_p,   g_x1);
    cudaGetSymbolAddress((void**)&y_p,    g_y);
    cudaGetSymbolAddress((void**)&hdnh_p, g_hdnh);

    const long long T_QKV = 3145728, Q_QKV = 6291456, W_SZ = 294912;
    const long long PART = 3145728;
    const long long OFF_VW = 884736, OFF_UO = 958464, OFF_VO = 1253376,
                    OFF_U1 = 1548288, OFF_V1 = 1843200, OFF_U2 = 3022848,
                    OFF_V2 = 4202496;
    const int FL_SMEM = 77824;
    cudaFuncSetAttribute(flash_attn, cudaFuncAttributeMaxDynamicSharedMemorySize, FL_SMEM);

    // 0) pack all weights to fp16
    const int NPACK = 4497408 + 2304;
    pack_all<<<(NPACK + 255) / 256, 256>>>(Pq, Pk, Pv, Vq, Vk, Vv, bq, bk, bv,
                                           Uo, Vo, U1, V1, U2, V2, wh_p, vb_p);

    // 1) t = x @ W   (z over qkv)
    gemm_mma<128, 1><<<dim3(3, 64, 3), 256>>>(
        x, wh_p, t_p, nullptr, nullptr,
        768, 384, 384, 0, 768, 1.0f, 0, 1, 1, 0LL,
        0LL, 0LL, 0LL, W_SZ, 0LL, 0LL, T_QKV, 0LL, 0LL, 0LL, 0LL, 0LL);

    // 2) Q/K/V = t @ Vqkv + b -> fp16. z=(q,b,h), K=32
    gemm_mma<64, 1><<<dim3(1, 8, 288), 256>>>(
        t_p, wh_p + OFF_VW, qkv_p, vb_p, nullptr,
        384, 64, 64, 0, 32, 1.0f, 2, 8, 12, 0LL,
        T_QKV, 393216LL, 32LL,
        24576LL, 0LL, 2048LL,
        Q_QKV, 786432LL, 65536LL,
        768LL, 0LL, 64LL);

    // 3) fused attention -> at2 (fp16)
    flash_attn<<<dim3(16, 96), 128, FL_SMEM>>>(
        qkv_p, qkv_p + Q_QKV, qkv_p + 2 * Q_QKV, mask, at2_p);

    // 4) ao partials = attn(fp16) @ Uo  (split-K x2)
    gemm_mma<128, 1, 1><<<dim3(3, 64, 2), 256>>>(
        (const float*)at2_p, wh_p + OFF_UO, tmp_p, nullptr, nullptr,
        768, 384, 384, 0, 384, 1.0f, 0, 1, 2, 0LL,
        0LL, 0LL, 384LL, 0LL, 0LL, 147456LL, 0LL, 0LL, PART, 0, 0, 0);

    // 5) x1pre = sum(ao) @ Vo + bo + x
    gemm_mma<128, 2><<<dim3(6, 64, 1), 256>>>(
        tmp_p, wh_p + OFF_VO, y_p, bo, x,
        384, 768, 768, 768, 384, 1.0f, 0, 1, 1, PART,
        0, 0, 0, 0, 0, 0, 0, 0, 0, 0, 0, 0);

    // 6) LN1
    ln_kernel<<<8192, 256>>>(y_p, x1_p, ln1g, ln1b);

    // 7) mid partials = x1 @ U1  (split-K x2)
    gemm_mma<128, 1><<<dim3(3, 64, 2), 256>>>(
        x1_p, wh_p + OFF_U1, tmp_p, nullptr, nullptr,
        768, 384, 384, 0, 384, 1.0f, 0, 1, 2, 0LL,
        0LL, 0LL, 384LL, 0LL, 0LL, 147456LL, 0LL, 0LL, PART, 0, 0, 0);

    // 8) hdn = gelu(sum(mid) @ V1 + b1) -> fp16
    gemm_mma<128, 2><<<dim3(24, 64, 1), 256>>>(
        tmp_p, wh_p + OFF_V1, hdnh_p, b1, nullptr,
        384, 3072, 3072, 0, 384, 1.0f, 3, 1, 1, PART,
        0, 0, 0, 0, 0, 0, 0, 0, 0, 0, 0, 0);

    // 9) h2 partials = hdn(fp16) @ U2  (split-K x4)
    gemm_mma<128, 1, 1><<<dim3(3, 64, 4), 256>>>(
        (const float*)hdnh_p, wh_p + OFF_U2, tmp_p, nullptr, nullptr,
        3072, 384, 384, 0, 768, 1.0f, 0, 1, 4, 0LL,
        0LL, 0LL, 768LL, 0LL, 0LL, 294912LL, 0LL, 0LL, PART, 0, 0, 0);

    // 10) ypre = sum(h2) @ V2 + b2 + x1
    gemm_mma<128, 4><<<dim3(6, 64, 1), 256>>>(
        tmp_p, wh_p + OFF_V2, y_p, b2, x1_p,
        384, 768, 768, 768, 384, 1.0f, 0, 1, 1, PART,
        0, 0, 0, 0, 0, 0, 0, 0, 0, 0, 0, 0);

    // 11) LN2 -> out
    ln_kernel<<<8192, 256>>>(y_p, out, ln2g, ln2b);
}